// round 1
// baseline (speedup 1.0000x reference)
#include <cuda_runtime.h>
#include <math.h>

#define N_HEAD   16
#define HEAD     128
#define ROPE     32
#define C_       2048
#define B_       2
#define T_       2048
#define M_TOK    (B_*T_)        // 4096
#define QKV_OUT  3072           // (16 + 2*4) * 128
#define FFN      8192

// ---------------- scratch (device globals; no allocations allowed) -------------
__device__ float g_ln1[(size_t)M_TOK * C_];
__device__ float g_ln2[(size_t)M_TOK * C_];
__device__ float g_qkv[(size_t)M_TOK * QKV_OUT];
__device__ float g_y  [(size_t)M_TOK * C_];
__device__ float g_h  [(size_t)M_TOK * C_];
__device__ float g_act[(size_t)M_TOK * FFN];

// ---------------- fused dual LayerNorm (reads x once, writes ln1 & ln2) --------
__global__ __launch_bounds__(256) void ln_dual_kernel(
    const float* __restrict__ x,
    const float* __restrict__ w1, const float* __restrict__ b1,
    const float* __restrict__ w2, const float* __restrict__ b2,
    float* __restrict__ o1, float* __restrict__ o2)
{
    int row = blockIdx.x;
    const float* xr = x + (size_t)row * C_;
    int tid = threadIdx.x;

    float v[8];
    float s = 0.f, s2 = 0.f;
#pragma unroll
    for (int i = 0; i < 8; i++) {
        float t = xr[tid + i * 256];
        v[i] = t; s += t; s2 += t * t;
    }
#pragma unroll
    for (int o = 16; o; o >>= 1) {
        s  += __shfl_xor_sync(0xffffffffu, s,  o);
        s2 += __shfl_xor_sync(0xffffffffu, s2, o);
    }
    __shared__ float sh[16];
    __shared__ float mu_s, rstd_s;
    int w = tid >> 5;
    if ((tid & 31) == 0) { sh[w] = s; sh[w + 8] = s2; }
    __syncthreads();
    if (tid == 0) {
        float a = 0.f, b = 0.f;
#pragma unroll
        for (int i = 0; i < 8; i++) { a += sh[i]; b += sh[i + 8]; }
        float mu  = a * (1.0f / C_);
        float var = b * (1.0f / C_) - mu * mu;
        mu_s = mu;
        rstd_s = rsqrtf(var + 1e-5f);
    }
    __syncthreads();
    float mu = mu_s, rs = rstd_s;
#pragma unroll
    for (int i = 0; i < 8; i++) {
        int c = tid + i * 256;
        float n = (v[i] - mu) * rs;
        o1[(size_t)row * C_ + c] = n * w1[c] + b1[c];
        o2[(size_t)row * C_ + c] = n * w2[c] + b2[c];
    }
}

// ---------------- RoPE in place on qkv (16 q heads + 4 k heads) ----------------
__global__ __launch_bounds__(320) void rope_kernel(
    float* __restrict__ qkv,
    const float* __restrict__ cosb, const float* __restrict__ sinb)
{
    int r = blockIdx.x;
    int t = r & (T_ - 1);
    int tid = threadIdx.x;          // 0..319
    int hh = tid >> 4;              // 0..19
    int i  = tid & 15;
    int col;
    if (hh < 16) col = ((hh >> 2) * 6 + (hh & 3)) * HEAD;   // q heads
    else         col = ((hh - 16) * 6 + 4) * HEAD;          // k heads (slot 4)
    float* p = qkv + (size_t)r * QKV_OUT + col;
    float c1 = cosb[t * ROPE + i],      s1 = sinb[t * ROPE + i];
    float c2 = cosb[t * ROPE + i + 16], s2 = sinb[t * ROPE + i + 16];
    float x1 = p[i], x2 = p[i + 16];
    p[i]      = x1 * c2 * 0.0f + x1 * c1 - x2 * s1;  // = x1*c1 - x2*s1
    p[i + 16] = x2 * c2 + x1 * s2;
}

// ---------------- SGEMM 128x128x8, 256 thr, 8x8/thread ------------------------
// EPI: 0 = +bias, 1 = +bias then exact GELU, 2 = +bias +add1 +add2
template <int EPI>
__global__ __launch_bounds__(256, 2) void sgemm_kernel(
    const float* __restrict__ A, const float* __restrict__ Bm,
    const float* __restrict__ bias, float* __restrict__ Co,
    int M, int N, int K,
    const float* __restrict__ add1, const float* __restrict__ add2)
{
    __shared__ float As[8][128];
    __shared__ float Bs[8][132];

    int tid = threadIdx.x;
    int bm = blockIdx.y * 128, bn = blockIdx.x * 128;
    int aRow = tid >> 1, aCol = (tid & 1) * 4;
    int bRow = tid >> 5, bCol = (tid & 31) * 4;
    const float* Ap = A + (size_t)(bm + aRow) * K + aCol;
    const float* Bp = Bm + (size_t)bRow * N + bn + bCol;
    int tr = tid >> 4, tc = tid & 15;

    float acc[8][8];
#pragma unroll
    for (int i = 0; i < 8; i++)
#pragma unroll
        for (int j = 0; j < 8; j++) acc[i][j] = 0.f;

    for (int k0 = 0; k0 < K; k0 += 8) {
        float4 a4 = *(const float4*)Ap;
        float4 b4 = *(const float4*)Bp;
        As[aCol + 0][aRow] = a4.x;
        As[aCol + 1][aRow] = a4.y;
        As[aCol + 2][aRow] = a4.z;
        As[aCol + 3][aRow] = a4.w;
        *(float4*)&Bs[bRow][bCol] = b4;
        __syncthreads();
#pragma unroll
        for (int k = 0; k < 8; k++) {
            float a[8], b[8];
            *(float4*)&a[0] = *(const float4*)&As[k][tr * 8];
            *(float4*)&a[4] = *(const float4*)&As[k][tr * 8 + 4];
            *(float4*)&b[0] = *(const float4*)&Bs[k][tc * 8];
            *(float4*)&b[4] = *(const float4*)&Bs[k][tc * 8 + 4];
#pragma unroll
            for (int i = 0; i < 8; i++)
#pragma unroll
                for (int j = 0; j < 8; j++) acc[i][j] += a[i] * b[j];
        }
        __syncthreads();
        Ap += 8;
        Bp += (size_t)8 * N;
    }

#pragma unroll
    for (int i = 0; i < 8; i++) {
        int m = bm + tr * 8 + i;
        size_t rowoff = (size_t)m * N;
#pragma unroll
        for (int j = 0; j < 8; j++) {
            int n = bn + tc * 8 + j;
            float v = acc[i][j] + bias[n];
            if (EPI == 1) v = 0.5f * v * (1.f + erff(v * 0.70710678118654752f));
            if (EPI == 2) v += add1[rowoff + n] + add2[rowoff + n];
            Co[rowoff + n] = v;
        }
    }
}

// ---------------- Flash attention, BM=BN=64, D=128, causal, GQA ----------------
#define ATT_PAD  132
#define PS_PAD   68
#define ATT_SMEM ((2 * 64 * ATT_PAD + 64 * PS_PAD) * 4)   // 84992 bytes

__global__ __launch_bounds__(256) void attn_kernel(
    const float* __restrict__ qkv, float* __restrict__ y)
{
    extern __shared__ float smem[];
    float* Qs  = smem;                        // 64 x 132
    float* KVs = smem + 64 * ATT_PAD;         // 64 x 132 (K then reused for V)
    float* Ps  = smem + 2 * 64 * ATT_PAD;     // 64 x 68

    int qt = blockIdx.x;      // query tile 0..31
    int h  = blockIdx.y;      // head
    int b  = blockIdx.z;
    int g  = h >> 2;
    int qcol = (g * 6 + (h & 3)) * HEAD;
    int kcol = (g * 6 + 4) * HEAD;
    int vcol = (g * 6 + 5) * HEAD;

    int tid = threadIdx.x;
    int tr = tid >> 4, tc = tid & 15;
    int qbase = qt * 64;
    const size_t RS = QKV_OUT;

    // load Q tile
    for (int idx = tid; idx < 64 * 32; idx += 256) {
        int rr = idx >> 5, dd = (idx & 31) * 4;
        *(float4*)&Qs[rr * ATT_PAD + dd] =
            *(const float4*)(qkv + (size_t)(b * T_ + qbase + rr) * RS + qcol + dd);
    }

    float acc[4][8];
#pragma unroll
    for (int i = 0; i < 4; i++)
#pragma unroll
        for (int j = 0; j < 8; j++) acc[i][j] = 0.f;
    float rmax[4] = {-1e30f, -1e30f, -1e30f, -1e30f};
    float rsum[4] = {0.f, 0.f, 0.f, 0.f};

    const float scale = 0.08838834764831845f;  // 1/sqrt(128)
    int ntiles = qt + 1;

    for (int kt = 0; kt < ntiles; kt++) {
        int nb = kt * 64;
        __syncthreads();   // KVs free (prev PV done), Ps free
        for (int idx = tid; idx < 64 * 32; idx += 256) {
            int rr = idx >> 5, dd = (idx & 31) * 4;
            *(float4*)&KVs[rr * ATT_PAD + dd] =
                *(const float4*)(qkv + (size_t)(b * T_ + nb + rr) * RS + kcol + dd);
        }
        __syncthreads();

        // S = Q K^T  (4x4 per thread)
        float s[4][4];
#pragma unroll
        for (int i = 0; i < 4; i++)
#pragma unroll
            for (int j = 0; j < 4; j++) s[i][j] = 0.f;
        for (int d = 0; d < 128; d += 4) {
            float4 q[4], k[4];
#pragma unroll
            for (int i = 0; i < 4; i++) q[i] = *(const float4*)&Qs[(tr * 4 + i) * ATT_PAD + d];
#pragma unroll
            for (int j = 0; j < 4; j++) k[j] = *(const float4*)&KVs[(tc * 4 + j) * ATT_PAD + d];
#pragma unroll
            for (int i = 0; i < 4; i++)
#pragma unroll
                for (int j = 0; j < 4; j++)
                    s[i][j] += q[i].x * k[j].x + q[i].y * k[j].y +
                               q[i].z * k[j].z + q[i].w * k[j].w;
        }

        // mask + online softmax update + write P
#pragma unroll
        for (int i = 0; i < 4; i++) {
            int mq = qbase + tr * 4 + i;
            float mloc = -1e30f;
#pragma unroll
            for (int j = 0; j < 4; j++) {
                int nk = nb + tc * 4 + j;
                float sv = s[i][j] * scale;
                if (nk > mq) sv = -1e30f;
                s[i][j] = sv;
                mloc = fmaxf(mloc, sv);
            }
#pragma unroll
            for (int o = 8; o; o >>= 1)
                mloc = fmaxf(mloc, __shfl_xor_sync(0xffffffffu, mloc, o, 16));
            float nm  = fmaxf(rmax[i], mloc);
            float fac = __expf(rmax[i] - nm);
            rmax[i] = nm;
            float ps = 0.f;
#pragma unroll
            for (int j = 0; j < 4; j++) {
                float p = __expf(s[i][j] - nm);
                s[i][j] = p;
                ps += p;
            }
#pragma unroll
            for (int o = 8; o; o >>= 1)
                ps += __shfl_xor_sync(0xffffffffu, ps, o, 16);
            rsum[i] = rsum[i] * fac + ps;
#pragma unroll
            for (int j = 0; j < 8; j++) acc[i][j] *= fac;
#pragma unroll
            for (int j = 0; j < 4; j++)
                Ps[(tr * 4 + i) * PS_PAD + tc * 4 + j] = s[i][j];
        }
        __syncthreads();    // K reads done, P written

        // load V over KVs
        for (int idx = tid; idx < 64 * 32; idx += 256) {
            int rr = idx >> 5, dd = (idx & 31) * 4;
            *(float4*)&KVs[rr * ATT_PAD + dd] =
                *(const float4*)(qkv + (size_t)(b * T_ + nb + rr) * RS + vcol + dd);
        }
        __syncthreads();

        // O += P V   (4 rows x 8 dims per thread)
        for (int kk = 0; kk < 64; kk++) {
            float4 v0 = *(const float4*)&KVs[kk * ATT_PAD + tc * 8];
            float4 v1 = *(const float4*)&KVs[kk * ATT_PAD + tc * 8 + 4];
#pragma unroll
            for (int i = 0; i < 4; i++) {
                float p = Ps[(tr * 4 + i) * PS_PAD + kk];
                acc[i][0] += p * v0.x; acc[i][1] += p * v0.y;
                acc[i][2] += p * v0.z; acc[i][3] += p * v0.w;
                acc[i][4] += p * v1.x; acc[i][5] += p * v1.y;
                acc[i][6] += p * v1.z; acc[i][7] += p * v1.w;
            }
        }
    }

    // write y in [B, T, H, D] layout
#pragma unroll
    for (int i = 0; i < 4; i++) {
        float inv = 1.f / rsum[i];
        size_t m = (size_t)(b * T_ + qbase + tr * 4 + i);
#pragma unroll
        for (int j = 0; j < 8; j++)
            y[m * C_ + h * HEAD + tc * 8 + j] = acc[i][j] * inv;
    }
}

// ---------------- launcher -----------------------------------------------------
extern "C" void kernel_launch(void* const* d_in, const int* in_sizes, int n_in,
                              void* d_out, int out_size)
{
    const float* x     = (const float*)d_in[0];
    const float* cosb  = (const float*)d_in[1];
    const float* sinb  = (const float*)d_in[2];
    const float* ln1w  = (const float*)d_in[3];
    const float* ln1b  = (const float*)d_in[4];
    const float* wqkv  = (const float*)d_in[5];
    const float* bqkv  = (const float*)d_in[6];
    const float* wproj = (const float*)d_in[7];
    const float* bproj = (const float*)d_in[8];
    const float* ln2w  = (const float*)d_in[9];
    const float* ln2b  = (const float*)d_in[10];
    const float* wfc1  = (const float*)d_in[11];
    const float* bfc1  = (const float*)d_in[12];
    const float* wfc2  = (const float*)d_in[13];
    const float* bfc2  = (const float*)d_in[14];
    float* out = (float*)d_out;

    float *ln1, *ln2, *qkv, *y, *h, *act;
    cudaGetSymbolAddress((void**)&ln1, g_ln1);
    cudaGetSymbolAddress((void**)&ln2, g_ln2);
    cudaGetSymbolAddress((void**)&qkv, g_qkv);
    cudaGetSymbolAddress((void**)&y,   g_y);
    cudaGetSymbolAddress((void**)&h,   g_h);
    cudaGetSymbolAddress((void**)&act, g_act);

    // 1. dual LayerNorm
    ln_dual_kernel<<<M_TOK, 256>>>(x, ln1w, ln1b, ln2w, ln2b, ln1, ln2);

    // 2. QKV projection
    sgemm_kernel<0><<<dim3(QKV_OUT / 128, M_TOK / 128), 256>>>(
        ln1, wqkv, bqkv, qkv, M_TOK, QKV_OUT, C_, nullptr, nullptr);

    // 3. RoPE
    rope_kernel<<<M_TOK, 320>>>(qkv, cosb, sinb);

    // 4. flash attention
    cudaFuncSetAttribute(attn_kernel, cudaFuncAttributeMaxDynamicSharedMemorySize, ATT_SMEM);
    attn_kernel<<<dim3(T_ / 64, N_HEAD, B_), 256, ATT_SMEM>>>(qkv, y);

    // 5. output projection -> h
    sgemm_kernel<0><<<dim3(C_ / 128, M_TOK / 128), 256>>>(
        y, wproj, bproj, h, M_TOK, C_, C_, nullptr, nullptr);

    // 6. fc1 + GELU -> act
    sgemm_kernel<1><<<dim3(FFN / 128, M_TOK / 128), 256>>>(
        ln2, wfc1, bfc1, act, M_TOK, FFN, C_, nullptr, nullptr);

    // 7. fc2 + h + x -> out
    sgemm_kernel<2><<<dim3(C_ / 128, M_TOK / 128), 256>>>(
        act, wfc2, bfc2, out, M_TOK, C_, FFN, h, x);
}

// round 4
// speedup vs baseline: 2.4088x; 2.4088x over previous
#include <cuda_runtime.h>
#include <math.h>
#include <stdint.h>

#define N_HEAD   16
#define HEAD     128
#define ROPE     32
#define C_       2048
#define B_       2
#define T_       2048
#define M_TOK    (B_*T_)        // 4096
#define QKV_OUT  3072           // (16 + 2*4) * 128
#define FFN      8192

// ---------------- scratch (device globals; no allocations allowed) -------------
__device__ float g_ln1[(size_t)M_TOK * C_];
__device__ float g_ln2[(size_t)M_TOK * C_];
__device__ float g_qkv[(size_t)M_TOK * QKV_OUT];
__device__ float g_y  [(size_t)M_TOK * C_];
__device__ float g_h  [(size_t)M_TOK * C_];
__device__ float g_act[(size_t)M_TOK * FFN];

// ---------------- fused dual LayerNorm (reads x once, writes ln1 & ln2) --------
__global__ __launch_bounds__(256) void ln_dual_kernel(
    const float* __restrict__ x,
    const float* __restrict__ w1, const float* __restrict__ b1,
    const float* __restrict__ w2, const float* __restrict__ b2,
    float* __restrict__ o1, float* __restrict__ o2)
{
    int row = blockIdx.x;
    const float* xr = x + (size_t)row * C_;
    int tid = threadIdx.x;

    float v[8];
    float s = 0.f, s2 = 0.f;
#pragma unroll
    for (int i = 0; i < 8; i++) {
        float t = xr[tid + i * 256];
        v[i] = t; s += t; s2 += t * t;
    }
#pragma unroll
    for (int o = 16; o; o >>= 1) {
        s  += __shfl_xor_sync(0xffffffffu, s,  o);
        s2 += __shfl_xor_sync(0xffffffffu, s2, o);
    }
    __shared__ float sh[16];
    __shared__ float mu_s, rstd_s;
    int w = tid >> 5;
    if ((tid & 31) == 0) { sh[w] = s; sh[w + 8] = s2; }
    __syncthreads();
    if (tid == 0) {
        float a = 0.f, b = 0.f;
#pragma unroll
        for (int i = 0; i < 8; i++) { a += sh[i]; b += sh[i + 8]; }
        float mu  = a * (1.0f / C_);
        float var = b * (1.0f / C_) - mu * mu;
        mu_s = mu;
        rstd_s = rsqrtf(var + 1e-5f);
    }
    __syncthreads();
    float mu = mu_s, rs = rstd_s;
#pragma unroll
    for (int i = 0; i < 8; i++) {
        int c = tid + i * 256;
        float n = (v[i] - mu) * rs;
        o1[(size_t)row * C_ + c] = n * w1[c] + b1[c];
        o2[(size_t)row * C_ + c] = n * w2[c] + b2[c];
    }
}

// ---------------- RoPE in place on qkv (16 q heads + 4 k heads) ----------------
__global__ __launch_bounds__(320) void rope_kernel(
    float* __restrict__ qkv,
    const float* __restrict__ cosb, const float* __restrict__ sinb)
{
    int r = blockIdx.x;
    int t = r & (T_ - 1);
    int tid = threadIdx.x;          // 0..319
    int hh = tid >> 4;              // 0..19
    int i  = tid & 15;
    int col;
    if (hh < 16) col = ((hh >> 2) * 6 + (hh & 3)) * HEAD;   // q heads
    else         col = ((hh - 16) * 6 + 4) * HEAD;          // k heads (slot 4)
    float* p = qkv + (size_t)r * QKV_OUT + col;
    float c1 = cosb[t * ROPE + i],      s1 = sinb[t * ROPE + i];
    float c2 = cosb[t * ROPE + i + 16], s2 = sinb[t * ROPE + i + 16];
    float x1 = p[i], x2 = p[i + 16];
    p[i]      = x1 * c1 - x2 * s1;
    p[i + 16] = x2 * c2 + x1 * s2;
}

// ---------------- tf32 tensor-core GEMM 128x128x32, 8 warps -------------------
// EPI: 0 = +bias, 1 = +bias then exact GELU, 2 = +bias +add1 +add2

__device__ __forceinline__ uint32_t f2tf(float f) {
    uint32_t u;
    asm("cvt.rna.tf32.f32 %0, %1;" : "=r"(u) : "f"(f));
    return u;
}

__device__ __forceinline__ void mma_tf32(float* c, const uint32_t* a, const uint32_t* b) {
    asm volatile(
        "mma.sync.aligned.m16n8k8.row.col.f32.tf32.tf32.f32 "
        "{%0,%1,%2,%3}, {%4,%5,%6,%7}, {%8,%9}, {%0,%1,%2,%3};"
        : "+f"(c[0]), "+f"(c[1]), "+f"(c[2]), "+f"(c[3])
        : "r"(a[0]), "r"(a[1]), "r"(a[2]), "r"(a[3]),
          "r"(b[0]), "r"(b[1]));
}

#define APAD 36     // (g*36+tg) mod 32 = g*4+tg : 32 distinct banks on A-frag reads
#define BPAD 136    // (tg*136+g) mod 32 = tg*8+g : 32 distinct banks on B-frag reads

template <int EPI>
__global__ __launch_bounds__(256) void tgemm_kernel(
    const float* __restrict__ A, const float* __restrict__ Bm,
    const float* __restrict__ bias, float* __restrict__ Co,
    int M, int N, int K,
    const float* __restrict__ add1, const float* __restrict__ add2)
{
    __shared__ uint32_t As[128][APAD];   // [m][k]
    __shared__ uint32_t Bs[32][BPAD];    // [k][n]  (n tile = 128)

    int tid = threadIdx.x;
    int lane = tid & 31, wid = tid >> 5;
    int wm = (wid >> 2) * 64;            // warp tile origin within block
    int wn = (wid & 3) * 32;
    int g  = lane >> 2;                  // 0..7
    int tg = lane & 3;                   // 0..3
    int bm = blockIdx.y * 128, bn = blockIdx.x * 128;

    // global load indexing
    int ar = tid >> 3;                   // +32*i : A row (0..127)
    int ac = (tid & 7) * 4;              // A k-offset (float4), 0..28
    int br = tid >> 5;                   // +8*i  : B k-row (0..31)
    int bc = (tid & 31) * 4;             // B n-offset (float4), 0..124

    const float* Abase = A + (size_t)bm * K;
    const float* Bbase = Bm + bn;

    float acc[4][4][4];
#pragma unroll
    for (int mi = 0; mi < 4; mi++)
#pragma unroll
        for (int ni = 0; ni < 4; ni++)
#pragma unroll
            for (int r = 0; r < 4; r++) acc[mi][ni][r] = 0.f;

    float4 ra[4], rb[4];
    // prologue: load first tile into registers
#pragma unroll
    for (int i = 0; i < 4; i++)
        ra[i] = *(const float4*)(Abase + (size_t)(ar + 32 * i) * K + ac);
#pragma unroll
    for (int i = 0; i < 4; i++)
        rb[i] = *(const float4*)(Bbase + (size_t)(br + 8 * i) * N + bc);

    for (int k0 = 0; k0 < K; k0 += 32) {
        // stage registers -> smem (with tf32 rounding)
#pragma unroll
        for (int i = 0; i < 4; i++) {
            uint4 u = make_uint4(f2tf(ra[i].x), f2tf(ra[i].y),
                                 f2tf(ra[i].z), f2tf(ra[i].w));
            *(uint4*)&As[ar + 32 * i][ac] = u;
        }
#pragma unroll
        for (int i = 0; i < 4; i++) {
            uint4 u = make_uint4(f2tf(rb[i].x), f2tf(rb[i].y),
                                 f2tf(rb[i].z), f2tf(rb[i].w));
            *(uint4*)&Bs[br + 8 * i][bc] = u;
        }
        __syncthreads();

        // prefetch next tile (latency hidden behind the MMA loop)
        if (k0 + 32 < K) {
#pragma unroll
            for (int i = 0; i < 4; i++)
                ra[i] = *(const float4*)(Abase + (size_t)(ar + 32 * i) * K + k0 + 32 + ac);
#pragma unroll
            for (int i = 0; i < 4; i++)
                rb[i] = *(const float4*)(Bbase + (size_t)(k0 + 32 + br + 8 * i) * N + bc);
        }

#pragma unroll
        for (int ks = 0; ks < 4; ks++) {
            int kb = ks * 8;
            uint32_t af[4][4], bf[4][2];
#pragma unroll
            for (int mi = 0; mi < 4; mi++) {
                int m = wm + mi * 16;
                af[mi][0] = As[m + g][kb + tg];
                af[mi][1] = As[m + g + 8][kb + tg];
                af[mi][2] = As[m + g][kb + tg + 4];
                af[mi][3] = As[m + g + 8][kb + tg + 4];
            }
#pragma unroll
            for (int ni = 0; ni < 4; ni++) {
                int n = wn + ni * 8;
                bf[ni][0] = Bs[kb + tg][n + g];
                bf[ni][1] = Bs[kb + tg + 4][n + g];
            }
#pragma unroll
            for (int mi = 0; mi < 4; mi++)
#pragma unroll
                for (int ni = 0; ni < 4; ni++)
                    mma_tf32(acc[mi][ni], af[mi], bf[ni]);
        }
        __syncthreads();
    }

    // epilogue
#pragma unroll
    for (int mi = 0; mi < 4; mi++) {
#pragma unroll
        for (int rr = 0; rr < 2; rr++) {
            int m = bm + wm + mi * 16 + g + rr * 8;
            size_t rowoff = (size_t)m * N;
#pragma unroll
            for (int ni = 0; ni < 4; ni++) {
                int n = bn + wn + ni * 8 + tg * 2;
                float v0 = acc[mi][ni][rr * 2 + 0] + bias[n];
                float v1 = acc[mi][ni][rr * 2 + 1] + bias[n + 1];
                if (EPI == 1) {
                    v0 = 0.5f * v0 * (1.f + erff(v0 * 0.70710678118654752f));
                    v1 = 0.5f * v1 * (1.f + erff(v1 * 0.70710678118654752f));
                }
                if (EPI == 2) {
                    v0 += add1[rowoff + n] + add2[rowoff + n];
                    v1 += add1[rowoff + n + 1] + add2[rowoff + n + 1];
                }
                *(float2*)(Co + rowoff + n) = make_float2(v0, v1);
            }
        }
    }
}

// ---------------- Flash attention, BM=BN=64, D=128, causal, GQA ----------------
#define ATT_PAD  132
#define PS_PAD   68
#define ATT_SMEM ((2 * 64 * ATT_PAD + 64 * PS_PAD) * 4)   // 84992 bytes

__global__ __launch_bounds__(256) void attn_kernel(
    const float* __restrict__ qkv, float* __restrict__ y)
{
    extern __shared__ float smem[];
    float* Qs  = smem;                        // 64 x 132
    float* KVs = smem + 64 * ATT_PAD;         // 64 x 132 (K then reused for V)
    float* Ps  = smem + 2 * 64 * ATT_PAD;     // 64 x 68

    int qt = blockIdx.x;      // query tile 0..31
    int h  = blockIdx.y;      // head
    int b  = blockIdx.z;
    int g  = h >> 2;
    int qcol = (g * 6 + (h & 3)) * HEAD;
    int kcol = (g * 6 + 4) * HEAD;
    int vcol = (g * 6 + 5) * HEAD;

    int tid = threadIdx.x;
    int tr = tid >> 4, tc = tid & 15;
    int qbase = qt * 64;
    const size_t RS = QKV_OUT;

    // load Q tile
    for (int idx = tid; idx < 64 * 32; idx += 256) {
        int rr = idx >> 5, dd = (idx & 31) * 4;
        *(float4*)&Qs[rr * ATT_PAD + dd] =
            *(const float4*)(qkv + (size_t)(b * T_ + qbase + rr) * RS + qcol + dd);
    }

    float acc[4][8];
#pragma unroll
    for (int i = 0; i < 4; i++)
#pragma unroll
        for (int j = 0; j < 8; j++) acc[i][j] = 0.f;
    float rmax[4] = {-1e30f, -1e30f, -1e30f, -1e30f};
    float rsum[4] = {0.f, 0.f, 0.f, 0.f};

    const float scale = 0.08838834764831845f;  // 1/sqrt(128)
    int ntiles = qt + 1;

    for (int kt = 0; kt < ntiles; kt++) {
        int nb = kt * 64;
        __syncthreads();   // KVs free (prev PV done), Ps free
        for (int idx = tid; idx < 64 * 32; idx += 256) {
            int rr = idx >> 5, dd = (idx & 31) * 4;
            *(float4*)&KVs[rr * ATT_PAD + dd] =
                *(const float4*)(qkv + (size_t)(b * T_ + nb + rr) * RS + kcol + dd);
        }
        __syncthreads();

        // S = Q K^T  (4x4 per thread)
        float s[4][4];
#pragma unroll
        for (int i = 0; i < 4; i++)
#pragma unroll
            for (int j = 0; j < 4; j++) s[i][j] = 0.f;
        for (int d = 0; d < 128; d += 4) {
            float4 q[4], k[4];
#pragma unroll
            for (int i = 0; i < 4; i++) q[i] = *(const float4*)&Qs[(tr * 4 + i) * ATT_PAD + d];
#pragma unroll
            for (int j = 0; j < 4; j++) k[j] = *(const float4*)&KVs[(tc * 4 + j) * ATT_PAD + d];
#pragma unroll
            for (int i = 0; i < 4; i++)
#pragma unroll
                for (int j = 0; j < 4; j++)
                    s[i][j] += q[i].x * k[j].x + q[i].y * k[j].y +
                               q[i].z * k[j].z + q[i].w * k[j].w;
        }

        // mask + online softmax update + write P
#pragma unroll
        for (int i = 0; i < 4; i++) {
            int mq = qbase + tr * 4 + i;
            float mloc = -1e30f;
#pragma unroll
            for (int j = 0; j < 4; j++) {
                int nk = nb + tc * 4 + j;
                float sv = s[i][j] * scale;
                if (nk > mq) sv = -1e30f;
                s[i][j] = sv;
                mloc = fmaxf(mloc, sv);
            }
#pragma unroll
            for (int o = 8; o; o >>= 1)
                mloc = fmaxf(mloc, __shfl_xor_sync(0xffffffffu, mloc, o, 16));
            float nm  = fmaxf(rmax[i], mloc);
            float fac = __expf(rmax[i] - nm);
            rmax[i] = nm;
            float ps = 0.f;
#pragma unroll
            for (int j = 0; j < 4; j++) {
                float p = __expf(s[i][j] - nm);
                s[i][j] = p;
                ps += p;
            }
#pragma unroll
            for (int o = 8; o; o >>= 1)
                ps += __shfl_xor_sync(0xffffffffu, ps, o, 16);
            rsum[i] = rsum[i] * fac + ps;
#pragma unroll
            for (int j = 0; j < 8; j++) acc[i][j] *= fac;
#pragma unroll
            for (int j = 0; j < 4; j++)
                Ps[(tr * 4 + i) * PS_PAD + tc * 4 + j] = s[i][j];
        }
        __syncthreads();    // K reads done, P written

        // load V over KVs
        for (int idx = tid; idx < 64 * 32; idx += 256) {
            int rr = idx >> 5, dd = (idx & 31) * 4;
            *(float4*)&KVs[rr * ATT_PAD + dd] =
                *(const float4*)(qkv + (size_t)(b * T_ + nb + rr) * RS + vcol + dd);
        }
        __syncthreads();

        // O += P V   (4 rows x 8 dims per thread)
        for (int kk = 0; kk < 64; kk++) {
            float4 v0 = *(const float4*)&KVs[kk * ATT_PAD + tc * 8];
            float4 v1 = *(const float4*)&KVs[kk * ATT_PAD + tc * 8 + 4];
#pragma unroll
            for (int i = 0; i < 4; i++) {
                float p = Ps[(tr * 4 + i) * PS_PAD + kk];
                acc[i][0] += p * v0.x; acc[i][1] += p * v0.y;
                acc[i][2] += p * v0.z; acc[i][3] += p * v0.w;
                acc[i][4] += p * v1.x; acc[i][5] += p * v1.y;
                acc[i][6] += p * v1.z; acc[i][7] += p * v1.w;
            }
        }
    }

    // write y in [B, T, H, D] layout
#pragma unroll
    for (int i = 0; i < 4; i++) {
        float inv = 1.f / rsum[i];
        size_t m = (size_t)(b * T_ + qbase + tr * 4 + i);
#pragma unroll
        for (int j = 0; j < 8; j++)
            y[m * C_ + h * HEAD + tc * 8 + j] = acc[i][j] * inv;
    }
}

// ---------------- launcher -----------------------------------------------------
extern "C" void kernel_launch(void* const* d_in, const int* in_sizes, int n_in,
                              void* d_out, int out_size)
{
    const float* x     = (const float*)d_in[0];
    const float* cosb  = (const float*)d_in[1];
    const float* sinb  = (const float*)d_in[2];
    const float* ln1w  = (const float*)d_in[3];
    const float* ln1b  = (const float*)d_in[4];
    const float* wqkv  = (const float*)d_in[5];
    const float* bqkv  = (const float*)d_in[6];
    const float* wproj = (const float*)d_in[7];
    const float* bproj = (const float*)d_in[8];
    const float* ln2w  = (const float*)d_in[9];
    const float* ln2b  = (const float*)d_in[10];
    const float* wfc1  = (const float*)d_in[11];
    const float* bfc1  = (const float*)d_in[12];
    const float* wfc2  = (const float*)d_in[13];
    const float* bfc2  = (const float*)d_in[14];
    float* out = (float*)d_out;

    float *ln1, *ln2, *qkv, *y, *h, *act;
    cudaGetSymbolAddress((void**)&ln1, g_ln1);
    cudaGetSymbolAddress((void**)&ln2, g_ln2);
    cudaGetSymbolAddress((void**)&qkv, g_qkv);
    cudaGetSymbolAddress((void**)&y,   g_y);
    cudaGetSymbolAddress((void**)&h,   g_h);
    cudaGetSymbolAddress((void**)&act, g_act);

    // 1. dual LayerNorm
    ln_dual_kernel<<<M_TOK, 256>>>(x, ln1w, ln1b, ln2w, ln2b, ln1, ln2);

    // 2. QKV projection (tf32 tensor cores)
    tgemm_kernel<0><<<dim3(QKV_OUT / 128, M_TOK / 128), 256>>>(
        ln1, wqkv, bqkv, qkv, M_TOK, QKV_OUT, C_, nullptr, nullptr);

    // 3. RoPE
    rope_kernel<<<M_TOK, 320>>>(qkv, cosb, sinb);

    // 4. flash attention
    cudaFuncSetAttribute(attn_kernel, cudaFuncAttributeMaxDynamicSharedMemorySize, ATT_SMEM);
    attn_kernel<<<dim3(T_ / 64, N_HEAD, B_), 256, ATT_SMEM>>>(qkv, y);

    // 5. output projection -> h
    tgemm_kernel<0><<<dim3(C_ / 128, M_TOK / 128), 256>>>(
        y, wproj, bproj, h, M_TOK, C_, C_, nullptr, nullptr);

    // 6. fc1 + GELU -> act
    tgemm_kernel<1><<<dim3(FFN / 128, M_TOK / 128), 256>>>(
        ln2, wfc1, bfc1, act, M_TOK, FFN, C_, nullptr, nullptr);

    // 7. fc2 + h + x -> out
    tgemm_kernel<2><<<dim3(C_ / 128, M_TOK / 128), 256>>>(
        act, wfc2, bfc2, out, M_TOK, C_, FFN, h, x);
}

// round 5
// speedup vs baseline: 3.6951x; 1.5340x over previous
#include <cuda_runtime.h>
#include <math.h>
#include <stdint.h>

#define N_HEAD   16
#define HEAD     128
#define ROPE     32
#define C_       2048
#define B_       2
#define T_       2048
#define M_TOK    (B_*T_)        // 4096
#define QKV_OUT  3072           // (16 + 2*4) * 128
#define FFN      8192

// ---------------- scratch (device globals; no allocations allowed) -------------
__device__ float g_ln1[(size_t)M_TOK * C_];
__device__ float g_ln2[(size_t)M_TOK * C_];
__device__ float g_qkv[(size_t)M_TOK * QKV_OUT];
__device__ float g_y  [(size_t)M_TOK * C_];
__device__ float g_h  [(size_t)M_TOK * C_];
__device__ float g_act[(size_t)M_TOK * FFN];

// ---------------- fused dual LayerNorm (reads x once, writes ln1 & ln2) --------
__global__ __launch_bounds__(256) void ln_dual_kernel(
    const float* __restrict__ x,
    const float* __restrict__ w1, const float* __restrict__ b1,
    const float* __restrict__ w2, const float* __restrict__ b2,
    float* __restrict__ o1, float* __restrict__ o2)
{
    int row = blockIdx.x;
    const float* xr = x + (size_t)row * C_;
    int tid = threadIdx.x;

    float v[8];
    float s = 0.f, s2 = 0.f;
#pragma unroll
    for (int i = 0; i < 8; i++) {
        float t = xr[tid + i * 256];
        v[i] = t; s += t; s2 += t * t;
    }
#pragma unroll
    for (int o = 16; o; o >>= 1) {
        s  += __shfl_xor_sync(0xffffffffu, s,  o);
        s2 += __shfl_xor_sync(0xffffffffu, s2, o);
    }
    __shared__ float sh[16];
    __shared__ float mu_s, rstd_s;
    int w = tid >> 5;
    if ((tid & 31) == 0) { sh[w] = s; sh[w + 8] = s2; }
    __syncthreads();
    if (tid == 0) {
        float a = 0.f, b = 0.f;
#pragma unroll
        for (int i = 0; i < 8; i++) { a += sh[i]; b += sh[i + 8]; }
        float mu  = a * (1.0f / C_);
        float var = b * (1.0f / C_) - mu * mu;
        mu_s = mu;
        rstd_s = rsqrtf(var + 1e-5f);
    }
    __syncthreads();
    float mu = mu_s, rs = rstd_s;
#pragma unroll
    for (int i = 0; i < 8; i++) {
        int c = tid + i * 256;
        float n = (v[i] - mu) * rs;
        o1[(size_t)row * C_ + c] = n * w1[c] + b1[c];
        o2[(size_t)row * C_ + c] = n * w2[c] + b2[c];
    }
}

// ---------------- RoPE in place on qkv (16 q heads + 4 k heads) ----------------
__global__ __launch_bounds__(320) void rope_kernel(
    float* __restrict__ qkv,
    const float* __restrict__ cosb, const float* __restrict__ sinb)
{
    int r = blockIdx.x;
    int t = r & (T_ - 1);
    int tid = threadIdx.x;          // 0..319
    int hh = tid >> 4;              // 0..19
    int i  = tid & 15;
    int col;
    if (hh < 16) col = ((hh >> 2) * 6 + (hh & 3)) * HEAD;   // q heads
    else         col = ((hh - 16) * 6 + 4) * HEAD;          // k heads (slot 4)
    float* p = qkv + (size_t)r * QKV_OUT + col;
    float c1 = cosb[t * ROPE + i],      s1 = sinb[t * ROPE + i];
    float c2 = cosb[t * ROPE + i + 16], s2 = sinb[t * ROPE + i + 16];
    float x1 = p[i], x2 = p[i + 16];
    p[i]      = x1 * c1 - x2 * s1;
    p[i + 16] = x2 * c2 + x1 * s2;
}

// ---------------- tf32 helpers -------------------------------------------------
__device__ __forceinline__ uint32_t f2tf(float f) {
    uint32_t u;
    asm("cvt.rna.tf32.f32 %0, %1;" : "=r"(u) : "f"(f));
    return u;
}

__device__ __forceinline__ void mma_tf32(float* c, const uint32_t* a, const uint32_t* b) {
    asm volatile(
        "mma.sync.aligned.m16n8k8.row.col.f32.tf32.tf32.f32 "
        "{%0,%1,%2,%3}, {%4,%5,%6,%7}, {%8,%9}, {%0,%1,%2,%3};"
        : "+f"(c[0]), "+f"(c[1]), "+f"(c[2]), "+f"(c[3])
        : "r"(a[0]), "r"(a[1]), "r"(a[2]), "r"(a[3]),
          "r"(b[0]), "r"(b[1]));
}

// ---------------- tf32 tensor-core GEMM 128x128x32, 8 warps -------------------
#define APAD 36     // (g*36+tg) mod 32 = g*4+tg : conflict-free A-frag reads
#define BPAD 136    // (tg*136+g) mod 32 = tg*8+g : conflict-free B-frag reads

template <int EPI>
__global__ __launch_bounds__(256) void tgemm_kernel(
    const float* __restrict__ A, const float* __restrict__ Bm,
    const float* __restrict__ bias, float* __restrict__ Co,
    int M, int N, int K,
    const float* __restrict__ add1, const float* __restrict__ add2)
{
    __shared__ uint32_t As[128][APAD];   // [m][k]
    __shared__ uint32_t Bs[32][BPAD];    // [k][n]  (n tile = 128)

    int tid = threadIdx.x;
    int lane = tid & 31, wid = tid >> 5;
    int wm = (wid >> 2) * 64;
    int wn = (wid & 3) * 32;
    int g  = lane >> 2;
    int tg = lane & 3;
    int bm = blockIdx.y * 128, bn = blockIdx.x * 128;

    int ar = tid >> 3;
    int ac = (tid & 7) * 4;
    int br = tid >> 5;
    int bc = (tid & 31) * 4;

    const float* Abase = A + (size_t)bm * K;
    const float* Bbase = Bm + bn;

    float acc[4][4][4];
#pragma unroll
    for (int mi = 0; mi < 4; mi++)
#pragma unroll
        for (int ni = 0; ni < 4; ni++)
#pragma unroll
            for (int r = 0; r < 4; r++) acc[mi][ni][r] = 0.f;

    float4 ra[4], rb[4];
#pragma unroll
    for (int i = 0; i < 4; i++)
        ra[i] = *(const float4*)(Abase + (size_t)(ar + 32 * i) * K + ac);
#pragma unroll
    for (int i = 0; i < 4; i++)
        rb[i] = *(const float4*)(Bbase + (size_t)(br + 8 * i) * N + bc);

    for (int k0 = 0; k0 < K; k0 += 32) {
#pragma unroll
        for (int i = 0; i < 4; i++) {
            uint4 u = make_uint4(f2tf(ra[i].x), f2tf(ra[i].y),
                                 f2tf(ra[i].z), f2tf(ra[i].w));
            *(uint4*)&As[ar + 32 * i][ac] = u;
        }
#pragma unroll
        for (int i = 0; i < 4; i++) {
            uint4 u = make_uint4(f2tf(rb[i].x), f2tf(rb[i].y),
                                 f2tf(rb[i].z), f2tf(rb[i].w));
            *(uint4*)&Bs[br + 8 * i][bc] = u;
        }
        __syncthreads();

        if (k0 + 32 < K) {
#pragma unroll
            for (int i = 0; i < 4; i++)
                ra[i] = *(const float4*)(Abase + (size_t)(ar + 32 * i) * K + k0 + 32 + ac);
#pragma unroll
            for (int i = 0; i < 4; i++)
                rb[i] = *(const float4*)(Bbase + (size_t)(k0 + 32 + br + 8 * i) * N + bc);
        }

#pragma unroll
        for (int ks = 0; ks < 4; ks++) {
            int kb = ks * 8;
            uint32_t af[4][4], bf[4][2];
#pragma unroll
            for (int mi = 0; mi < 4; mi++) {
                int m = wm + mi * 16;
                af[mi][0] = As[m + g][kb + tg];
                af[mi][1] = As[m + g + 8][kb + tg];
                af[mi][2] = As[m + g][kb + tg + 4];
                af[mi][3] = As[m + g + 8][kb + tg + 4];
            }
#pragma unroll
            for (int ni = 0; ni < 4; ni++) {
                int n = wn + ni * 8;
                bf[ni][0] = Bs[kb + tg][n + g];
                bf[ni][1] = Bs[kb + tg + 4][n + g];
            }
#pragma unroll
            for (int mi = 0; mi < 4; mi++)
#pragma unroll
                for (int ni = 0; ni < 4; ni++)
                    mma_tf32(acc[mi][ni], af[mi], bf[ni]);
        }
        __syncthreads();
    }

#pragma unroll
    for (int mi = 0; mi < 4; mi++) {
#pragma unroll
        for (int rr = 0; rr < 2; rr++) {
            int m = bm + wm + mi * 16 + g + rr * 8;
            size_t rowoff = (size_t)m * N;
#pragma unroll
            for (int ni = 0; ni < 4; ni++) {
                int n = bn + wn + ni * 8 + tg * 2;
                float v0 = acc[mi][ni][rr * 2 + 0] + bias[n];
                float v1 = acc[mi][ni][rr * 2 + 1] + bias[n + 1];
                if (EPI == 1) {
                    v0 = 0.5f * v0 * (1.f + erff(v0 * 0.70710678118654752f));
                    v1 = 0.5f * v1 * (1.f + erff(v1 * 0.70710678118654752f));
                }
                if (EPI == 2) {
                    v0 += add1[rowoff + n] + add2[rowoff + n];
                    v1 += add1[rowoff + n + 1] + add2[rowoff + n + 1];
                }
                *(float2*)(Co + rowoff + n) = make_float2(v0, v1);
            }
        }
    }
}

// ---------------- Flash attention, tf32 MMA, BM=64, BN=64, D=128 ---------------
// 128 threads (4 warps). Warp w owns query rows [w*16, w*16+16): all softmax
// row statistics stay within a warp (4-lane shfl groups).
// Q/K pad 132 (bank 4g+tg), V pad 136 (bank 8tg+g), P pad 68 (bank 4g+tg).
#define AQ_PAD 132
#define AK_PAD 132
#define AV_PAD 136
#define AP_PAD 68
// smem words: Q 64*132 + KV 64*136 + P 64*68 = 21504 -> 86016 bytes
#define ATT_SMEM ((64 * AQ_PAD + 64 * AV_PAD + 64 * AP_PAD) * 4)

__global__ __launch_bounds__(128) void attn_kernel(
    const float* __restrict__ qkv, float* __restrict__ y)
{
    extern __shared__ uint32_t asm_[];
    uint32_t* Qs  = asm_;                           // [64][132]
    uint32_t* KVs = asm_ + 64 * AQ_PAD;             // K stride 132 / V stride 136
    uint32_t* Ps  = asm_ + 64 * AQ_PAD + 64 * AV_PAD; // [64][68]

    int qt = blockIdx.x, h = blockIdx.y, b = blockIdx.z;
    int gq = h >> 2;
    int qcol = (gq * 6 + (h & 3)) * HEAD;
    int kcol = (gq * 6 + 4) * HEAD;
    int vcol = (gq * 6 + 5) * HEAD;

    int tid = threadIdx.x, lane = tid & 31, w = tid >> 5;
    int g = lane >> 2, tg = lane & 3;
    int qbase = qt * 64;
    const size_t RS = QKV_OUT;
    const float scale = 0.08838834764831845f;  // 1/sqrt(128)

    // load Q tile (tf32-converted)
    for (int idx = tid; idx < 64 * 32; idx += 128) {
        int rr = idx >> 5, dd = (idx & 31) * 4;
        float4 q = *(const float4*)(qkv + (size_t)(b * T_ + qbase + rr) * RS + qcol + dd);
        *(uint4*)&Qs[rr * AQ_PAD + dd] =
            make_uint4(f2tf(q.x), f2tf(q.y), f2tf(q.z), f2tf(q.w));
    }

    float o[16][4];
#pragma unroll
    for (int nt = 0; nt < 16; nt++)
#pragma unroll
        for (int c = 0; c < 4; c++) o[nt][c] = 0.f;
    float rmax0 = -1e30f, rmax1 = -1e30f;
    float rsum0 = 0.f,    rsum1 = 0.f;

    int row0 = qbase + w * 16 + g;     // this thread's two rows
    int row1 = row0 + 8;

    for (int kt = 0; kt <= qt; kt++) {
        int nb = kt * 64;
        __syncthreads();   // prev PV reads of KVs done; (iter 0: Qs stores done)
        for (int idx = tid; idx < 64 * 32; idx += 128) {
            int rr = idx >> 5, dd = (idx & 31) * 4;
            float4 k = *(const float4*)(qkv + (size_t)(b * T_ + nb + rr) * RS + kcol + dd);
            *(uint4*)&KVs[rr * AK_PAD + dd] =
                make_uint4(f2tf(k.x), f2tf(k.y), f2tf(k.z), f2tf(k.w));
        }
        __syncthreads();

        // S = Q K^T : warp computes 16x64 (8 n-tiles)
        float s[8][4];
#pragma unroll
        for (int nt = 0; nt < 8; nt++)
#pragma unroll
            for (int c = 0; c < 4; c++) s[nt][c] = 0.f;

#pragma unroll
        for (int ks = 0; ks < 16; ks++) {
            int kb = ks * 8;
            uint32_t a[4];
            a[0] = Qs[(w * 16 + g) * AQ_PAD + kb + tg];
            a[1] = Qs[(w * 16 + g + 8) * AQ_PAD + kb + tg];
            a[2] = Qs[(w * 16 + g) * AQ_PAD + kb + tg + 4];
            a[3] = Qs[(w * 16 + g + 8) * AQ_PAD + kb + tg + 4];
#pragma unroll
            for (int nt = 0; nt < 8; nt++) {
                uint32_t bf[2];
                bf[0] = KVs[(nt * 8 + g) * AK_PAD + kb + tg];
                bf[1] = KVs[(nt * 8 + g) * AK_PAD + kb + tg + 4];
                mma_tf32(s[nt], a, bf);
            }
        }

        // scale + causal mask + online softmax
        bool diag = (kt == qt);
        float ml0 = -1e30f, ml1 = -1e30f;
#pragma unroll
        for (int nt = 0; nt < 8; nt++) {
            int colb = nb + nt * 8 + tg * 2;
            float v0 = s[nt][0] * scale, v1 = s[nt][1] * scale;
            float v2 = s[nt][2] * scale, v3 = s[nt][3] * scale;
            if (diag) {
                if (colb     > row0) v0 = -1e30f;
                if (colb + 1 > row0) v1 = -1e30f;
                if (colb     > row1) v2 = -1e30f;
                if (colb + 1 > row1) v3 = -1e30f;
            }
            s[nt][0] = v0; s[nt][1] = v1; s[nt][2] = v2; s[nt][3] = v3;
            ml0 = fmaxf(ml0, fmaxf(v0, v1));
            ml1 = fmaxf(ml1, fmaxf(v2, v3));
        }
        ml0 = fmaxf(ml0, __shfl_xor_sync(0xffffffffu, ml0, 1));
        ml0 = fmaxf(ml0, __shfl_xor_sync(0xffffffffu, ml0, 2));
        ml1 = fmaxf(ml1, __shfl_xor_sync(0xffffffffu, ml1, 1));
        ml1 = fmaxf(ml1, __shfl_xor_sync(0xffffffffu, ml1, 2));

        float nm0 = fmaxf(rmax0, ml0), nm1 = fmaxf(rmax1, ml1);
        float f0 = __expf(rmax0 - nm0), f1 = __expf(rmax1 - nm1);
        rmax0 = nm0; rmax1 = nm1;

        float ps0 = 0.f, ps1 = 0.f;
#pragma unroll
        for (int nt = 0; nt < 8; nt++) {
            float p0 = __expf(s[nt][0] - nm0);
            float p1 = __expf(s[nt][1] - nm0);
            float p2 = __expf(s[nt][2] - nm1);
            float p3 = __expf(s[nt][3] - nm1);
            ps0 += p0 + p1;
            ps1 += p2 + p3;
            *(uint2*)&Ps[(w * 16 + g) * AP_PAD + nt * 8 + tg * 2] =
                make_uint2(f2tf(p0), f2tf(p1));
            *(uint2*)&Ps[(w * 16 + g + 8) * AP_PAD + nt * 8 + tg * 2] =
                make_uint2(f2tf(p2), f2tf(p3));
        }
        ps0 += __shfl_xor_sync(0xffffffffu, ps0, 1);
        ps0 += __shfl_xor_sync(0xffffffffu, ps0, 2);
        ps1 += __shfl_xor_sync(0xffffffffu, ps1, 1);
        ps1 += __shfl_xor_sync(0xffffffffu, ps1, 2);
        rsum0 = rsum0 * f0 + ps0;
        rsum1 = rsum1 * f1 + ps1;

#pragma unroll
        for (int nt = 0; nt < 16; nt++) {
            o[nt][0] *= f0; o[nt][1] *= f0;
            o[nt][2] *= f1; o[nt][3] *= f1;
        }
        __syncthreads();   // K reads done, P written

        // load V over KVs (stride 136)
        for (int idx = tid; idx < 64 * 32; idx += 128) {
            int rr = idx >> 5, dd = (idx & 31) * 4;
            float4 v = *(const float4*)(qkv + (size_t)(b * T_ + nb + rr) * RS + vcol + dd);
            *(uint4*)&KVs[rr * AV_PAD + dd] =
                make_uint4(f2tf(v.x), f2tf(v.y), f2tf(v.z), f2tf(v.w));
        }
        __syncthreads();

        // O += P V : 8 k-steps x 16 n-tiles
#pragma unroll
        for (int ks = 0; ks < 8; ks++) {
            int kb = ks * 8;
            uint32_t a[4];
            a[0] = Ps[(w * 16 + g) * AP_PAD + kb + tg];
            a[1] = Ps[(w * 16 + g + 8) * AP_PAD + kb + tg];
            a[2] = Ps[(w * 16 + g) * AP_PAD + kb + tg + 4];
            a[3] = Ps[(w * 16 + g + 8) * AP_PAD + kb + tg + 4];
#pragma unroll
            for (int nt = 0; nt < 16; nt++) {
                uint32_t bf[2];
                bf[0] = KVs[(kb + tg) * AV_PAD + nt * 8 + g];
                bf[1] = KVs[(kb + tg + 4) * AV_PAD + nt * 8 + g];
                mma_tf32(o[nt], a, bf);
            }
        }
    }

    // write y [B, T, H*D]
    float inv0 = 1.f / rsum0, inv1 = 1.f / rsum1;
    size_t m0 = (size_t)(b * T_ + row0 - qbase + qbase);   // = b*T_ + row0
    size_t m1 = m0 + 8;
#pragma unroll
    for (int nt = 0; nt < 16; nt++) {
        int col = h * HEAD + nt * 8 + tg * 2;
        *(float2*)(y + m0 * C_ + col) = make_float2(o[nt][0] * inv0, o[nt][1] * inv0);
        *(float2*)(y + m1 * C_ + col) = make_float2(o[nt][2] * inv1, o[nt][3] * inv1);
    }
}

// ---------------- launcher -----------------------------------------------------
extern "C" void kernel_launch(void* const* d_in, const int* in_sizes, int n_in,
                              void* d_out, int out_size)
{
    const float* x     = (const float*)d_in[0];
    const float* cosb  = (const float*)d_in[1];
    const float* sinb  = (const float*)d_in[2];
    const float* ln1w  = (const float*)d_in[3];
    const float* ln1b  = (const float*)d_in[4];
    const float* wqkv  = (const float*)d_in[5];
    const float* bqkv  = (const float*)d_in[6];
    const float* wproj = (const float*)d_in[7];
    const float* bproj = (const float*)d_in[8];
    const float* ln2w  = (const float*)d_in[9];
    const float* ln2b  = (const float*)d_in[10];
    const float* wfc1  = (const float*)d_in[11];
    const float* bfc1  = (const float*)d_in[12];
    const float* wfc2  = (const float*)d_in[13];
    const float* bfc2  = (const float*)d_in[14];
    float* out = (float*)d_out;

    float *ln1, *ln2, *qkv, *y, *h, *act;
    cudaGetSymbolAddress((void**)&ln1, g_ln1);
    cudaGetSymbolAddress((void**)&ln2, g_ln2);
    cudaGetSymbolAddress((void**)&qkv, g_qkv);
    cudaGetSymbolAddress((void**)&y,   g_y);
    cudaGetSymbolAddress((void**)&h,   g_h);
    cudaGetSymbolAddress((void**)&act, g_act);

    // 1. dual LayerNorm
    ln_dual_kernel<<<M_TOK, 256>>>(x, ln1w, ln1b, ln2w, ln2b, ln1, ln2);

    // 2. QKV projection (tf32 tensor cores)
    tgemm_kernel<0><<<dim3(QKV_OUT / 128, M_TOK / 128), 256>>>(
        ln1, wqkv, bqkv, qkv, M_TOK, QKV_OUT, C_, nullptr, nullptr);

    // 3. RoPE
    rope_kernel<<<M_TOK, 320>>>(qkv, cosb, sinb);

    // 4. flash attention (tf32 tensor cores)
    cudaFuncSetAttribute(attn_kernel, cudaFuncAttributeMaxDynamicSharedMemorySize, ATT_SMEM);
    attn_kernel<<<dim3(T_ / 64, N_HEAD, B_), 128, ATT_SMEM>>>(qkv, y);

    // 5. output projection -> h
    tgemm_kernel<0><<<dim3(C_ / 128, M_TOK / 128), 256>>>(
        y, wproj, bproj, h, M_TOK, C_, C_, nullptr, nullptr);

    // 6. fc1 + GELU -> act
    tgemm_kernel<1><<<dim3(FFN / 128, M_TOK / 128), 256>>>(
        ln2, wfc1, bfc1, act, M_TOK, FFN, C_, nullptr, nullptr);

    // 7. fc2 + h + x -> out
    tgemm_kernel<2><<<dim3(C_ / 128, M_TOK / 128), 256>>>(
        act, wfc2, bfc2, out, M_TOK, C_, FFN, h, x);
}

// round 6
// speedup vs baseline: 3.8027x; 1.0291x over previous
#include <cuda_runtime.h>
#include <math.h>
#include <stdint.h>

#define N_HEAD   16
#define HEAD     128
#define ROPE     32
#define C_       2048
#define B_       2
#define T_       2048
#define M_TOK    (B_*T_)        // 4096
#define QKV_OUT  3072           // (16 + 2*4) * 128
#define FFN      8192

// ---------------- scratch (device globals; no allocations allowed) -------------
__device__ float g_ln1[(size_t)M_TOK * C_];
__device__ float g_ln2[(size_t)M_TOK * C_];
__device__ float g_qkv[(size_t)M_TOK * QKV_OUT];
__device__ float g_y  [(size_t)M_TOK * C_];
__device__ float g_h  [(size_t)M_TOK * C_];
__device__ float g_act[(size_t)M_TOK * FFN];

// ---------------- fused dual LayerNorm -----------------------------------------
__global__ __launch_bounds__(256) void ln_dual_kernel(
    const float* __restrict__ x,
    const float* __restrict__ w1, const float* __restrict__ b1,
    const float* __restrict__ w2, const float* __restrict__ b2,
    float* __restrict__ o1, float* __restrict__ o2)
{
    int row = blockIdx.x;
    const float* xr = x + (size_t)row * C_;
    int tid = threadIdx.x;

    float v[8];
    float s = 0.f, s2 = 0.f;
#pragma unroll
    for (int i = 0; i < 8; i++) {
        float t = xr[tid + i * 256];
        v[i] = t; s += t; s2 += t * t;
    }
#pragma unroll
    for (int o = 16; o; o >>= 1) {
        s  += __shfl_xor_sync(0xffffffffu, s,  o);
        s2 += __shfl_xor_sync(0xffffffffu, s2, o);
    }
    __shared__ float sh[16];
    __shared__ float mu_s, rstd_s;
    int w = tid >> 5;
    if ((tid & 31) == 0) { sh[w] = s; sh[w + 8] = s2; }
    __syncthreads();
    if (tid == 0) {
        float a = 0.f, b = 0.f;
#pragma unroll
        for (int i = 0; i < 8; i++) { a += sh[i]; b += sh[i + 8]; }
        float mu  = a * (1.0f / C_);
        float var = b * (1.0f / C_) - mu * mu;
        mu_s = mu;
        rstd_s = rsqrtf(var + 1e-5f);
    }
    __syncthreads();
    float mu = mu_s, rs = rstd_s;
#pragma unroll
    for (int i = 0; i < 8; i++) {
        int c = tid + i * 256;
        float n = (v[i] - mu) * rs;
        o1[(size_t)row * C_ + c] = n * w1[c] + b1[c];
        o2[(size_t)row * C_ + c] = n * w2[c] + b2[c];
    }
}

// ---------------- RoPE in place on qkv ------------------------------------------
__global__ __launch_bounds__(320) void rope_kernel(
    float* __restrict__ qkv,
    const float* __restrict__ cosb, const float* __restrict__ sinb)
{
    int r = blockIdx.x;
    int t = r & (T_ - 1);
    int tid = threadIdx.x;          // 0..319
    int hh = tid >> 4;              // 0..19
    int i  = tid & 15;
    int col;
    if (hh < 16) col = ((hh >> 2) * 6 + (hh & 3)) * HEAD;   // q heads
    else         col = ((hh - 16) * 6 + 4) * HEAD;          // k heads (slot 4)
    float* p = qkv + (size_t)r * QKV_OUT + col;
    float c1 = cosb[t * ROPE + i],      s1 = sinb[t * ROPE + i];
    float c2 = cosb[t * ROPE + i + 16], s2 = sinb[t * ROPE + i + 16];
    float x1 = p[i], x2 = p[i + 16];
    p[i]      = x1 * c1 - x2 * s1;
    p[i + 16] = x2 * c2 + x1 * s2;
}

// ---------------- tf32 helpers ---------------------------------------------------
__device__ __forceinline__ uint32_t f2tf(float f) {
    uint32_t u;
    asm("cvt.rna.tf32.f32 %0, %1;" : "=r"(u) : "f"(f));
    return u;
}

__device__ __forceinline__ void mma_tf32(float* c, const uint32_t* a, const uint32_t* b) {
    asm volatile(
        "mma.sync.aligned.m16n8k8.row.col.f32.tf32.tf32.f32 "
        "{%0,%1,%2,%3}, {%4,%5,%6,%7}, {%8,%9}, {%0,%1,%2,%3};"
        : "+f"(c[0]), "+f"(c[1]), "+f"(c[2]), "+f"(c[3])
        : "r"(a[0]), "r"(a[1]), "r"(a[2]), "r"(a[3]),
          "r"(b[0]), "r"(b[1]));
}

// ---------------- tf32 tensor-core GEMM 128x256x32, 8 warps, double-buffered ----
// warp tile 64x64; pads: APAD=36 (bank 4g+tg), BPAD=264 (bank 8tg+g)
#define APAD 36
#define BPAD 264
#define GSM_WORDS (2 * 128 * APAD + 2 * 32 * BPAD)    // 26112 words
#define GSM_BYTES (GSM_WORDS * 4)                     // 104448 bytes

template <int EPI>
__global__ __launch_bounds__(256, 1) void tgemm_kernel(
    const float* __restrict__ A, const float* __restrict__ Bm,
    const float* __restrict__ bias, float* __restrict__ Co,
    int M, int N, int K,
    const float* __restrict__ add1, const float* __restrict__ add2)
{
    extern __shared__ uint32_t gsm[];
    uint32_t* As = gsm;                    // [2][128][APAD]
    uint32_t* Bs = gsm + 2 * 128 * APAD;   // [2][32][BPAD]

    int tid = threadIdx.x;
    int lane = tid & 31, wid = tid >> 5;
    int wm = (wid >> 2) * 64;              // 2 warp rows
    int wn = (wid & 3) * 64;               // 4 warp cols
    int g  = lane >> 2;
    int tg = lane & 3;
    int bm = blockIdx.y * 128, bn = blockIdx.x * 256;

    // global load indexing
    int ar = tid >> 3;                     // A row (0..31), +32*i
    int ac = (tid & 7) * 4;                // A k-offset float4
    int br = tid >> 5;                     // B k-row (0..7), +8*i
    int bc = (tid & 31) * 4;               // B n-offset float4, +128*p

    const float* Abase = A + (size_t)bm * K;
    const float* Bbase = Bm + bn;

    float acc[4][8][4];
#pragma unroll
    for (int mi = 0; mi < 4; mi++)
#pragma unroll
        for (int ni = 0; ni < 8; ni++)
#pragma unroll
            for (int r = 0; r < 4; r++) acc[mi][ni][r] = 0.f;

    float4 ra[4], rb[4][2];

    // prologue: tile 0 -> buffer 0
#pragma unroll
    for (int i = 0; i < 4; i++)
        ra[i] = *(const float4*)(Abase + (size_t)(ar + 32 * i) * K + ac);
#pragma unroll
    for (int i = 0; i < 4; i++)
#pragma unroll
        for (int p = 0; p < 2; p++)
            rb[i][p] = *(const float4*)(Bbase + (size_t)(br + 8 * i) * N + bc + 128 * p);

#pragma unroll
    for (int i = 0; i < 4; i++) {
        *(uint4*)&As[(ar + 32 * i) * APAD + ac] =
            make_uint4(f2tf(ra[i].x), f2tf(ra[i].y), f2tf(ra[i].z), f2tf(ra[i].w));
    }
#pragma unroll
    for (int i = 0; i < 4; i++)
#pragma unroll
        for (int p = 0; p < 2; p++) {
            *(uint4*)&Bs[(br + 8 * i) * BPAD + bc + 128 * p] =
                make_uint4(f2tf(rb[i][p].x), f2tf(rb[i][p].y),
                           f2tf(rb[i][p].z), f2tf(rb[i][p].w));
        }
    __syncthreads();

    for (int k0 = 0; k0 < K; k0 += 32) {
        int buf = (k0 >> 5) & 1;
        uint32_t* Ab = As + buf * 128 * APAD;
        uint32_t* Bb = Bs + buf * 32 * BPAD;
        bool more = (k0 + 32 < K);

        // issue next tile's global loads (latency hidden by MMA loop)
        if (more) {
#pragma unroll
            for (int i = 0; i < 4; i++)
                ra[i] = *(const float4*)(Abase + (size_t)(ar + 32 * i) * K + k0 + 32 + ac);
#pragma unroll
            for (int i = 0; i < 4; i++)
#pragma unroll
                for (int p = 0; p < 2; p++)
                    rb[i][p] = *(const float4*)(Bbase + (size_t)(k0 + 32 + br + 8 * i) * N + bc + 128 * p);
        }

#pragma unroll
        for (int ks = 0; ks < 4; ks++) {
            int kb = ks * 8;
            uint32_t af[4][4], bf[8][2];
#pragma unroll
            for (int mi = 0; mi < 4; mi++) {
                int m = wm + mi * 16;
                af[mi][0] = Ab[(m + g) * APAD + kb + tg];
                af[mi][1] = Ab[(m + g + 8) * APAD + kb + tg];
                af[mi][2] = Ab[(m + g) * APAD + kb + tg + 4];
                af[mi][3] = Ab[(m + g + 8) * APAD + kb + tg + 4];
            }
#pragma unroll
            for (int ni = 0; ni < 8; ni++) {
                int n = wn + ni * 8;
                bf[ni][0] = Bb[(kb + tg) * BPAD + n + g];
                bf[ni][1] = Bb[(kb + tg + 4) * BPAD + n + g];
            }
#pragma unroll
            for (int mi = 0; mi < 4; mi++)
#pragma unroll
                for (int ni = 0; ni < 8; ni++)
                    mma_tf32(acc[mi][ni], af[mi], bf[ni]);
        }

        // store next tile into the other buffer
        if (more) {
            uint32_t* An = As + (buf ^ 1) * 128 * APAD;
            uint32_t* Bn = Bs + (buf ^ 1) * 32 * BPAD;
#pragma unroll
            for (int i = 0; i < 4; i++) {
                *(uint4*)&An[(ar + 32 * i) * APAD + ac] =
                    make_uint4(f2tf(ra[i].x), f2tf(ra[i].y), f2tf(ra[i].z), f2tf(ra[i].w));
            }
#pragma unroll
            for (int i = 0; i < 4; i++)
#pragma unroll
                for (int p = 0; p < 2; p++) {
                    *(uint4*)&Bn[(br + 8 * i) * BPAD + bc + 128 * p] =
                        make_uint4(f2tf(rb[i][p].x), f2tf(rb[i][p].y),
                                   f2tf(rb[i][p].z), f2tf(rb[i][p].w));
                }
        }
        __syncthreads();
    }

    // epilogue
#pragma unroll
    for (int mi = 0; mi < 4; mi++) {
#pragma unroll
        for (int rr = 0; rr < 2; rr++) {
            int m = bm + wm + mi * 16 + g + rr * 8;
            size_t rowoff = (size_t)m * N;
#pragma unroll
            for (int ni = 0; ni < 8; ni++) {
                int n = bn + wn + ni * 8 + tg * 2;
                float v0 = acc[mi][ni][rr * 2 + 0] + bias[n];
                float v1 = acc[mi][ni][rr * 2 + 1] + bias[n + 1];
                if (EPI == 1) {
                    v0 = 0.5f * v0 * (1.f + erff(v0 * 0.70710678118654752f));
                    v1 = 0.5f * v1 * (1.f + erff(v1 * 0.70710678118654752f));
                }
                if (EPI == 2) {
                    v0 += add1[rowoff + n] + add2[rowoff + n];
                    v1 += add1[rowoff + n + 1] + add2[rowoff + n + 1];
                }
                *(float2*)(Co + rowoff + n) = make_float2(v0, v1);
            }
        }
    }
}

// ---------------- Flash attention, tf32 MMA, BM=64, BN=64, D=128 ---------------
#define AQ_PAD 132
#define AK_PAD 132
#define AV_PAD 136
#define AP_PAD 68
#define ATT_SMEM ((64 * AQ_PAD + 64 * AV_PAD + 64 * AP_PAD) * 4)

__global__ __launch_bounds__(128) void attn_kernel(
    const float* __restrict__ qkv, float* __restrict__ y)
{
    extern __shared__ uint32_t asm_[];
    uint32_t* Qs  = asm_;                             // [64][132]
    uint32_t* KVs = asm_ + 64 * AQ_PAD;               // K stride 132 / V stride 136
    uint32_t* Ps  = asm_ + 64 * AQ_PAD + 64 * AV_PAD; // [64][68]

    int qt = blockIdx.x, h = blockIdx.y, b = blockIdx.z;
    int gq = h >> 2;
    int qcol = (gq * 6 + (h & 3)) * HEAD;
    int kcol = (gq * 6 + 4) * HEAD;
    int vcol = (gq * 6 + 5) * HEAD;

    int tid = threadIdx.x, lane = tid & 31, w = tid >> 5;
    int g = lane >> 2, tg = lane & 3;
    int qbase = qt * 64;
    const size_t RS = QKV_OUT;
    const float scale = 0.08838834764831845f;  // 1/sqrt(128)

    for (int idx = tid; idx < 64 * 32; idx += 128) {
        int rr = idx >> 5, dd = (idx & 31) * 4;
        float4 q = *(const float4*)(qkv + (size_t)(b * T_ + qbase + rr) * RS + qcol + dd);
        *(uint4*)&Qs[rr * AQ_PAD + dd] =
            make_uint4(f2tf(q.x), f2tf(q.y), f2tf(q.z), f2tf(q.w));
    }

    float o[16][4];
#pragma unroll
    for (int nt = 0; nt < 16; nt++)
#pragma unroll
        for (int c = 0; c < 4; c++) o[nt][c] = 0.f;
    float rmax0 = -1e30f, rmax1 = -1e30f;
    float rsum0 = 0.f,    rsum1 = 0.f;

    int row0 = qbase + w * 16 + g;
    int row1 = row0 + 8;

    for (int kt = 0; kt <= qt; kt++) {
        int nb = kt * 64;
        __syncthreads();
        for (int idx = tid; idx < 64 * 32; idx += 128) {
            int rr = idx >> 5, dd = (idx & 31) * 4;
            float4 k = *(const float4*)(qkv + (size_t)(b * T_ + nb + rr) * RS + kcol + dd);
            *(uint4*)&KVs[rr * AK_PAD + dd] =
                make_uint4(f2tf(k.x), f2tf(k.y), f2tf(k.z), f2tf(k.w));
        }
        __syncthreads();

        float s[8][4];
#pragma unroll
        for (int nt = 0; nt < 8; nt++)
#pragma unroll
            for (int c = 0; c < 4; c++) s[nt][c] = 0.f;

#pragma unroll
        for (int ks = 0; ks < 16; ks++) {
            int kb = ks * 8;
            uint32_t a[4];
            a[0] = Qs[(w * 16 + g) * AQ_PAD + kb + tg];
            a[1] = Qs[(w * 16 + g + 8) * AQ_PAD + kb + tg];
            a[2] = Qs[(w * 16 + g) * AQ_PAD + kb + tg + 4];
            a[3] = Qs[(w * 16 + g + 8) * AQ_PAD + kb + tg + 4];
#pragma unroll
            for (int nt = 0; nt < 8; nt++) {
                uint32_t bf[2];
                bf[0] = KVs[(nt * 8 + g) * AK_PAD + kb + tg];
                bf[1] = KVs[(nt * 8 + g) * AK_PAD + kb + tg + 4];
                mma_tf32(s[nt], a, bf);
            }
        }

        bool diag = (kt == qt);
        float ml0 = -1e30f, ml1 = -1e30f;
#pragma unroll
        for (int nt = 0; nt < 8; nt++) {
            int colb = nb + nt * 8 + tg * 2;
            float v0 = s[nt][0] * scale, v1 = s[nt][1] * scale;
            float v2 = s[nt][2] * scale, v3 = s[nt][3] * scale;
            if (diag) {
                if (colb     > row0) v0 = -1e30f;
                if (colb + 1 > row0) v1 = -1e30f;
                if (colb     > row1) v2 = -1e30f;
                if (colb + 1 > row1) v3 = -1e30f;
            }
            s[nt][0] = v0; s[nt][1] = v1; s[nt][2] = v2; s[nt][3] = v3;
            ml0 = fmaxf(ml0, fmaxf(v0, v1));
            ml1 = fmaxf(ml1, fmaxf(v2, v3));
        }
        ml0 = fmaxf(ml0, __shfl_xor_sync(0xffffffffu, ml0, 1));
        ml0 = fmaxf(ml0, __shfl_xor_sync(0xffffffffu, ml0, 2));
        ml1 = fmaxf(ml1, __shfl_xor_sync(0xffffffffu, ml1, 1));
        ml1 = fmaxf(ml1, __shfl_xor_sync(0xffffffffu, ml1, 2));

        float nm0 = fmaxf(rmax0, ml0), nm1 = fmaxf(rmax1, ml1);
        float f0 = __expf(rmax0 - nm0), f1 = __expf(rmax1 - nm1);
        rmax0 = nm0; rmax1 = nm1;

        float ps0 = 0.f, ps1 = 0.f;
#pragma unroll
        for (int nt = 0; nt < 8; nt++) {
            float p0 = __expf(s[nt][0] - nm0);
            float p1 = __expf(s[nt][1] - nm0);
            float p2 = __expf(s[nt][2] - nm1);
            float p3 = __expf(s[nt][3] - nm1);
            ps0 += p0 + p1;
            ps1 += p2 + p3;
            *(uint2*)&Ps[(w * 16 + g) * AP_PAD + nt * 8 + tg * 2] =
                make_uint2(f2tf(p0), f2tf(p1));
            *(uint2*)&Ps[(w * 16 + g + 8) * AP_PAD + nt * 8 + tg * 2] =
                make_uint2(f2tf(p2), f2tf(p3));
        }
        ps0 += __shfl_xor_sync(0xffffffffu, ps0, 1);
        ps0 += __shfl_xor_sync(0xffffffffu, ps0, 2);
        ps1 += __shfl_xor_sync(0xffffffffu, ps1, 1);
        ps1 += __shfl_xor_sync(0xffffffffu, ps1, 2);
        rsum0 = rsum0 * f0 + ps0;
        rsum1 = rsum1 * f1 + ps1;

#pragma unroll
        for (int nt = 0; nt < 16; nt++) {
            o[nt][0] *= f0; o[nt][1] *= f0;
            o[nt][2] *= f1; o[nt][3] *= f1;
        }
        __syncthreads();

        for (int idx = tid; idx < 64 * 32; idx += 128) {
            int rr = idx >> 5, dd = (idx & 31) * 4;
            float4 v = *(const float4*)(qkv + (size_t)(b * T_ + nb + rr) * RS + vcol + dd);
            *(uint4*)&KVs[rr * AV_PAD + dd] =
                make_uint4(f2tf(v.x), f2tf(v.y), f2tf(v.z), f2tf(v.w));
        }
        __syncthreads();

#pragma unroll
        for (int ks = 0; ks < 8; ks++) {
            int kb = ks * 8;
            uint32_t a[4];
            a[0] = Ps[(w * 16 + g) * AP_PAD + kb + tg];
            a[1] = Ps[(w * 16 + g + 8) * AP_PAD + kb + tg];
            a[2] = Ps[(w * 16 + g) * AP_PAD + kb + tg + 4];
            a[3] = Ps[(w * 16 + g + 8) * AP_PAD + kb + tg + 4];
#pragma unroll
            for (int nt = 0; nt < 16; nt++) {
                uint32_t bf[2];
                bf[0] = KVs[(kb + tg) * AV_PAD + nt * 8 + g];
                bf[1] = KVs[(kb + tg + 4) * AV_PAD + nt * 8 + g];
                mma_tf32(o[nt], a, bf);
            }
        }
    }

    float inv0 = 1.f / rsum0, inv1 = 1.f / rsum1;
    size_t m0 = (size_t)(b * T_ + row0);
    size_t m1 = m0 + 8;
#pragma unroll
    for (int nt = 0; nt < 16; nt++) {
        int col = h * HEAD + nt * 8 + tg * 2;
        *(float2*)(y + m0 * C_ + col) = make_float2(o[nt][0] * inv0, o[nt][1] * inv0);
        *(float2*)(y + m1 * C_ + col) = make_float2(o[nt][2] * inv1, o[nt][3] * inv1);
    }
}

// ---------------- launcher -----------------------------------------------------
extern "C" void kernel_launch(void* const* d_in, const int* in_sizes, int n_in,
                              void* d_out, int out_size)
{
    const float* x     = (const float*)d_in[0];
    const float* cosb  = (const float*)d_in[1];
    const float* sinb  = (const float*)d_in[2];
    const float* ln1w  = (const float*)d_in[3];
    const float* ln1b  = (const float*)d_in[4];
    const float* wqkv  = (const float*)d_in[5];
    const float* bqkv  = (const float*)d_in[6];
    const float* wproj = (const float*)d_in[7];
    const float* bproj = (const float*)d_in[8];
    const float* ln2w  = (const float*)d_in[9];
    const float* ln2b  = (const float*)d_in[10];
    const float* wfc1  = (const float*)d_in[11];
    const float* bfc1  = (const float*)d_in[12];
    const float* wfc2  = (const float*)d_in[13];
    const float* bfc2  = (const float*)d_in[14];
    float* out = (float*)d_out;

    float *ln1, *ln2, *qkv, *y, *h, *act;
    cudaGetSymbolAddress((void**)&ln1, g_ln1);
    cudaGetSymbolAddress((void**)&ln2, g_ln2);
    cudaGetSymbolAddress((void**)&qkv, g_qkv);
    cudaGetSymbolAddress((void**)&y,   g_y);
    cudaGetSymbolAddress((void**)&h,   g_h);
    cudaGetSymbolAddress((void**)&act, g_act);

    cudaFuncSetAttribute(tgemm_kernel<0>, cudaFuncAttributeMaxDynamicSharedMemorySize, GSM_BYTES);
    cudaFuncSetAttribute(tgemm_kernel<1>, cudaFuncAttributeMaxDynamicSharedMemorySize, GSM_BYTES);
    cudaFuncSetAttribute(tgemm_kernel<2>, cudaFuncAttributeMaxDynamicSharedMemorySize, GSM_BYTES);
    cudaFuncSetAttribute(attn_kernel, cudaFuncAttributeMaxDynamicSharedMemorySize, ATT_SMEM);

    // 1. dual LayerNorm
    ln_dual_kernel<<<M_TOK, 256>>>(x, ln1w, ln1b, ln2w, ln2b, ln1, ln2);

    // 2. QKV projection
    tgemm_kernel<0><<<dim3(QKV_OUT / 256, M_TOK / 128), 256, GSM_BYTES>>>(
        ln1, wqkv, bqkv, qkv, M_TOK, QKV_OUT, C_, nullptr, nullptr);

    // 3. RoPE
    rope_kernel<<<M_TOK, 320>>>(qkv, cosb, sinb);

    // 4. flash attention
    attn_kernel<<<dim3(T_ / 64, N_HEAD, B_), 128, ATT_SMEM>>>(qkv, y);

    // 5. output projection -> h
    tgemm_kernel<0><<<dim3(C_ / 256, M_TOK / 128), 256, GSM_BYTES>>>(
        y, wproj, bproj, h, M_TOK, C_, C_, nullptr, nullptr);

    // 6. fc1 + GELU -> act
    tgemm_kernel<1><<<dim3(FFN / 256, M_TOK / 128), 256, GSM_BYTES>>>(
        ln2, wfc1, bfc1, act, M_TOK, FFN, C_, nullptr, nullptr);

    // 7. fc2 + h + x -> out
    tgemm_kernel<2><<<dim3(C_ / 256, M_TOK / 128), 256, GSM_BYTES>>>(
        act, wfc2, bfc2, out, M_TOK, C_, FFN, h, x);
}

// round 8
// speedup vs baseline: 3.8119x; 1.0024x over previous
#include <cuda_runtime.h>
#include <math.h>
#include <stdint.h>

#define N_HEAD   16
#define HEAD     128
#define ROPE     32
#define C_       2048
#define B_       2
#define T_       2048
#define M_TOK    (B_*T_)        // 4096
#define QKV_OUT  3072           // (16 + 2*4) * 128
#define FFN      8192

// ---------------- scratch (device globals; no allocations allowed) -------------
__device__ float g_ln1[(size_t)M_TOK * C_];
__device__ float g_ln2[(size_t)M_TOK * C_];
__device__ float g_qkv[(size_t)M_TOK * QKV_OUT];
__device__ float g_y  [(size_t)M_TOK * C_];
__device__ float g_h  [(size_t)M_TOK * C_];
__device__ float g_act[(size_t)M_TOK * FFN];

// ---------------- fused dual LayerNorm -----------------------------------------
__global__ __launch_bounds__(256) void ln_dual_kernel(
    const float* __restrict__ x,
    const float* __restrict__ w1, const float* __restrict__ b1,
    const float* __restrict__ w2, const float* __restrict__ b2,
    float* __restrict__ o1, float* __restrict__ o2)
{
    int row = blockIdx.x;
    const float* xr = x + (size_t)row * C_;
    int tid = threadIdx.x;

    float v[8];
    float s = 0.f, s2 = 0.f;
#pragma unroll
    for (int i = 0; i < 8; i++) {
        float t = xr[tid + i * 256];
        v[i] = t; s += t; s2 += t * t;
    }
#pragma unroll
    for (int o = 16; o; o >>= 1) {
        s  += __shfl_xor_sync(0xffffffffu, s,  o);
        s2 += __shfl_xor_sync(0xffffffffu, s2, o);
    }
    __shared__ float sh[16];
    __shared__ float mu_s, rstd_s;
    int w = tid >> 5;
    if ((tid & 31) == 0) { sh[w] = s; sh[w + 8] = s2; }
    __syncthreads();
    if (tid == 0) {
        float a = 0.f, b = 0.f;
#pragma unroll
        for (int i = 0; i < 8; i++) { a += sh[i]; b += sh[i + 8]; }
        float mu  = a * (1.0f / C_);
        float var = b * (1.0f / C_) - mu * mu;
        mu_s = mu;
        rstd_s = rsqrtf(var + 1e-5f);
    }
    __syncthreads();
    float mu = mu_s, rs = rstd_s;
#pragma unroll
    for (int i = 0; i < 8; i++) {
        int c = tid + i * 256;
        float n = (v[i] - mu) * rs;
        o1[(size_t)row * C_ + c] = n * w1[c] + b1[c];
        o2[(size_t)row * C_ + c] = n * w2[c] + b2[c];
    }
}

// ---------------- RoPE in place on qkv ------------------------------------------
__global__ __launch_bounds__(320) void rope_kernel(
    float* __restrict__ qkv,
    const float* __restrict__ cosb, const float* __restrict__ sinb)
{
    int r = blockIdx.x;
    int t = r & (T_ - 1);
    int tid = threadIdx.x;          // 0..319
    int hh = tid >> 4;              // 0..19
    int i  = tid & 15;
    int col;
    if (hh < 16) col = ((hh >> 2) * 6 + (hh & 3)) * HEAD;   // q heads
    else         col = ((hh - 16) * 6 + 4) * HEAD;          // k heads (slot 4)
    float* p = qkv + (size_t)r * QKV_OUT + col;
    float c1 = cosb[t * ROPE + i],      s1 = sinb[t * ROPE + i];
    float c2 = cosb[t * ROPE + i + 16], s2 = sinb[t * ROPE + i + 16];
    float x1 = p[i], x2 = p[i + 16];
    p[i]      = x1 * c1 - x2 * s1;
    p[i + 16] = x2 * c2 + x1 * s2;
}

// ---------------- tf32 / cp.async helpers ----------------------------------------
__device__ __forceinline__ uint32_t f2tf(float f) {
    uint32_t u;
    asm("cvt.rna.tf32.f32 %0, %1;" : "=r"(u) : "f"(f));
    return u;
}

__device__ __forceinline__ void mma_tf32(float* c, const uint32_t* a, const uint32_t* b) {
    asm volatile(
        "mma.sync.aligned.m16n8k8.row.col.f32.tf32.tf32.f32 "
        "{%0,%1,%2,%3}, {%4,%5,%6,%7}, {%8,%9}, {%0,%1,%2,%3};"
        : "+f"(c[0]), "+f"(c[1]), "+f"(c[2]), "+f"(c[3])
        : "r"(a[0]), "r"(a[1]), "r"(a[2]), "r"(a[3]),
          "r"(b[0]), "r"(b[1]));
}

__device__ __forceinline__ void cp16(float* smem, const float* gmem) {
    uint32_t sa = (uint32_t)__cvta_generic_to_shared(smem);
    asm volatile("cp.async.cg.shared.global [%0], [%1], 16;" :: "r"(sa), "l"(gmem));
}
#define CP_COMMIT() asm volatile("cp.async.commit_group;" ::: "memory")
#define CP_WAIT(n)  asm volatile("cp.async.wait_group %0;" :: "n"(n) : "memory")

// ---------------- tf32 GEMM 128x256x32, 8 warps, 3-stage cp.async pipeline ------
// warp tile 64x64. smem fp32; tf32 cvt at fragment-read time.
// APAD=36 (bank 4g+tg), BPAD=264 (bank 8tg+g) — conflict-free frag reads.
#define APAD 36
#define BPAD 264
#define ASZ  (128 * APAD)              // 4608 words
#define BSZ  (32 * BPAD)               // 8448 words
#define STG  (ASZ + BSZ)               // 13056 words per stage
#define GSM_BYTES (3 * STG * 4)        // 156672 bytes

template <int EPI>
__global__ __launch_bounds__(256, 1) void tgemm_kernel(
    const float* __restrict__ A, const float* __restrict__ Bm,
    const float* __restrict__ bias, float* __restrict__ Co,
    int M, int N, int K,
    const float* __restrict__ add1, const float* __restrict__ add2)
{
    extern __shared__ float gsm[];

    int tid = threadIdx.x;
    int lane = tid & 31, wid = tid >> 5;
    int wm = (wid >> 2) * 64;
    int wn = (wid & 3) * 64;
    int g  = lane >> 2;
    int tg = lane & 3;
    int bm = blockIdx.y * 128, bn = blockIdx.x * 256;

    int ar = tid >> 3;                 // A row 0..31 (+32*i)
    int ac = (tid & 7) * 4;            // A k word offset
    int br = tid >> 5;                 // B k-row 0..7 (+8*i)
    int bc = (tid & 31) * 4;           // B n word offset (+128*p)

    const float* Abase = A + (size_t)bm * K;
    const float* Bbase = Bm + bn;

    float acc[4][8][4];
#pragma unroll
    for (int mi = 0; mi < 4; mi++)
#pragma unroll
        for (int ni = 0; ni < 8; ni++)
#pragma unroll
            for (int r = 0; r < 4; r++) acc[mi][ni][r] = 0.f;

    int nIter = K >> 5;

    // issue tile `it` into stage s
    auto issue = [&](int it, int s) {
        float* As = gsm + s * STG;
        float* Bs = As + ASZ;
        int k0 = it << 5;
#pragma unroll
        for (int i = 0; i < 4; i++)
            cp16(&As[(ar + 32 * i) * APAD + ac],
                 Abase + (size_t)(ar + 32 * i) * K + k0 + ac);
#pragma unroll
        for (int i = 0; i < 4; i++)
#pragma unroll
            for (int p = 0; p < 2; p++)
                cp16(&Bs[(br + 8 * i) * BPAD + bc + 128 * p],
                     Bbase + (size_t)(k0 + br + 8 * i) * N + bc + 128 * p);
        CP_COMMIT();
    };

    // prologue: stages 0 and 1 in flight
    issue(0, 0);
    issue(1, 1);

    for (int it = 0; it < nIter; it++) {
        int s = it % 3;
        // tile `it` must be complete; allow the one younger group to fly
        if (it + 1 < nIter) { CP_WAIT(1); } else { CP_WAIT(0); }
        __syncthreads();   // tile `it` visible to all; all warps done with stage (it+2)%3

        if (it + 2 < nIter) issue(it + 2, (it + 2) % 3);

        const float* Ab = gsm + s * STG;
        const float* Bb = Ab + ASZ;

#pragma unroll
        for (int ks = 0; ks < 4; ks++) {
            int kb = ks * 8;
            uint32_t af[4][4], bf[8][2];
#pragma unroll
            for (int mi = 0; mi < 4; mi++) {
                int m = wm + mi * 16;
                af[mi][0] = f2tf(Ab[(m + g) * APAD + kb + tg]);
                af[mi][1] = f2tf(Ab[(m + g + 8) * APAD + kb + tg]);
                af[mi][2] = f2tf(Ab[(m + g) * APAD + kb + tg + 4]);
                af[mi][3] = f2tf(Ab[(m + g + 8) * APAD + kb + tg + 4]);
            }
#pragma unroll
            for (int ni = 0; ni < 8; ni++) {
                int n = wn + ni * 8;
                bf[ni][0] = f2tf(Bb[(kb + tg) * BPAD + n + g]);
                bf[ni][1] = f2tf(Bb[(kb + tg + 4) * BPAD + n + g]);
            }
#pragma unroll
            for (int mi = 0; mi < 4; mi++)
#pragma unroll
                for (int ni = 0; ni < 8; ni++)
                    mma_tf32(acc[mi][ni], af[mi], bf[ni]);
        }
    }

    // epilogue
#pragma unroll
    for (int mi = 0; mi < 4; mi++) {
#pragma unroll
        for (int rr = 0; rr < 2; rr++) {
            int m = bm + wm + mi * 16 + g + rr * 8;
            size_t rowoff = (size_t)m * N;
#pragma unroll
            for (int ni = 0; ni < 8; ni++) {
                int n = bn + wn + ni * 8 + tg * 2;
                float v0 = acc[mi][ni][rr * 2 + 0] + bias[n];
                float v1 = acc[mi][ni][rr * 2 + 1] + bias[n + 1];
                if (EPI == 1) {
                    v0 = 0.5f * v0 * (1.f + erff(v0 * 0.70710678118654752f));
                    v1 = 0.5f * v1 * (1.f + erff(v1 * 0.70710678118654752f));
                }
                if (EPI == 2) {
                    v0 += add1[rowoff + n] + add2[rowoff + n];
                    v1 += add1[rowoff + n + 1] + add2[rowoff + n + 1];
                }
                *(float2*)(Co + rowoff + n) = make_float2(v0, v1);
            }
        }
    }
}

// ---------------- Flash attention, tf32 MMA, BM=64, BN=64, D=128 ---------------
#define AQ_PAD 132
#define AK_PAD 132
#define AV_PAD 136
#define AP_PAD 68
#define ATT_SMEM ((64 * AQ_PAD + 64 * AV_PAD + 64 * AP_PAD) * 4)

__global__ __launch_bounds__(128) void attn_kernel(
    const float* __restrict__ qkv, float* __restrict__ y)
{
    extern __shared__ uint32_t asm_[];
    uint32_t* Qs  = asm_;                             // [64][132]
    uint32_t* KVs = asm_ + 64 * AQ_PAD;               // K stride 132 / V stride 136
    uint32_t* Ps  = asm_ + 64 * AQ_PAD + 64 * AV_PAD; // [64][68]

    int qt = blockIdx.x, h = blockIdx.y, b = blockIdx.z;
    int gq = h >> 2;
    int qcol = (gq * 6 + (h & 3)) * HEAD;
    int kcol = (gq * 6 + 4) * HEAD;
    int vcol = (gq * 6 + 5) * HEAD;

    int tid = threadIdx.x, lane = tid & 31, w = tid >> 5;
    int g = lane >> 2, tg = lane & 3;
    int qbase = qt * 64;
    const size_t RS = QKV_OUT;
    const float scale = 0.08838834764831845f;  // 1/sqrt(128)

    for (int idx = tid; idx < 64 * 32; idx += 128) {
        int rr = idx >> 5, dd = (idx & 31) * 4;
        float4 q = *(const float4*)(qkv + (size_t)(b * T_ + qbase + rr) * RS + qcol + dd);
        *(uint4*)&Qs[rr * AQ_PAD + dd] =
            make_uint4(f2tf(q.x), f2tf(q.y), f2tf(q.z), f2tf(q.w));
    }

    float o[16][4];
#pragma unroll
    for (int nt = 0; nt < 16; nt++)
#pragma unroll
        for (int c = 0; c < 4; c++) o[nt][c] = 0.f;
    float rmax0 = -1e30f, rmax1 = -1e30f;
    float rsum0 = 0.f,    rsum1 = 0.f;

    int row0 = qbase + w * 16 + g;
    int row1 = row0 + 8;

    for (int kt = 0; kt <= qt; kt++) {
        int nb = kt * 64;
        __syncthreads();
        for (int idx = tid; idx < 64 * 32; idx += 128) {
            int rr = idx >> 5, dd = (idx & 31) * 4;
            float4 k = *(const float4*)(qkv + (size_t)(b * T_ + nb + rr) * RS + kcol + dd);
            *(uint4*)&KVs[rr * AK_PAD + dd] =
                make_uint4(f2tf(k.x), f2tf(k.y), f2tf(k.z), f2tf(k.w));
        }
        __syncthreads();

        float s[8][4];
#pragma unroll
        for (int nt = 0; nt < 8; nt++)
#pragma unroll
            for (int c = 0; c < 4; c++) s[nt][c] = 0.f;

#pragma unroll
        for (int ks = 0; ks < 16; ks++) {
            int kb = ks * 8;
            uint32_t a[4];
            a[0] = Qs[(w * 16 + g) * AQ_PAD + kb + tg];
            a[1] = Qs[(w * 16 + g + 8) * AQ_PAD + kb + tg];
            a[2] = Qs[(w * 16 + g) * AQ_PAD + kb + tg + 4];
            a[3] = Qs[(w * 16 + g + 8) * AQ_PAD + kb + tg + 4];
#pragma unroll
            for (int nt = 0; nt < 8; nt++) {
                uint32_t bf[2];
                bf[0] = KVs[(nt * 8 + g) * AK_PAD + kb + tg];
                bf[1] = KVs[(nt * 8 + g) * AK_PAD + kb + tg + 4];
                mma_tf32(s[nt], a, bf);
            }
        }

        bool diag = (kt == qt);
        float ml0 = -1e30f, ml1 = -1e30f;
#pragma unroll
        for (int nt = 0; nt < 8; nt++) {
            int colb = nb + nt * 8 + tg * 2;
            float v0 = s[nt][0] * scale, v1 = s[nt][1] * scale;
            float v2 = s[nt][2] * scale, v3 = s[nt][3] * scale;
            if (diag) {
                if (colb     > row0) v0 = -1e30f;
                if (colb + 1 > row0) v1 = -1e30f;
                if (colb     > row1) v2 = -1e30f;
                if (colb + 1 > row1) v3 = -1e30f;
            }
            s[nt][0] = v0; s[nt][1] = v1; s[nt][2] = v2; s[nt][3] = v3;
            ml0 = fmaxf(ml0, fmaxf(v0, v1));
            ml1 = fmaxf(ml1, fmaxf(v2, v3));
        }
        ml0 = fmaxf(ml0, __shfl_xor_sync(0xffffffffu, ml0, 1));
        ml0 = fmaxf(ml0, __shfl_xor_sync(0xffffffffu, ml0, 2));
        ml1 = fmaxf(ml1, __shfl_xor_sync(0xffffffffu, ml1, 1));
        ml1 = fmaxf(ml1, __shfl_xor_sync(0xffffffffu, ml1, 2));

        float nm0 = fmaxf(rmax0, ml0), nm1 = fmaxf(rmax1, ml1);
        float f0 = __expf(rmax0 - nm0), f1 = __expf(rmax1 - nm1);
        rmax0 = nm0; rmax1 = nm1;

        float ps0 = 0.f, ps1 = 0.f;
#pragma unroll
        for (int nt = 0; nt < 8; nt++) {
            float p0 = __expf(s[nt][0] - nm0);
            float p1 = __expf(s[nt][1] - nm0);
            float p2 = __expf(s[nt][2] - nm1);
            float p3 = __expf(s[nt][3] - nm1);
            ps0 += p0 + p1;
            ps1 += p2 + p3;
            *(uint2*)&Ps[(w * 16 + g) * AP_PAD + nt * 8 + tg * 2] =
                make_uint2(f2tf(p0), f2tf(p1));
            *(uint2*)&Ps[(w * 16 + g + 8) * AP_PAD + nt * 8 + tg * 2] =
                make_uint2(f2tf(p2), f2tf(p3));
        }
        ps0 += __shfl_xor_sync(0xffffffffu, ps0, 1);
        ps0 += __shfl_xor_sync(0xffffffffu, ps0, 2);
        ps1 += __shfl_xor_sync(0xffffffffu, ps1, 1);
        ps1 += __shfl_xor_sync(0xffffffffu, ps1, 2);
        rsum0 = rsum0 * f0 + ps0;
        rsum1 = rsum1 * f1 + ps1;

#pragma unroll
        for (int nt = 0; nt < 16; nt++) {
            o[nt][0] *= f0; o[nt][1] *= f0;
            o[nt][2] *= f1; o[nt][3] *= f1;
        }
        __syncthreads();

        for (int idx = tid; idx < 64 * 32; idx += 128) {
            int rr = idx >> 5, dd = (idx & 31) * 4;
            float4 v = *(const float4*)(qkv + (size_t)(b * T_ + nb + rr) * RS + vcol + dd);
            *(uint4*)&KVs[rr * AV_PAD + dd] =
                make_uint4(f2tf(v.x), f2tf(v.y), f2tf(v.z), f2tf(v.w));
        }
        __syncthreads();

#pragma unroll
        for (int ks = 0; ks < 8; ks++) {
            int kb = ks * 8;
            uint32_t a[4];
            a[0] = Ps[(w * 16 + g) * AP_PAD + kb + tg];
            a[1] = Ps[(w * 16 + g + 8) * AP_PAD + kb + tg];
            a[2] = Ps[(w * 16 + g) * AP_PAD + kb + tg + 4];
            a[3] = Ps[(w * 16 + g + 8) * AP_PAD + kb + tg + 4];
#pragma unroll
            for (int nt = 0; nt < 16; nt++) {
                uint32_t bf[2];
                bf[0] = KVs[(kb + tg) * AV_PAD + nt * 8 + g];
                bf[1] = KVs[(kb + tg + 4) * AV_PAD + nt * 8 + g];
                mma_tf32(o[nt], a, bf);
            }
        }
    }

    float inv0 = 1.f / rsum0, inv1 = 1.f / rsum1;
    size_t m0 = (size_t)(b * T_ + row0);
    size_t m1 = m0 + 8;
#pragma unroll
    for (int nt = 0; nt < 16; nt++) {
        int col = h * HEAD + nt * 8 + tg * 2;
        *(float2*)(y + m0 * C_ + col) = make_float2(o[nt][0] * inv0, o[nt][1] * inv0);
        *(float2*)(y + m1 * C_ + col) = make_float2(o[nt][2] * inv1, o[nt][3] * inv1);
    }
}

// ---------------- launcher -----------------------------------------------------
extern "C" void kernel_launch(void* const* d_in, const int* in_sizes, int n_in,
                              void* d_out, int out_size)
{
    const float* x     = (const float*)d_in[0];
    const float* cosb  = (const float*)d_in[1];
    const float* sinb  = (const float*)d_in[2];
    const float* ln1w  = (const float*)d_in[3];
    const float* ln1b  = (const float*)d_in[4];
    const float* wqkv  = (const float*)d_in[5];
    const float* bqkv  = (const float*)d_in[6];
    const float* wproj = (const float*)d_in[7];
    const float* bproj = (const float*)d_in[8];
    const float* ln2w  = (const float*)d_in[9];
    const float* ln2b  = (const float*)d_in[10];
    const float* wfc1  = (const float*)d_in[11];
    const float* bfc1  = (const float*)d_in[12];
    const float* wfc2  = (const float*)d_in[13];
    const float* bfc2  = (const float*)d_in[14];
    float* out = (float*)d_out;

    float *ln1, *ln2, *qkv, *y, *h, *act;
    cudaGetSymbolAddress((void**)&ln1, g_ln1);
    cudaGetSymbolAddress((void**)&ln2, g_ln2);
    cudaGetSymbolAddress((void**)&qkv, g_qkv);
    cudaGetSymbolAddress((void**)&y,   g_y);
    cudaGetSymbolAddress((void**)&h,   g_h);
    cudaGetSymbolAddress((void**)&act, g_act);

    cudaFuncSetAttribute(tgemm_kernel<0>, cudaFuncAttributeMaxDynamicSharedMemorySize, GSM_BYTES);
    cudaFuncSetAttribute(tgemm_kernel<1>, cudaFuncAttributeMaxDynamicSharedMemorySize, GSM_BYTES);
    cudaFuncSetAttribute(tgemm_kernel<2>, cudaFuncAttributeMaxDynamicSharedMemorySize, GSM_BYTES);
    cudaFuncSetAttribute(attn_kernel, cudaFuncAttributeMaxDynamicSharedMemorySize, ATT_SMEM);

    // 1. dual LayerNorm
    ln_dual_kernel<<<M_TOK, 256>>>(x, ln1w, ln1b, ln2w, ln2b, ln1, ln2);

    // 2. QKV projection
    tgemm_kernel<0><<<dim3(QKV_OUT / 256, M_TOK / 128), 256, GSM_BYTES>>>(
        ln1, wqkv, bqkv, qkv, M_TOK, QKV_OUT, C_, nullptr, nullptr);

    // 3. RoPE
    rope_kernel<<<M_TOK, 320>>>(qkv, cosb, sinb);

    // 4. flash attention
    attn_kernel<<<dim3(T_ / 64, N_HEAD, B_), 128, ATT_SMEM>>>(qkv, y);

    // 5. output projection -> h
    tgemm_kernel<0><<<dim3(C_ / 256, M_TOK / 128), 256, GSM_BYTES>>>(
        y, wproj, bproj, h, M_TOK, C_, C_, nullptr, nullptr);

    // 6. fc1 + GELU -> act
    tgemm_kernel<1><<<dim3(FFN / 256, M_TOK / 128), 256, GSM_BYTES>>>(
        ln2, wfc1, bfc1, act, M_TOK, FFN, C_, nullptr, nullptr);

    // 7. fc2 + h + x -> out
    tgemm_kernel<2><<<dim3(C_ / 256, M_TOK / 128), 256, GSM_BYTES>>>(
        act, wfc2, bfc2, out, M_TOK, C_, FFN, h, x);
}

// round 10
// speedup vs baseline: 5.6325x; 1.4776x over previous
#include <cuda_runtime.h>
#include <cuda_fp16.h>
#include <math.h>
#include <stdint.h>

#define N_HEAD   16
#define HEAD     128
#define ROPE     32
#define C_       2048
#define B_       2
#define T_       2048
#define M_TOK    (B_*T_)        // 4096
#define QKV_OUT  3072
#define FFN      8192

// ---------------- scratch (device globals; no allocations allowed) -------------
__device__ __half g_ln1[(size_t)M_TOK * C_];
__device__ __half g_ln2[(size_t)M_TOK * C_];
__device__ float  g_qkv[(size_t)M_TOK * QKV_OUT];
__device__ __half g_y  [(size_t)M_TOK * C_];
__device__ float  g_h  [(size_t)M_TOK * C_];
__device__ __half g_act[(size_t)M_TOK * FFN];
// transposed fp16 weights, [N][K]
__device__ __half g_wqkv_t[(size_t)QKV_OUT * C_];
__device__ __half g_wproj_t[(size_t)C_ * C_];
__device__ __half g_wfc1_t[(size_t)FFN * C_];
__device__ __half g_wfc2_t[(size_t)C_ * FFN];

// ---------------- helpers --------------------------------------------------------
__device__ __forceinline__ uint32_t f2tf(float f) {
    uint32_t u;
    asm("cvt.rna.tf32.f32 %0, %1;" : "=r"(u) : "f"(f));
    return u;
}

__device__ __forceinline__ void mma_tf32(float* c, const uint32_t* a, const uint32_t* b) {
    asm volatile(
        "mma.sync.aligned.m16n8k8.row.col.f32.tf32.tf32.f32 "
        "{%0,%1,%2,%3}, {%4,%5,%6,%7}, {%8,%9}, {%0,%1,%2,%3};"
        : "+f"(c[0]), "+f"(c[1]), "+f"(c[2]), "+f"(c[3])
        : "r"(a[0]), "r"(a[1]), "r"(a[2]), "r"(a[3]),
          "r"(b[0]), "r"(b[1]));
}

__device__ __forceinline__ void mma_f16(float* c, const uint32_t* a, const uint32_t* b) {
    asm volatile(
        "mma.sync.aligned.m16n8k16.row.col.f32.f16.f16.f32 "
        "{%0,%1,%2,%3}, {%4,%5,%6,%7}, {%8,%9}, {%0,%1,%2,%3};"
        : "+f"(c[0]), "+f"(c[1]), "+f"(c[2]), "+f"(c[3])
        : "r"(a[0]), "r"(a[1]), "r"(a[2]), "r"(a[3]),
          "r"(b[0]), "r"(b[1]));
}

__device__ __forceinline__ void cp16(void* smem, const void* gmem) {
    uint32_t sa = (uint32_t)__cvta_generic_to_shared(smem);
    asm volatile("cp.async.cg.shared.global [%0], [%1], 16;" :: "r"(sa), "l"(gmem));
}
#define CP_COMMIT() asm volatile("cp.async.commit_group;" ::: "memory")
#define CP_WAIT(n)  asm volatile("cp.async.wait_group %0;" :: "n"(n) : "memory")

// ---------------- weight transpose + fp16 cast:  Wt[n][k] = h(W[k][n]) ----------
__global__ __launch_bounds__(256) void transpose_h_kernel(
    const float* __restrict__ W, __half* __restrict__ Wt, int K, int N)
{
    __shared__ float t[32][33];
    int k0 = blockIdx.x * 32, n0 = blockIdx.y * 32;
    int tx = threadIdx.x, ty = threadIdx.y;   // 32 x 8
#pragma unroll
    for (int i = 0; i < 32; i += 8)
        t[ty + i][tx] = W[(size_t)(k0 + ty + i) * N + n0 + tx];
    __syncthreads();
#pragma unroll
    for (int i = 0; i < 32; i += 8)
        Wt[(size_t)(n0 + ty + i) * K + k0 + tx] = __float2half_rn(t[tx][ty + i]);
}

// ---------------- fused dual LayerNorm (fp16 outputs) ----------------------------
__global__ __launch_bounds__(256) void ln_dual_kernel(
    const float* __restrict__ x,
    const float* __restrict__ w1, const float* __restrict__ b1,
    const float* __restrict__ w2, const float* __restrict__ b2,
    __half* __restrict__ o1, __half* __restrict__ o2)
{
    int row = blockIdx.x;
    const float* xr = x + (size_t)row * C_;
    int tid = threadIdx.x;

    float v[8];
    float s = 0.f, s2 = 0.f;
#pragma unroll
    for (int i = 0; i < 8; i++) {
        float t = xr[tid + i * 256];
        v[i] = t; s += t; s2 += t * t;
    }
#pragma unroll
    for (int o = 16; o; o >>= 1) {
        s  += __shfl_xor_sync(0xffffffffu, s,  o);
        s2 += __shfl_xor_sync(0xffffffffu, s2, o);
    }
    __shared__ float sh[16];
    __shared__ float mu_s, rstd_s;
    int w = tid >> 5;
    if ((tid & 31) == 0) { sh[w] = s; sh[w + 8] = s2; }
    __syncthreads();
    if (tid == 0) {
        float a = 0.f, b = 0.f;
#pragma unroll
        for (int i = 0; i < 8; i++) { a += sh[i]; b += sh[i + 8]; }
        float mu  = a * (1.0f / C_);
        float var = b * (1.0f / C_) - mu * mu;
        mu_s = mu;
        rstd_s = rsqrtf(var + 1e-5f);
    }
    __syncthreads();
    float mu = mu_s, rs = rstd_s;
#pragma unroll
    for (int i = 0; i < 8; i++) {
        int c = tid + i * 256;
        float n = (v[i] - mu) * rs;
        o1[(size_t)row * C_ + c] = __float2half_rn(n * w1[c] + b1[c]);
        o2[(size_t)row * C_ + c] = __float2half_rn(n * w2[c] + b2[c]);
    }
}

// ---------------- RoPE in place on qkv (fp32) ------------------------------------
__global__ __launch_bounds__(320) void rope_kernel(
    float* __restrict__ qkv,
    const float* __restrict__ cosb, const float* __restrict__ sinb)
{
    int r = blockIdx.x;
    int t = r & (T_ - 1);
    int tid = threadIdx.x;
    int hh = tid >> 4;
    int i  = tid & 15;
    int col;
    if (hh < 16) col = ((hh >> 2) * 6 + (hh & 3)) * HEAD;
    else         col = ((hh - 16) * 6 + 4) * HEAD;
    float* p = qkv + (size_t)r * QKV_OUT + col;
    float c1 = cosb[t * ROPE + i],      s1 = sinb[t * ROPE + i];
    float c2 = cosb[t * ROPE + i + 16], s2 = sinb[t * ROPE + i + 16];
    float x1 = p[i], x2 = p[i + 16];
    p[i]      = x1 * c1 - x2 * s1;
    p[i + 16] = x2 * c2 + x1 * s2;
}

// ---------------- fp16 GEMM 128x256x32, 8 warps, 3-stage cp.async ---------------
// A [M][K], Bt [N][K], both fp16 K-major. warp tile 64x64, m16n8k16.
// Pad 40 halves/row: frag half2 at bank (20*row + tg) mod 32 -> conflict-free.
// EPI: 0 = +bias -> float out, 1 = +bias,GELU -> HALF out, 2 = +bias+add1+add2 -> float out
#define APADH 40
#define ASZH  (128 * APADH)            // 5120 halves
#define BSZH  (256 * APADH)            // 10240 halves
#define STGH  (ASZH + BSZH)            // 15360 halves
#define HSM_BYTES (3 * STGH * 2)       // 92160 bytes

template <int EPI>
__global__ __launch_bounds__(256, 1) void hgemm_kernel(
    const __half* __restrict__ A, const __half* __restrict__ Bt,
    const float* __restrict__ bias, void* __restrict__ Co,
    int M, int N, int K,
    const float* __restrict__ add1, const float* __restrict__ add2)
{
    extern __shared__ __half hsm[];

    int tid = threadIdx.x;
    int lane = tid & 31, wid = tid >> 5;
    int wm = (wid >> 2) * 64;
    int wn = (wid & 3) * 64;
    int g  = lane >> 2;
    int tg = lane & 3;
    int bm = blockIdx.y * 128, bn = blockIdx.x * 256;

    const __half* Agb = A  + (size_t)bm * K;
    const __half* Bgb = Bt + (size_t)bn * K;

    float acc[4][8][4];
#pragma unroll
    for (int mi = 0; mi < 4; mi++)
#pragma unroll
        for (int ni = 0; ni < 8; ni++)
#pragma unroll
            for (int r = 0; r < 4; r++) acc[mi][ni][r] = 0.f;

    int nIter = K >> 5;

    auto produce = [&](int it) {
        int s = it % 3;
        int k0 = it << 5;
        __half* As = hsm + s * STGH;
        __half* Bs = As + ASZH;
#pragma unroll
        for (int i = 0; i < 2; i++) {           // A: 512 16B-chunks / 256 thr
            int idx = tid + 256 * i;
            int r = idx >> 2, c = (idx & 3) * 8;
            cp16(As + r * APADH + c, Agb + (size_t)r * K + k0 + c);
        }
#pragma unroll
        for (int i = 0; i < 4; i++) {           // B: 1024 chunks
            int idx = tid + 256 * i;
            int r = idx >> 2, c = (idx & 3) * 8;
            cp16(Bs + r * APADH + c, Bgb + (size_t)r * K + k0 + c);
        }
        CP_COMMIT();
    };

    produce(0);
    produce(1);

    for (int it = 0; it < nIter; it++) {
        int s = it % 3;
        if (it + 1 < nIter) { CP_WAIT(1); } else { CP_WAIT(0); }
        __syncthreads();
        if (it + 2 < nIter) produce(it + 2);

        const __half* As = hsm + s * STGH;
        const __half* Bs = As + ASZH;

#pragma unroll
        for (int ks = 0; ks < 2; ks++) {
            int kh = ks * 16;
            uint32_t af[4][4], bf[8][2];
#pragma unroll
            for (int mi = 0; mi < 4; mi++) {
                int m = wm + mi * 16;
                af[mi][0] = *(const uint32_t*)&As[(m + g) * APADH + kh + 2 * tg];
                af[mi][1] = *(const uint32_t*)&As[(m + g + 8) * APADH + kh + 2 * tg];
                af[mi][2] = *(const uint32_t*)&As[(m + g) * APADH + kh + 2 * tg + 8];
                af[mi][3] = *(const uint32_t*)&As[(m + g + 8) * APADH + kh + 2 * tg + 8];
            }
#pragma unroll
            for (int ni = 0; ni < 8; ni++) {
                int n = wn + ni * 8;
                bf[ni][0] = *(const uint32_t*)&Bs[(n + g) * APADH + kh + 2 * tg];
                bf[ni][1] = *(const uint32_t*)&Bs[(n + g) * APADH + kh + 2 * tg + 8];
            }
#pragma unroll
            for (int mi = 0; mi < 4; mi++)
#pragma unroll
                for (int ni = 0; ni < 8; ni++)
                    mma_f16(acc[mi][ni], af[mi], bf[ni]);
        }
    }

    // epilogue
#pragma unroll
    for (int mi = 0; mi < 4; mi++) {
#pragma unroll
        for (int rr = 0; rr < 2; rr++) {
            int m = bm + wm + mi * 16 + g + rr * 8;
            size_t rowoff = (size_t)m * N;
#pragma unroll
            for (int ni = 0; ni < 8; ni++) {
                int n = bn + wn + ni * 8 + tg * 2;
                float v0 = acc[mi][ni][rr * 2 + 0] + bias[n];
                float v1 = acc[mi][ni][rr * 2 + 1] + bias[n + 1];
                if (EPI == 1) {
                    v0 = 0.5f * v0 * (1.f + erff(v0 * 0.70710678118654752f));
                    v1 = 0.5f * v1 * (1.f + erff(v1 * 0.70710678118654752f));
                    *(__half2*)((__half*)Co + rowoff + n) = __floats2half2_rn(v0, v1);
                } else {
                    if (EPI == 2) {
                        v0 += add1[rowoff + n] + add2[rowoff + n];
                        v1 += add1[rowoff + n + 1] + add2[rowoff + n + 1];
                    }
                    *(float2*)((float*)Co + rowoff + n) = make_float2(v0, v1);
                }
            }
        }
    }
}

// ---------------- Flash attention, tf32 MMA, BM=64, BN=64, D=128 ----------------
#define AQ_PAD 132
#define AK_PAD 132
#define AV_PAD 136
#define AP_PAD 68
#define ATT_SMEM ((64 * AQ_PAD + 64 * AV_PAD + 64 * AP_PAD) * 4)

__global__ __launch_bounds__(128) void attn_kernel(
    const float* __restrict__ qkv, __half* __restrict__ y)
{
    extern __shared__ uint32_t asm_[];
    uint32_t* Qs  = asm_;
    uint32_t* KVs = asm_ + 64 * AQ_PAD;
    uint32_t* Ps  = asm_ + 64 * AQ_PAD + 64 * AV_PAD;

    int qt = blockIdx.x, h = blockIdx.y, b = blockIdx.z;
    int gq = h >> 2;
    int qcol = (gq * 6 + (h & 3)) * HEAD;
    int kcol = (gq * 6 + 4) * HEAD;
    int vcol = (gq * 6 + 5) * HEAD;

    int tid = threadIdx.x, lane = tid & 31, w = tid >> 5;
    int g = lane >> 2, tg = lane & 3;
    int qbase = qt * 64;
    const size_t RS = QKV_OUT;
    const float scale = 0.08838834764831845f;

    for (int idx = tid; idx < 64 * 32; idx += 128) {
        int rr = idx >> 5, dd = (idx & 31) * 4;
        float4 q = *(const float4*)(qkv + (size_t)(b * T_ + qbase + rr) * RS + qcol + dd);
        *(uint4*)&Qs[rr * AQ_PAD + dd] =
            make_uint4(f2tf(q.x), f2tf(q.y), f2tf(q.z), f2tf(q.w));
    }

    float o[16][4];
#pragma unroll
    for (int nt = 0; nt < 16; nt++)
#pragma unroll
        for (int c = 0; c < 4; c++) o[nt][c] = 0.f;
    float rmax0 = -1e30f, rmax1 = -1e30f;
    float rsum0 = 0.f,    rsum1 = 0.f;

    int row0 = qbase + w * 16 + g;
    int row1 = row0 + 8;

    for (int kt = 0; kt <= qt; kt++) {
        int nb = kt * 64;
        __syncthreads();
        for (int idx = tid; idx < 64 * 32; idx += 128) {
            int rr = idx >> 5, dd = (idx & 31) * 4;
            float4 k = *(const float4*)(qkv + (size_t)(b * T_ + nb + rr) * RS + kcol + dd);
            *(uint4*)&KVs[rr * AK_PAD + dd] =
                make_uint4(f2tf(k.x), f2tf(k.y), f2tf(k.z), f2tf(k.w));
        }
        __syncthreads();

        float s[8][4];
#pragma unroll
        for (int nt = 0; nt < 8; nt++)
#pragma unroll
            for (int c = 0; c < 4; c++) s[nt][c] = 0.f;

#pragma unroll
        for (int ks = 0; ks < 16; ks++) {
            int kb = ks * 8;
            uint32_t a[4];
            a[0] = Qs[(w * 16 + g) * AQ_PAD + kb + tg];
            a[1] = Qs[(w * 16 + g + 8) * AQ_PAD + kb + tg];
            a[2] = Qs[(w * 16 + g) * AQ_PAD + kb + tg + 4];
            a[3] = Qs[(w * 16 + g + 8) * AQ_PAD + kb + tg + 4];
#pragma unroll
            for (int nt = 0; nt < 8; nt++) {
                uint32_t bf[2];
                bf[0] = KVs[(nt * 8 + g) * AK_PAD + kb + tg];
                bf[1] = KVs[(nt * 8 + g) * AK_PAD + kb + tg + 4];
                mma_tf32(s[nt], a, bf);
            }
        }

        bool diag = (kt == qt);
        float ml0 = -1e30f, ml1 = -1e30f;
#pragma unroll
        for (int nt = 0; nt < 8; nt++) {
            int colb = nb + nt * 8 + tg * 2;
            float v0 = s[nt][0] * scale, v1 = s[nt][1] * scale;
            float v2 = s[nt][2] * scale, v3 = s[nt][3] * scale;
            if (diag) {
                if (colb     > row0) v0 = -1e30f;
                if (colb + 1 > row0) v1 = -1e30f;
                if (colb     > row1) v2 = -1e30f;
                if (colb + 1 > row1) v3 = -1e30f;
            }
            s[nt][0] = v0; s[nt][1] = v1; s[nt][2] = v2; s[nt][3] = v3;
            ml0 = fmaxf(ml0, fmaxf(v0, v1));
            ml1 = fmaxf(ml1, fmaxf(v2, v3));
        }
        ml0 = fmaxf(ml0, __shfl_xor_sync(0xffffffffu, ml0, 1));
        ml0 = fmaxf(ml0, __shfl_xor_sync(0xffffffffu, ml0, 2));
        ml1 = fmaxf(ml1, __shfl_xor_sync(0xffffffffu, ml1, 1));
        ml1 = fmaxf(ml1, __shfl_xor_sync(0xffffffffu, ml1, 2));

        float nm0 = fmaxf(rmax0, ml0), nm1 = fmaxf(rmax1, ml1);
        float f0 = __expf(rmax0 - nm0), f1 = __expf(rmax1 - nm1);
        rmax0 = nm0; rmax1 = nm1;

        float ps0 = 0.f, ps1 = 0.f;
#pragma unroll
        for (int nt = 0; nt < 8; nt++) {
            float p0 = __expf(s[nt][0] - nm0);
            float p1 = __expf(s[nt][1] - nm0);
            float p2 = __expf(s[nt][2] - nm1);
            float p3 = __expf(s[nt][3] - nm1);
            ps0 += p0 + p1;
            ps1 += p2 + p3;
            *(uint2*)&Ps[(w * 16 + g) * AP_PAD + nt * 8 + tg * 2] =
                make_uint2(f2tf(p0), f2tf(p1));
            *(uint2*)&Ps[(w * 16 + g + 8) * AP_PAD + nt * 8 + tg * 2] =
                make_uint2(f2tf(p2), f2tf(p3));
        }
        ps0 += __shfl_xor_sync(0xffffffffu, ps0, 1);
        ps0 += __shfl_xor_sync(0xffffffffu, ps0, 2);
        ps1 += __shfl_xor_sync(0xffffffffu, ps1, 1);
        ps1 += __shfl_xor_sync(0xffffffffu, ps1, 2);
        rsum0 = rsum0 * f0 + ps0;
        rsum1 = rsum1 * f1 + ps1;

#pragma unroll
        for (int nt = 0; nt < 16; nt++) {
            o[nt][0] *= f0; o[nt][1] *= f0;
            o[nt][2] *= f1; o[nt][3] *= f1;
        }
        __syncthreads();

        for (int idx = tid; idx < 64 * 32; idx += 128) {
            int rr = idx >> 5, dd = (idx & 31) * 4;
            float4 v = *(const float4*)(qkv + (size_t)(b * T_ + nb + rr) * RS + vcol + dd);
            *(uint4*)&KVs[rr * AV_PAD + dd] =
                make_uint4(f2tf(v.x), f2tf(v.y), f2tf(v.z), f2tf(v.w));
        }
        __syncthreads();

#pragma unroll
        for (int ks = 0; ks < 8; ks++) {
            int kb = ks * 8;
            uint32_t a[4];
            a[0] = Ps[(w * 16 + g) * AP_PAD + kb + tg];
            a[1] = Ps[(w * 16 + g + 8) * AP_PAD + kb + tg];
            a[2] = Ps[(w * 16 + g) * AP_PAD + kb + tg + 4];
            a[3] = Ps[(w * 16 + g + 8) * AP_PAD + kb + tg + 4];
#pragma unroll
            for (int nt = 0; nt < 16; nt++) {
                uint32_t bf[2];
                bf[0] = KVs[(kb + tg) * AV_PAD + nt * 8 + g];
                bf[1] = KVs[(kb + tg + 4) * AV_PAD + nt * 8 + g];
                mma_tf32(o[nt], a, bf);
            }
        }
    }

    // y written as fp16 (A operand of the proj GEMM)
    float inv0 = 1.f / rsum0, inv1 = 1.f / rsum1;
    size_t m0 = (size_t)(b * T_ + row0);
    size_t m1 = m0 + 8;
#pragma unroll
    for (int nt = 0; nt < 16; nt++) {
        int col = h * HEAD + nt * 8 + tg * 2;
        *(__half2*)(y + m0 * C_ + col) = __floats2half2_rn(o[nt][0] * inv0, o[nt][1] * inv0);
        *(__half2*)(y + m1 * C_ + col) = __floats2half2_rn(o[nt][2] * inv1, o[nt][3] * inv1);
    }
}

// ---------------- launcher -----------------------------------------------------
extern "C" void kernel_launch(void* const* d_in, const int* in_sizes, int n_in,
                              void* d_out, int out_size)
{
    const float* x     = (const float*)d_in[0];
    const float* cosb  = (const float*)d_in[1];
    const float* sinb  = (const float*)d_in[2];
    const float* ln1w  = (const float*)d_in[3];
    const float* ln1b  = (const float*)d_in[4];
    const float* wqkv  = (const float*)d_in[5];
    const float* bqkv  = (const float*)d_in[6];
    const float* wproj = (const float*)d_in[7];
    const float* bproj = (const float*)d_in[8];
    const float* ln2w  = (const float*)d_in[9];
    const float* ln2b  = (const float*)d_in[10];
    const float* wfc1  = (const float*)d_in[11];
    const float* bfc1  = (const float*)d_in[12];
    const float* wfc2  = (const float*)d_in[13];
    const float* bfc2  = (const float*)d_in[14];
    float* out = (float*)d_out;

    __half *ln1, *ln2, *y, *act, *wqt, *wpt, *w1t, *w2t;
    float *qkv, *h;
    cudaGetSymbolAddress((void**)&ln1, g_ln1);
    cudaGetSymbolAddress((void**)&ln2, g_ln2);
    cudaGetSymbolAddress((void**)&qkv, g_qkv);
    cudaGetSymbolAddress((void**)&y,   g_y);
    cudaGetSymbolAddress((void**)&h,   g_h);
    cudaGetSymbolAddress((void**)&act, g_act);
    cudaGetSymbolAddress((void**)&wqt, g_wqkv_t);
    cudaGetSymbolAddress((void**)&wpt, g_wproj_t);
    cudaGetSymbolAddress((void**)&w1t, g_wfc1_t);
    cudaGetSymbolAddress((void**)&w2t, g_wfc2_t);

    cudaFuncSetAttribute(hgemm_kernel<0>, cudaFuncAttributeMaxDynamicSharedMemorySize, HSM_BYTES);
    cudaFuncSetAttribute(hgemm_kernel<1>, cudaFuncAttributeMaxDynamicSharedMemorySize, HSM_BYTES);
    cudaFuncSetAttribute(hgemm_kernel<2>, cudaFuncAttributeMaxDynamicSharedMemorySize, HSM_BYTES);
    cudaFuncSetAttribute(attn_kernel, cudaFuncAttributeMaxDynamicSharedMemorySize, ATT_SMEM);

    dim3 tb(32, 8);
    // weight transposes (fp16 cast)
    transpose_h_kernel<<<dim3(C_ / 32, QKV_OUT / 32), tb>>>(wqkv, wqt, C_, QKV_OUT);
    transpose_h_kernel<<<dim3(C_ / 32, C_ / 32), tb>>>(wproj, wpt, C_, C_);
    transpose_h_kernel<<<dim3(C_ / 32, FFN / 32), tb>>>(wfc1, w1t, C_, FFN);
    transpose_h_kernel<<<dim3(FFN / 32, C_ / 32), tb>>>(wfc2, w2t, FFN, C_);

    // 1. dual LayerNorm (fp16 outputs)
    ln_dual_kernel<<<M_TOK, 256>>>(x, ln1w, ln1b, ln2w, ln2b, ln1, ln2);

    // 2. QKV projection (fp16 MMA) -> fp32 qkv
    hgemm_kernel<0><<<dim3(QKV_OUT / 256, M_TOK / 128), 256, HSM_BYTES>>>(
        ln1, wqt, bqkv, qkv, M_TOK, QKV_OUT, C_, nullptr, nullptr);

    // 3. RoPE
    rope_kernel<<<M_TOK, 320>>>(qkv, cosb, sinb);

    // 4. flash attention (tf32) -> fp16 y
    attn_kernel<<<dim3(T_ / 64, N_HEAD, B_), 128, ATT_SMEM>>>(qkv, y);

    // 5. output projection -> fp32 h
    hgemm_kernel<0><<<dim3(C_ / 256, M_TOK / 128), 256, HSM_BYTES>>>(
        y, wpt, bproj, h, M_TOK, C_, C_, nullptr, nullptr);

    // 6. fc1 + GELU -> fp16 act
    hgemm_kernel<1><<<dim3(FFN / 256, M_TOK / 128), 256, HSM_BYTES>>>(
        ln2, w1t, bfc1, act, M_TOK, FFN, C_, nullptr, nullptr);

    // 7. fc2 + h + x -> out (fp32)
    hgemm_kernel<2><<<dim3(C_ / 256, M_TOK / 128), 256, HSM_BYTES>>>(
        act, w2t, bfc2, out, M_TOK, C_, FFN, h, x);
}

// round 12
// speedup vs baseline: 6.2648x; 1.1123x over previous
#include <cuda_runtime.h>
#include <cuda_fp16.h>
#include <math.h>
#include <stdint.h>

#define N_HEAD   16
#define HEAD     128
#define ROPE     32
#define C_       2048
#define B_       2
#define T_       2048
#define M_TOK    (B_*T_)        // 4096
#define QKV_OUT  3072
#define FFN      8192

// ---------------- scratch (device globals; no allocations allowed) -------------
__device__ __half g_ln1[(size_t)M_TOK * C_];
__device__ __half g_ln2[(size_t)M_TOK * C_];
__device__ float  g_qkv[(size_t)M_TOK * QKV_OUT];
__device__ __half g_y  [(size_t)M_TOK * C_];
__device__ float  g_h  [(size_t)M_TOK * C_];
__device__ __half g_act[(size_t)M_TOK * FFN];
// transposed fp16 weights, [N][K]
__device__ __half g_wqkv_t[(size_t)QKV_OUT * C_];
__device__ __half g_wproj_t[(size_t)C_ * C_];
__device__ __half g_wfc1_t[(size_t)FFN * C_];
__device__ __half g_wfc2_t[(size_t)C_ * FFN];

// ---------------- helpers --------------------------------------------------------
__device__ __forceinline__ void mma_f16(float* c, const uint32_t* a, const uint32_t* b) {
    asm volatile(
        "mma.sync.aligned.m16n8k16.row.col.f32.f16.f16.f32 "
        "{%0,%1,%2,%3}, {%4,%5,%6,%7}, {%8,%9}, {%0,%1,%2,%3};"
        : "+f"(c[0]), "+f"(c[1]), "+f"(c[2]), "+f"(c[3])
        : "r"(a[0]), "r"(a[1]), "r"(a[2]), "r"(a[3]),
          "r"(b[0]), "r"(b[1]));
}

__device__ __forceinline__ void cp16(void* smem, const void* gmem) {
    uint32_t sa = (uint32_t)__cvta_generic_to_shared(smem);
    asm volatile("cp.async.cg.shared.global [%0], [%1], 16;" :: "r"(sa), "l"(gmem));
}
#define CP_COMMIT() asm volatile("cp.async.commit_group;" ::: "memory")
#define CP_WAIT(n)  asm volatile("cp.async.wait_group %0;" :: "n"(n) : "memory")

__device__ __forceinline__ uint32_t h2u(__half2 h) {
    return *(uint32_t*)&h;
}

__device__ __forceinline__ void ldmatrix_x4_trans(
    uint32_t& r0, uint32_t& r1, uint32_t& r2, uint32_t& r3, uint32_t smem_addr)
{
    asm volatile(
        "ldmatrix.sync.aligned.m8n8.x4.trans.shared.b16 {%0,%1,%2,%3}, [%4];"
        : "=r"(r0), "=r"(r1), "=r"(r2), "=r"(r3) : "r"(smem_addr));
}

// ---------------- weight transpose + fp16 cast:  Wt[n][k] = h(W[k][n]) ----------
__global__ __launch_bounds__(256) void transpose_h_kernel(
    const float* __restrict__ W, __half* __restrict__ Wt, int K, int N)
{
    __shared__ float t[64][33];
    int k0 = blockIdx.x * 64, n0 = blockIdx.y * 32;
    int tx = threadIdx.x, ty = threadIdx.y;   // 32 x 8
#pragma unroll
    for (int i = 0; i < 64; i += 8)
        t[ty + i][tx] = W[(size_t)(k0 + ty + i) * N + n0 + tx];
    __syncthreads();
#pragma unroll
    for (int j = 0; j < 32; j += 8) {
        int n = n0 + ty + j;
        __half2 h = __floats2half2_rn(t[2 * tx][ty + j], t[2 * tx + 1][ty + j]);
        *(__half2*)&Wt[(size_t)n * K + k0 + 2 * tx] = h;
    }
}

// ---------------- fused dual LayerNorm (fp16 outputs, vectorized) ---------------
__global__ __launch_bounds__(256) void ln_dual_kernel(
    const float* __restrict__ x,
    const float* __restrict__ w1, const float* __restrict__ b1,
    const float* __restrict__ w2, const float* __restrict__ b2,
    __half* __restrict__ o1, __half* __restrict__ o2)
{
    int row = blockIdx.x;
    const float* xr = x + (size_t)row * C_;
    int tid = threadIdx.x;
    int c0 = tid * 8;

    float v[8];
    *(float4*)&v[0] = *(const float4*)(xr + c0);
    *(float4*)&v[4] = *(const float4*)(xr + c0 + 4);
    float s = 0.f, s2 = 0.f;
#pragma unroll
    for (int i = 0; i < 8; i++) { s += v[i]; s2 += v[i] * v[i]; }
#pragma unroll
    for (int o = 16; o; o >>= 1) {
        s  += __shfl_xor_sync(0xffffffffu, s,  o);
        s2 += __shfl_xor_sync(0xffffffffu, s2, o);
    }
    __shared__ float sh[16];
    __shared__ float mu_s, rstd_s;
    int w = tid >> 5;
    if ((tid & 31) == 0) { sh[w] = s; sh[w + 8] = s2; }
    __syncthreads();
    if (tid == 0) {
        float a = 0.f, b = 0.f;
#pragma unroll
        for (int i = 0; i < 8; i++) { a += sh[i]; b += sh[i + 8]; }
        float mu  = a * (1.0f / C_);
        float var = b * (1.0f / C_) - mu * mu;
        mu_s = mu;
        rstd_s = rsqrtf(var + 1e-5f);
    }
    __syncthreads();
    float mu = mu_s, rs = rstd_s;

    float w1v[8], b1v[8], w2v[8], b2v[8];
    *(float4*)&w1v[0] = *(const float4*)(w1 + c0);
    *(float4*)&w1v[4] = *(const float4*)(w1 + c0 + 4);
    *(float4*)&b1v[0] = *(const float4*)(b1 + c0);
    *(float4*)&b1v[4] = *(const float4*)(b1 + c0 + 4);
    *(float4*)&w2v[0] = *(const float4*)(w2 + c0);
    *(float4*)&w2v[4] = *(const float4*)(w2 + c0 + 4);
    *(float4*)&b2v[0] = *(const float4*)(b2 + c0);
    *(float4*)&b2v[4] = *(const float4*)(b2 + c0 + 4);

    uint32_t u1[4], u2[4];
#pragma unroll
    for (int j = 0; j < 4; j++) {
        float n0 = (v[2 * j] - mu) * rs, n1 = (v[2 * j + 1] - mu) * rs;
        u1[j] = h2u(__floats2half2_rn(n0 * w1v[2 * j] + b1v[2 * j],
                                      n1 * w1v[2 * j + 1] + b1v[2 * j + 1]));
        u2[j] = h2u(__floats2half2_rn(n0 * w2v[2 * j] + b2v[2 * j],
                                      n1 * w2v[2 * j + 1] + b2v[2 * j + 1]));
    }
    *(uint4*)(o1 + (size_t)row * C_ + c0) = make_uint4(u1[0], u1[1], u1[2], u1[3]);
    *(uint4*)(o2 + (size_t)row * C_ + c0) = make_uint4(u2[0], u2[1], u2[2], u2[3]);
}

// ---------------- RoPE in place on qkv (fp32) ------------------------------------
__global__ __launch_bounds__(320) void rope_kernel(
    float* __restrict__ qkv,
    const float* __restrict__ cosb, const float* __restrict__ sinb)
{
    int r = blockIdx.x;
    int t = r & (T_ - 1);
    int tid = threadIdx.x;
    int hh = tid >> 4;
    int i  = tid & 15;
    int col;
    if (hh < 16) col = ((hh >> 2) * 6 + (hh & 3)) * HEAD;
    else         col = ((hh - 16) * 6 + 4) * HEAD;
    float* p = qkv + (size_t)r * QKV_OUT + col;
    float c1 = cosb[t * ROPE + i],      s1 = sinb[t * ROPE + i];
    float c2 = cosb[t * ROPE + i + 16], s2 = sinb[t * ROPE + i + 16];
    float x1 = p[i], x2 = p[i + 16];
    p[i]      = x1 * c1 - x2 * s1;
    p[i + 16] = x2 * c2 + x1 * s2;
}

// ---------------- fp16 GEMM 128x256x32, 8 warps, 3-stage cp.async ---------------
#define APADH 40
#define ASZH  (128 * APADH)
#define BSZH  (256 * APADH)
#define STGH  (ASZH + BSZH)
#define HSM_BYTES (3 * STGH * 2)

template <int EPI>
__global__ __launch_bounds__(256, 1) void hgemm_kernel(
    const __half* __restrict__ A, const __half* __restrict__ Bt,
    const float* __restrict__ bias, void* __restrict__ Co,
    int M, int N, int K,
    const float* __restrict__ add1, const float* __restrict__ add2)
{
    extern __shared__ __half hsm[];

    int tid = threadIdx.x;
    int lane = tid & 31, wid = tid >> 5;
    int wm = (wid >> 2) * 64;
    int wn = (wid & 3) * 64;
    int g  = lane >> 2;
    int tg = lane & 3;
    int bm = blockIdx.y * 128, bn = blockIdx.x * 256;

    const __half* Agb = A  + (size_t)bm * K;
    const __half* Bgb = Bt + (size_t)bn * K;

    float acc[4][8][4];
#pragma unroll
    for (int mi = 0; mi < 4; mi++)
#pragma unroll
        for (int ni = 0; ni < 8; ni++)
#pragma unroll
            for (int r = 0; r < 4; r++) acc[mi][ni][r] = 0.f;

    int nIter = K >> 5;

    auto produce = [&](int it) {
        int s = it % 3;
        int k0 = it << 5;
        __half* As = hsm + s * STGH;
        __half* Bs = As + ASZH;
#pragma unroll
        for (int i = 0; i < 2; i++) {
            int idx = tid + 256 * i;
            int r = idx >> 2, c = (idx & 3) * 8;
            cp16(As + r * APADH + c, Agb + (size_t)r * K + k0 + c);
        }
#pragma unroll
        for (int i = 0; i < 4; i++) {
            int idx = tid + 256 * i;
            int r = idx >> 2, c = (idx & 3) * 8;
            cp16(Bs + r * APADH + c, Bgb + (size_t)r * K + k0 + c);
        }
        CP_COMMIT();
    };

    produce(0);
    produce(1);

    for (int it = 0; it < nIter; it++) {
        int s = it % 3;
        if (it + 1 < nIter) { CP_WAIT(1); } else { CP_WAIT(0); }
        __syncthreads();
        if (it + 2 < nIter) produce(it + 2);

        const __half* As = hsm + s * STGH;
        const __half* Bs = As + ASZH;

#pragma unroll
        for (int ks = 0; ks < 2; ks++) {
            int kh = ks * 16;
            uint32_t af[4][4], bf[8][2];
#pragma unroll
            for (int mi = 0; mi < 4; mi++) {
                int m = wm + mi * 16;
                af[mi][0] = *(const uint32_t*)&As[(m + g) * APADH + kh + 2 * tg];
                af[mi][1] = *(const uint32_t*)&As[(m + g + 8) * APADH + kh + 2 * tg];
                af[mi][2] = *(const uint32_t*)&As[(m + g) * APADH + kh + 2 * tg + 8];
                af[mi][3] = *(const uint32_t*)&As[(m + g + 8) * APADH + kh + 2 * tg + 8];
            }
#pragma unroll
            for (int ni = 0; ni < 8; ni++) {
                int n = wn + ni * 8;
                bf[ni][0] = *(const uint32_t*)&Bs[(n + g) * APADH + kh + 2 * tg];
                bf[ni][1] = *(const uint32_t*)&Bs[(n + g) * APADH + kh + 2 * tg + 8];
            }
#pragma unroll
            for (int mi = 0; mi < 4; mi++)
#pragma unroll
                for (int ni = 0; ni < 8; ni++)
                    mma_f16(acc[mi][ni], af[mi], bf[ni]);
        }
    }

#pragma unroll
    for (int mi = 0; mi < 4; mi++) {
#pragma unroll
        for (int rr = 0; rr < 2; rr++) {
            int m = bm + wm + mi * 16 + g + rr * 8;
            size_t rowoff = (size_t)m * N;
#pragma unroll
            for (int ni = 0; ni < 8; ni++) {
                int n = bn + wn + ni * 8 + tg * 2;
                float v0 = acc[mi][ni][rr * 2 + 0] + bias[n];
                float v1 = acc[mi][ni][rr * 2 + 1] + bias[n + 1];
                if (EPI == 1) {
                    v0 = 0.5f * v0 * (1.f + erff(v0 * 0.70710678118654752f));
                    v1 = 0.5f * v1 * (1.f + erff(v1 * 0.70710678118654752f));
                    *(__half2*)((__half*)Co + rowoff + n) = __floats2half2_rn(v0, v1);
                } else {
                    if (EPI == 2) {
                        v0 += add1[rowoff + n] + add2[rowoff + n];
                        v1 += add1[rowoff + n + 1] + add2[rowoff + n + 1];
                    }
                    *(float2*)((float*)Co + rowoff + n) = make_float2(v0, v1);
                }
            }
        }
    }
}

// ---------------- Flash attention, fp16 MMA, BM=64, BN=64, D=128 ----------------
// Qs/Ks/Vs all [64 rows][136 halves]; V stored NATURALLY [key][dim] and its
// PV B-fragments produced by ldmatrix.x4.trans. Ps [64][72].
#define QK_PAD 136
#define P_PAD  72
#define KV_HALVES (64 * QK_PAD)                  // 8704
#define ATT_SMEM ((64 * QK_PAD + KV_HALVES + 64 * P_PAD) * 2)   // 44032 B

__global__ __launch_bounds__(128) void attn_kernel(
    const float* __restrict__ qkv, __half* __restrict__ y)
{
    extern __shared__ __half hsm_a[];
    __half* Qs  = hsm_a;                       // [64][136]
    __half* KVs = hsm_a + 64 * QK_PAD;         // K or V tile [64][136]
    __half* Ps  = KVs + KV_HALVES;             // [64][72]

    int qt = blockIdx.x, h = blockIdx.y, b = blockIdx.z;
    int gq = h >> 2;
    int qcol = (gq * 6 + (h & 3)) * HEAD;
    int kcol = (gq * 6 + 4) * HEAD;
    int vcol = (gq * 6 + 5) * HEAD;

    int tid = threadIdx.x, lane = tid & 31, w = tid >> 5;
    int g = lane >> 2, tg = lane & 3;
    int qbase = qt * 64;
    const size_t RS = QKV_OUT;
    const float scale = 0.08838834764831845f;  // folded into Q

    // ldmatrix per-lane offsets (V tile):
    // lanes 0-7 -> matrix0 rows (keys kh+0..7,  dims D0)
    // lanes 8-15 -> matrix1 (keys kh+8..15, dims D0)
    // lanes 16-23 -> matrix2 (keys kh+0..7,  dims D0+8)
    // lanes 24-31 -> matrix3 (keys kh+8..15, dims D0+8)
    int lm_row = ((lane >> 3) & 1) * 8 + (lane & 7);
    int lm_dim = (lane >> 4) * 8;
    uint32_t v_u32 = (uint32_t)__cvta_generic_to_shared(KVs);

    // load Q tile (scaled, fp16)
    for (int idx = tid; idx < 64 * 32; idx += 128) {
        int rr = idx >> 5, dd = (idx & 31) * 4;
        float4 q = *(const float4*)(qkv + (size_t)(b * T_ + qbase + rr) * RS + qcol + dd);
        uint2 u = make_uint2(h2u(__floats2half2_rn(q.x * scale, q.y * scale)),
                             h2u(__floats2half2_rn(q.z * scale, q.w * scale)));
        *(uint2*)&Qs[rr * QK_PAD + dd] = u;
    }

    float o[16][4];
#pragma unroll
    for (int nt = 0; nt < 16; nt++)
#pragma unroll
        for (int c = 0; c < 4; c++) o[nt][c] = 0.f;
    float rmax0 = -1e30f, rmax1 = -1e30f;
    float rsum0 = 0.f,    rsum1 = 0.f;

    int row0 = qbase + w * 16 + g;
    int row1 = row0 + 8;

    for (int kt = 0; kt <= qt; kt++) {
        int nb = kt * 64;
        __syncthreads();   // prev PV done with KVs / Q stores visible (iter 0)
        // load K tile [64][136]
        for (int idx = tid; idx < 64 * 32; idx += 128) {
            int rr = idx >> 5, dd = (idx & 31) * 4;
            float4 k = *(const float4*)(qkv + (size_t)(b * T_ + nb + rr) * RS + kcol + dd);
            uint2 u = make_uint2(h2u(__floats2half2_rn(k.x, k.y)),
                                 h2u(__floats2half2_rn(k.z, k.w)));
            *(uint2*)&KVs[rr * QK_PAD + dd] = u;
        }
        __syncthreads();

        // S = (Q*scale) K^T : fp16 m16n8k16, 8 k-steps x 8 n-tiles
        float s[8][4];
#pragma unroll
        for (int nt = 0; nt < 8; nt++)
#pragma unroll
            for (int c = 0; c < 4; c++) s[nt][c] = 0.f;

#pragma unroll
        for (int ks = 0; ks < 8; ks++) {
            int kh = ks * 16;
            uint32_t a[4];
            a[0] = *(const uint32_t*)&Qs[(w * 16 + g) * QK_PAD + kh + 2 * tg];
            a[1] = *(const uint32_t*)&Qs[(w * 16 + g + 8) * QK_PAD + kh + 2 * tg];
            a[2] = *(const uint32_t*)&Qs[(w * 16 + g) * QK_PAD + kh + 2 * tg + 8];
            a[3] = *(const uint32_t*)&Qs[(w * 16 + g + 8) * QK_PAD + kh + 2 * tg + 8];
#pragma unroll
            for (int nt = 0; nt < 8; nt++) {
                uint32_t bf[2];
                bf[0] = *(const uint32_t*)&KVs[(nt * 8 + g) * QK_PAD + kh + 2 * tg];
                bf[1] = *(const uint32_t*)&KVs[(nt * 8 + g) * QK_PAD + kh + 2 * tg + 8];
                mma_f16(s[nt], a, bf);
            }
        }

        // causal mask + online softmax (scores already scaled)
        bool diag = (kt == qt);
        float ml0 = -1e30f, ml1 = -1e30f;
#pragma unroll
        for (int nt = 0; nt < 8; nt++) {
            int colb = nb + nt * 8 + tg * 2;
            float v0 = s[nt][0], v1 = s[nt][1];
            float v2 = s[nt][2], v3 = s[nt][3];
            if (diag) {
                if (colb     > row0) v0 = -1e30f;
                if (colb + 1 > row0) v1 = -1e30f;
                if (colb     > row1) v2 = -1e30f;
                if (colb + 1 > row1) v3 = -1e30f;
            }
            s[nt][0] = v0; s[nt][1] = v1; s[nt][2] = v2; s[nt][3] = v3;
            ml0 = fmaxf(ml0, fmaxf(v0, v1));
            ml1 = fmaxf(ml1, fmaxf(v2, v3));
        }
        ml0 = fmaxf(ml0, __shfl_xor_sync(0xffffffffu, ml0, 1));
        ml0 = fmaxf(ml0, __shfl_xor_sync(0xffffffffu, ml0, 2));
        ml1 = fmaxf(ml1, __shfl_xor_sync(0xffffffffu, ml1, 1));
        ml1 = fmaxf(ml1, __shfl_xor_sync(0xffffffffu, ml1, 2));

        float nm0 = fmaxf(rmax0, ml0), nm1 = fmaxf(rmax1, ml1);
        float f0 = __expf(rmax0 - nm0), f1 = __expf(rmax1 - nm1);
        rmax0 = nm0; rmax1 = nm1;

        float ps0 = 0.f, ps1 = 0.f;
#pragma unroll
        for (int nt = 0; nt < 8; nt++) {
            float p0 = __expf(s[nt][0] - nm0);
            float p1 = __expf(s[nt][1] - nm0);
            float p2 = __expf(s[nt][2] - nm1);
            float p3 = __expf(s[nt][3] - nm1);
            ps0 += p0 + p1;
            ps1 += p2 + p3;
            *(uint32_t*)&Ps[(w * 16 + g) * P_PAD + nt * 8 + 2 * tg] =
                h2u(__floats2half2_rn(p0, p1));
            *(uint32_t*)&Ps[(w * 16 + g + 8) * P_PAD + nt * 8 + 2 * tg] =
                h2u(__floats2half2_rn(p2, p3));
        }
        ps0 += __shfl_xor_sync(0xffffffffu, ps0, 1);
        ps0 += __shfl_xor_sync(0xffffffffu, ps0, 2);
        ps1 += __shfl_xor_sync(0xffffffffu, ps1, 1);
        ps1 += __shfl_xor_sync(0xffffffffu, ps1, 2);
        rsum0 = rsum0 * f0 + ps0;
        rsum1 = rsum1 * f1 + ps1;

#pragma unroll
        for (int nt = 0; nt < 16; nt++) {
            o[nt][0] *= f0; o[nt][1] *= f0;
            o[nt][2] *= f1; o[nt][3] *= f1;
        }
        __syncthreads();   // K reads done, P written

        // load V tile NATURALLY [key][dim] (same pattern as K: conflict-free)
        for (int idx = tid; idx < 64 * 32; idx += 128) {
            int rr = idx >> 5, dd = (idx & 31) * 4;
            float4 v = *(const float4*)(qkv + (size_t)(b * T_ + nb + rr) * RS + vcol + dd);
            uint2 u = make_uint2(h2u(__floats2half2_rn(v.x, v.y)),
                                 h2u(__floats2half2_rn(v.z, v.w)));
            *(uint2*)&KVs[rr * QK_PAD + dd] = u;
        }
        __syncthreads();

        // O += P V : A from Ps, B via ldmatrix.x4.trans on natural-layout V
#pragma unroll
        for (int ks = 0; ks < 4; ks++) {
            int kh = ks * 16;
            uint32_t a[4];
            a[0] = *(const uint32_t*)&Ps[(w * 16 + g) * P_PAD + kh + 2 * tg];
            a[1] = *(const uint32_t*)&Ps[(w * 16 + g + 8) * P_PAD + kh + 2 * tg];
            a[2] = *(const uint32_t*)&Ps[(w * 16 + g) * P_PAD + kh + 2 * tg + 8];
            a[3] = *(const uint32_t*)&Ps[(w * 16 + g + 8) * P_PAD + kh + 2 * tg + 8];
#pragma unroll
            for (int ntp = 0; ntp < 8; ntp++) {
                uint32_t addr = v_u32 +
                    (uint32_t)(((kh + lm_row) * QK_PAD + ntp * 16 + lm_dim) * 2);
                uint32_t r0, r1, r2, r3;
                ldmatrix_x4_trans(r0, r1, r2, r3, addr);
                uint32_t b0[2] = {r0, r1};
                uint32_t b1[2] = {r2, r3};
                mma_f16(o[2 * ntp],     a, b0);
                mma_f16(o[2 * ntp + 1], a, b1);
            }
        }
    }

    // y written as fp16 (A operand of the proj GEMM)
    float inv0 = 1.f / rsum0, inv1 = 1.f / rsum1;
    size_t m0 = (size_t)(b * T_ + row0);
    size_t m1 = m0 + 8;
#pragma unroll
    for (int nt = 0; nt < 16; nt++) {
        int col = h * HEAD + nt * 8 + tg * 2;
        *(__half2*)(y + m0 * C_ + col) = __floats2half2_rn(o[nt][0] * inv0, o[nt][1] * inv0);
        *(__half2*)(y + m1 * C_ + col) = __floats2half2_rn(o[nt][2] * inv1, o[nt][3] * inv1);
    }
}

// ---------------- launcher -----------------------------------------------------
extern "C" void kernel_launch(void* const* d_in, const int* in_sizes, int n_in,
                              void* d_out, int out_size)
{
    const float* x     = (const float*)d_in[0];
    const float* cosb  = (const float*)d_in[1];
    const float* sinb  = (const float*)d_in[2];
    const float* ln1w  = (const float*)d_in[3];
    const float* ln1b  = (const float*)d_in[4];
    const float* wqkv  = (const float*)d_in[5];
    const float* bqkv  = (const float*)d_in[6];
    const float* wproj = (const float*)d_in[7];
    const float* bproj = (const float*)d_in[8];
    const float* ln2w  = (const float*)d_in[9];
    const float* ln2b  = (const float*)d_in[10];
    const float* wfc1  = (const float*)d_in[11];
    const float* bfc1  = (const float*)d_in[12];
    const float* wfc2  = (const float*)d_in[13];
    const float* bfc2  = (const float*)d_in[14];
    float* out = (float*)d_out;

    __half *ln1, *ln2, *y, *act, *wqt, *wpt, *w1t, *w2t;
    float *qkv, *h;
    cudaGetSymbolAddress((void**)&ln1, g_ln1);
    cudaGetSymbolAddress((void**)&ln2, g_ln2);
    cudaGetSymbolAddress((void**)&qkv, g_qkv);
    cudaGetSymbolAddress((void**)&y,   g_y);
    cudaGetSymbolAddress((void**)&h,   g_h);
    cudaGetSymbolAddress((void**)&act, g_act);
    cudaGetSymbolAddress((void**)&wqt, g_wqkv_t);
    cudaGetSymbolAddress((void**)&wpt, g_wproj_t);
    cudaGetSymbolAddress((void**)&w1t, g_wfc1_t);
    cudaGetSymbolAddress((void**)&w2t, g_wfc2_t);

    cudaFuncSetAttribute(hgemm_kernel<0>, cudaFuncAttributeMaxDynamicSharedMemorySize, HSM_BYTES);
    cudaFuncSetAttribute(hgemm_kernel<1>, cudaFuncAttributeMaxDynamicSharedMemorySize, HSM_BYTES);
    cudaFuncSetAttribute(hgemm_kernel<2>, cudaFuncAttributeMaxDynamicSharedMemorySize, HSM_BYTES);
    cudaFuncSetAttribute(attn_kernel, cudaFuncAttributeMaxDynamicSharedMemorySize, ATT_SMEM);

    dim3 tb(32, 8);
    // weight transposes (fp16 cast)
    transpose_h_kernel<<<dim3(C_ / 64, QKV_OUT / 32), tb>>>(wqkv, wqt, C_, QKV_OUT);
    transpose_h_kernel<<<dim3(C_ / 64, C_ / 32), tb>>>(wproj, wpt, C_, C_);
    transpose_h_kernel<<<dim3(C_ / 64, FFN / 32), tb>>>(wfc1, w1t, C_, FFN);
    transpose_h_kernel<<<dim3(FFN / 64, C_ / 32), tb>>>(wfc2, w2t, FFN, C_);

    // 1. dual LayerNorm (fp16 outputs)
    ln_dual_kernel<<<M_TOK, 256>>>(x, ln1w, ln1b, ln2w, ln2b, ln1, ln2);

    // 2. QKV projection (fp16 MMA) -> fp32 qkv
    hgemm_kernel<0><<<dim3(QKV_OUT / 256, M_TOK / 128), 256, HSM_BYTES>>>(
        ln1, wqt, bqkv, qkv, M_TOK, QKV_OUT, C_, nullptr, nullptr);

    // 3. RoPE
    rope_kernel<<<M_TOK, 320>>>(qkv, cosb, sinb);

    // 4. flash attention (fp16 MMA) -> fp16 y
    attn_kernel<<<dim3(T_ / 64, N_HEAD, B_), 128, ATT_SMEM>>>(qkv, y);

    // 5. output projection -> fp32 h
    hgemm_kernel<0><<<dim3(C_ / 256, M_TOK / 128), 256, HSM_BYTES>>>(
        y, wpt, bproj, h, M_TOK, C_, C_, nullptr, nullptr);

    // 6. fc1 + GELU -> fp16 act
    hgemm_kernel<1><<<dim3(FFN / 256, M_TOK / 128), 256, HSM_BYTES>>>(
        ln2, w1t, bfc1, act, M_TOK, FFN, C_, nullptr, nullptr);

    // 7. fc2 + h + x -> out (fp32)
    hgemm_kernel<2><<<dim3(C_ / 256, M_TOK / 128), 256, HSM_BYTES>>>(
        act, w2t, bfc2, out, M_TOK, C_, FFN, h, x);
}

// round 13
// speedup vs baseline: 6.2833x; 1.0029x over previous
#include <cuda_runtime.h>
#include <cuda_fp16.h>
#include <math.h>
#include <stdint.h>

#define N_HEAD   16
#define HEAD     128
#define ROPE     32
#define C_       2048
#define B_       2
#define T_       2048
#define M_TOK    (B_*T_)        // 4096
#define QKV_OUT  3072
#define FFN      8192

// ---------------- scratch (device globals; no allocations allowed) -------------
__device__ __half g_ln1[(size_t)M_TOK * C_];
__device__ __half g_ln2[(size_t)M_TOK * C_];
__device__ float  g_qkv[(size_t)M_TOK * QKV_OUT];
__device__ __half g_y  [(size_t)M_TOK * C_];
__device__ float  g_h  [(size_t)M_TOK * C_];
__device__ __half g_act[(size_t)M_TOK * FFN];
// transposed fp16 weights, [N][K]
__device__ __half g_wqkv_t[(size_t)QKV_OUT * C_];
__device__ __half g_wproj_t[(size_t)C_ * C_];
__device__ __half g_wfc1_t[(size_t)FFN * C_];
__device__ __half g_wfc2_t[(size_t)C_ * FFN];

// ---------------- helpers --------------------------------------------------------
__device__ __forceinline__ void mma_f16(float* c, const uint32_t* a, const uint32_t* b) {
    asm volatile(
        "mma.sync.aligned.m16n8k16.row.col.f32.f16.f16.f32 "
        "{%0,%1,%2,%3}, {%4,%5,%6,%7}, {%8,%9}, {%0,%1,%2,%3};"
        : "+f"(c[0]), "+f"(c[1]), "+f"(c[2]), "+f"(c[3])
        : "r"(a[0]), "r"(a[1]), "r"(a[2]), "r"(a[3]),
          "r"(b[0]), "r"(b[1]));
}

__device__ __forceinline__ void cp16(void* smem, const void* gmem) {
    uint32_t sa = (uint32_t)__cvta_generic_to_shared(smem);
    asm volatile("cp.async.cg.shared.global [%0], [%1], 16;" :: "r"(sa), "l"(gmem));
}
#define CP_COMMIT() asm volatile("cp.async.commit_group;" ::: "memory")
#define CP_WAIT(n)  asm volatile("cp.async.wait_group %0;" :: "n"(n) : "memory")

__device__ __forceinline__ uint32_t h2u(__half2 h) {
    return *(uint32_t*)&h;
}

__device__ __forceinline__ void ldmatrix_x4(
    uint32_t& r0, uint32_t& r1, uint32_t& r2, uint32_t& r3, uint32_t smem_addr)
{
    asm volatile(
        "ldmatrix.sync.aligned.m8n8.x4.shared.b16 {%0,%1,%2,%3}, [%4];"
        : "=r"(r0), "=r"(r1), "=r"(r2), "=r"(r3) : "r"(smem_addr));
}

__device__ __forceinline__ void ldmatrix_x4_trans(
    uint32_t& r0, uint32_t& r1, uint32_t& r2, uint32_t& r3, uint32_t smem_addr)
{
    asm volatile(
        "ldmatrix.sync.aligned.m8n8.x4.trans.shared.b16 {%0,%1,%2,%3}, [%4];"
        : "=r"(r0), "=r"(r1), "=r"(r2), "=r"(r3) : "r"(smem_addr));
}

// ---------------- weight transpose + fp16 cast:  Wt[n][k] = h(W[k][n]) ----------
__global__ __launch_bounds__(256) void transpose_h_kernel(
    const float* __restrict__ W, __half* __restrict__ Wt, int K, int N)
{
    __shared__ float t[64][33];
    int k0 = blockIdx.x * 64, n0 = blockIdx.y * 32;
    int tx = threadIdx.x, ty = threadIdx.y;   // 32 x 8
#pragma unroll
    for (int i = 0; i < 64; i += 8)
        t[ty + i][tx] = W[(size_t)(k0 + ty + i) * N + n0 + tx];
    __syncthreads();
#pragma unroll
    for (int j = 0; j < 32; j += 8) {
        int n = n0 + ty + j;
        __half2 h = __floats2half2_rn(t[2 * tx][ty + j], t[2 * tx + 1][ty + j]);
        *(__half2*)&Wt[(size_t)n * K + k0 + 2 * tx] = h;
    }
}

// ---------------- fused dual LayerNorm (fp16 outputs, vectorized) ---------------
__global__ __launch_bounds__(256) void ln_dual_kernel(
    const float* __restrict__ x,
    const float* __restrict__ w1, const float* __restrict__ b1,
    const float* __restrict__ w2, const float* __restrict__ b2,
    __half* __restrict__ o1, __half* __restrict__ o2)
{
    int row = blockIdx.x;
    const float* xr = x + (size_t)row * C_;
    int tid = threadIdx.x;
    int c0 = tid * 8;

    float v[8];
    *(float4*)&v[0] = *(const float4*)(xr + c0);
    *(float4*)&v[4] = *(const float4*)(xr + c0 + 4);
    float s = 0.f, s2 = 0.f;
#pragma unroll
    for (int i = 0; i < 8; i++) { s += v[i]; s2 += v[i] * v[i]; }
#pragma unroll
    for (int o = 16; o; o >>= 1) {
        s  += __shfl_xor_sync(0xffffffffu, s,  o);
        s2 += __shfl_xor_sync(0xffffffffu, s2, o);
    }
    __shared__ float sh[16];
    __shared__ float mu_s, rstd_s;
    int w = tid >> 5;
    if ((tid & 31) == 0) { sh[w] = s; sh[w + 8] = s2; }
    __syncthreads();
    if (tid == 0) {
        float a = 0.f, b = 0.f;
#pragma unroll
        for (int i = 0; i < 8; i++) { a += sh[i]; b += sh[i + 8]; }
        float mu  = a * (1.0f / C_);
        float var = b * (1.0f / C_) - mu * mu;
        mu_s = mu;
        rstd_s = rsqrtf(var + 1e-5f);
    }
    __syncthreads();
    float mu = mu_s, rs = rstd_s;

    float w1v[8], b1v[8], w2v[8], b2v[8];
    *(float4*)&w1v[0] = *(const float4*)(w1 + c0);
    *(float4*)&w1v[4] = *(const float4*)(w1 + c0 + 4);
    *(float4*)&b1v[0] = *(const float4*)(b1 + c0);
    *(float4*)&b1v[4] = *(const float4*)(b1 + c0 + 4);
    *(float4*)&w2v[0] = *(const float4*)(w2 + c0);
    *(float4*)&w2v[4] = *(const float4*)(w2 + c0 + 4);
    *(float4*)&b2v[0] = *(const float4*)(b2 + c0);
    *(float4*)&b2v[4] = *(const float4*)(b2 + c0 + 4);

    uint32_t u1[4], u2[4];
#pragma unroll
    for (int j = 0; j < 4; j++) {
        float n0 = (v[2 * j] - mu) * rs, n1 = (v[2 * j + 1] - mu) * rs;
        u1[j] = h2u(__floats2half2_rn(n0 * w1v[2 * j] + b1v[2 * j],
                                      n1 * w1v[2 * j + 1] + b1v[2 * j + 1]));
        u2[j] = h2u(__floats2half2_rn(n0 * w2v[2 * j] + b2v[2 * j],
                                      n1 * w2v[2 * j + 1] + b2v[2 * j + 1]));
    }
    *(uint4*)(o1 + (size_t)row * C_ + c0) = make_uint4(u1[0], u1[1], u1[2], u1[3]);
    *(uint4*)(o2 + (size_t)row * C_ + c0) = make_uint4(u2[0], u2[1], u2[2], u2[3]);
}

// ---------------- RoPE in place on qkv (fp32) ------------------------------------
__global__ __launch_bounds__(320) void rope_kernel(
    float* __restrict__ qkv,
    const float* __restrict__ cosb, const float* __restrict__ sinb)
{
    int r = blockIdx.x;
    int t = r & (T_ - 1);
    int tid = threadIdx.x;
    int hh = tid >> 4;
    int i  = tid & 15;
    int col;
    if (hh < 16) col = ((hh >> 2) * 6 + (hh & 3)) * HEAD;
    else         col = ((hh - 16) * 6 + 4) * HEAD;
    float* p = qkv + (size_t)r * QKV_OUT + col;
    float c1 = cosb[t * ROPE + i],      s1 = sinb[t * ROPE + i];
    float c2 = cosb[t * ROPE + i + 16], s2 = sinb[t * ROPE + i + 16];
    float x1 = p[i], x2 = p[i + 16];
    p[i]      = x1 * c1 - x2 * s1;
    p[i + 16] = x2 * c2 + x1 * s2;
}

// ---------------- fp16 GEMM 128x128x32, 8 warps, 2 CTAs/SM, ldmatrix ------------
// A [M][K], Bt [N][K], fp16 K-major. Warp tile 64x32. 3-stage cp.async.
// Pitch 40 halves: ldmatrix 8-row reads cover all 32 banks (row pitch 80B).
#define APADH 40
#define ASZH  (128 * APADH)            // 5120 halves
#define BSZH  (128 * APADH)            // 5120 halves
#define STGH  (ASZH + BSZH)            // 10240 halves
#define HSM_BYTES (3 * STGH * 2)       // 61440 bytes

template <int EPI>
__global__ __launch_bounds__(256, 2) void hgemm_kernel(
    const __half* __restrict__ A, const __half* __restrict__ Bt,
    const float* __restrict__ bias, void* __restrict__ Co,
    int M, int N, int K,
    const float* __restrict__ add1, const float* __restrict__ add2)
{
    extern __shared__ __half hsm[];

    int tid = threadIdx.x;
    int lane = tid & 31, wid = tid >> 5;
    int wm = (wid >> 2) * 64;              // 2 warp rows
    int wn = (wid & 3) * 32;               // 4 warp cols
    int g  = lane >> 2;
    int tg = lane & 3;
    int bm = blockIdx.y * 128, bn = blockIdx.x * 128;

    const __half* Agb = A  + (size_t)bm * K;
    const __half* Bgb = Bt + (size_t)bn * K;

    // ldmatrix lane-address components
    int lm_r = lane & 15;                  // row within 16-row block
    int lm_c = (lane >> 4) * 8;            // k-offset 0 or 8

    float acc[4][4][4];
#pragma unroll
    for (int mi = 0; mi < 4; mi++)
#pragma unroll
        for (int ni = 0; ni < 4; ni++)
#pragma unroll
            for (int r = 0; r < 4; r++) acc[mi][ni][r] = 0.f;

    int nIter = K >> 5;

    auto produce = [&](int it) {
        int s = it % 3;
        int k0 = it << 5;
        __half* As = hsm + s * STGH;
        __half* Bs = As + ASZH;
#pragma unroll
        for (int i = 0; i < 2; i++) {          // A: 512 16B chunks
            int idx = tid + 256 * i;
            int r = idx >> 2, c = (idx & 3) * 8;
            cp16(As + r * APADH + c, Agb + (size_t)r * K + k0 + c);
        }
#pragma unroll
        for (int i = 0; i < 2; i++) {          // B: 512 chunks
            int idx = tid + 256 * i;
            int r = idx >> 2, c = (idx & 3) * 8;
            cp16(Bs + r * APADH + c, Bgb + (size_t)r * K + k0 + c);
        }
        CP_COMMIT();
    };

    produce(0);
    produce(1);

    for (int it = 0; it < nIter; it++) {
        int s = it % 3;
        if (it + 1 < nIter) { CP_WAIT(1); } else { CP_WAIT(0); }
        __syncthreads();
        if (it + 2 < nIter) produce(it + 2);

        const __half* As = hsm + s * STGH;
        const __half* Bs = As + ASZH;
        uint32_t a_u32 = (uint32_t)__cvta_generic_to_shared(As);
        uint32_t b_u32 = (uint32_t)__cvta_generic_to_shared(Bs);

#pragma unroll
        for (int ks = 0; ks < 2; ks++) {
            int kh = ks * 16;
            uint32_t af[4][4], bf[2][4];
            // A fragments: 4 ldmatrix.x4 (16 rows x 16 k each)
#pragma unroll
            for (int mi = 0; mi < 4; mi++) {
                uint32_t addr = a_u32 +
                    (uint32_t)(((wm + mi * 16 + lm_r) * APADH + kh + lm_c) * 2);
                ldmatrix_x4(af[mi][0], af[mi][1], af[mi][2], af[mi][3], addr);
            }
            // B fragments: 2 ldmatrix.x4 (16 n-rows x 16 k each)
#pragma unroll
            for (int n2 = 0; n2 < 2; n2++) {
                uint32_t addr = b_u32 +
                    (uint32_t)(((wn + n2 * 16 + lm_r) * APADH + kh + lm_c) * 2);
                ldmatrix_x4(bf[n2][0], bf[n2][1], bf[n2][2], bf[n2][3], addr);
            }
#pragma unroll
            for (int mi = 0; mi < 4; mi++)
#pragma unroll
                for (int ni = 0; ni < 4; ni++) {
                    int n2 = ni >> 1, lo = ni & 1;
                    uint32_t b[2] = { bf[n2][lo], bf[n2][lo + 2] };
                    mma_f16(acc[mi][ni], af[mi], b);
                }
        }
    }

    // epilogue
#pragma unroll
    for (int mi = 0; mi < 4; mi++) {
#pragma unroll
        for (int rr = 0; rr < 2; rr++) {
            int m = bm + wm + mi * 16 + g + rr * 8;
            size_t rowoff = (size_t)m * N;
#pragma unroll
            for (int ni = 0; ni < 4; ni++) {
                int n = bn + wn + ni * 8 + tg * 2;
                float v0 = acc[mi][ni][rr * 2 + 0] + bias[n];
                float v1 = acc[mi][ni][rr * 2 + 1] + bias[n + 1];
                if (EPI == 1) {
                    v0 = 0.5f * v0 * (1.f + erff(v0 * 0.70710678118654752f));
                    v1 = 0.5f * v1 * (1.f + erff(v1 * 0.70710678118654752f));
                    *(__half2*)((__half*)Co + rowoff + n) = __floats2half2_rn(v0, v1);
                } else {
                    if (EPI == 2) {
                        v0 += add1[rowoff + n] + add2[rowoff + n];
                        v1 += add1[rowoff + n + 1] + add2[rowoff + n + 1];
                    }
                    *(float2*)((float*)Co + rowoff + n) = make_float2(v0, v1);
                }
            }
        }
    }
}

// ---------------- Flash attention, fp16 MMA, BM=64, BN=64, D=128 ----------------
#define QK_PAD 136
#define P_PAD  72
#define KV_HALVES (64 * QK_PAD)
#define ATT_SMEM ((64 * QK_PAD + KV_HALVES + 64 * P_PAD) * 2)   // 44032 B

__global__ __launch_bounds__(128) void attn_kernel(
    const float* __restrict__ qkv, __half* __restrict__ y)
{
    extern __shared__ __half hsm_a[];
    __half* Qs  = hsm_a;                       // [64][136]
    __half* KVs = hsm_a + 64 * QK_PAD;         // K or V tile [64][136]
    __half* Ps  = KVs + KV_HALVES;             // [64][72]

    int qt = blockIdx.x, h = blockIdx.y, b = blockIdx.z;
    int gq = h >> 2;
    int qcol = (gq * 6 + (h & 3)) * HEAD;
    int kcol = (gq * 6 + 4) * HEAD;
    int vcol = (gq * 6 + 5) * HEAD;

    int tid = threadIdx.x, lane = tid & 31, w = tid >> 5;
    int g = lane >> 2, tg = lane & 3;
    int qbase = qt * 64;
    const size_t RS = QKV_OUT;
    const float scale = 0.08838834764831845f;  // folded into Q

    int lm_row = ((lane >> 3) & 1) * 8 + (lane & 7);
    int lm_dim = (lane >> 4) * 8;
    uint32_t v_u32 = (uint32_t)__cvta_generic_to_shared(KVs);

    // load Q tile (scaled, fp16)
    for (int idx = tid; idx < 64 * 32; idx += 128) {
        int rr = idx >> 5, dd = (idx & 31) * 4;
        float4 q = *(const float4*)(qkv + (size_t)(b * T_ + qbase + rr) * RS + qcol + dd);
        uint2 u = make_uint2(h2u(__floats2half2_rn(q.x * scale, q.y * scale)),
                             h2u(__floats2half2_rn(q.z * scale, q.w * scale)));
        *(uint2*)&Qs[rr * QK_PAD + dd] = u;
    }

    float o[16][4];
#pragma unroll
    for (int nt = 0; nt < 16; nt++)
#pragma unroll
        for (int c = 0; c < 4; c++) o[nt][c] = 0.f;
    float rmax0 = -1e30f, rmax1 = -1e30f;
    float rsum0 = 0.f,    rsum1 = 0.f;

    int row0 = qbase + w * 16 + g;
    int row1 = row0 + 8;

    for (int kt = 0; kt <= qt; kt++) {
        int nb = kt * 64;
        __syncthreads();
        for (int idx = tid; idx < 64 * 32; idx += 128) {
            int rr = idx >> 5, dd = (idx & 31) * 4;
            float4 k = *(const float4*)(qkv + (size_t)(b * T_ + nb + rr) * RS + kcol + dd);
            uint2 u = make_uint2(h2u(__floats2half2_rn(k.x, k.y)),
                                 h2u(__floats2half2_rn(k.z, k.w)));
            *(uint2*)&KVs[rr * QK_PAD + dd] = u;
        }
        __syncthreads();

        float s[8][4];
#pragma unroll
        for (int nt = 0; nt < 8; nt++)
#pragma unroll
            for (int c = 0; c < 4; c++) s[nt][c] = 0.f;

#pragma unroll
        for (int ks = 0; ks < 8; ks++) {
            int kh = ks * 16;
            uint32_t a[4];
            a[0] = *(const uint32_t*)&Qs[(w * 16 + g) * QK_PAD + kh + 2 * tg];
            a[1] = *(const uint32_t*)&Qs[(w * 16 + g + 8) * QK_PAD + kh + 2 * tg];
            a[2] = *(const uint32_t*)&Qs[(w * 16 + g) * QK_PAD + kh + 2 * tg + 8];
            a[3] = *(const uint32_t*)&Qs[(w * 16 + g + 8) * QK_PAD + kh + 2 * tg + 8];
#pragma unroll
            for (int nt = 0; nt < 8; nt++) {
                uint32_t bf[2];
                bf[0] = *(const uint32_t*)&KVs[(nt * 8 + g) * QK_PAD + kh + 2 * tg];
                bf[1] = *(const uint32_t*)&KVs[(nt * 8 + g) * QK_PAD + kh + 2 * tg + 8];
                mma_f16(s[nt], a, bf);
            }
        }

        bool diag = (kt == qt);
        float ml0 = -1e30f, ml1 = -1e30f;
#pragma unroll
        for (int nt = 0; nt < 8; nt++) {
            int colb = nb + nt * 8 + tg * 2;
            float v0 = s[nt][0], v1 = s[nt][1];
            float v2 = s[nt][2], v3 = s[nt][3];
            if (diag) {
                if (colb     > row0) v0 = -1e30f;
                if (colb + 1 > row0) v1 = -1e30f;
                if (colb     > row1) v2 = -1e30f;
                if (colb + 1 > row1) v3 = -1e30f;
            }
            s[nt][0] = v0; s[nt][1] = v1; s[nt][2] = v2; s[nt][3] = v3;
            ml0 = fmaxf(ml0, fmaxf(v0, v1));
            ml1 = fmaxf(ml1, fmaxf(v2, v3));
        }
        ml0 = fmaxf(ml0, __shfl_xor_sync(0xffffffffu, ml0, 1));
        ml0 = fmaxf(ml0, __shfl_xor_sync(0xffffffffu, ml0, 2));
        ml1 = fmaxf(ml1, __shfl_xor_sync(0xffffffffu, ml1, 1));
        ml1 = fmaxf(ml1, __shfl_xor_sync(0xffffffffu, ml1, 2));

        float nm0 = fmaxf(rmax0, ml0), nm1 = fmaxf(rmax1, ml1);
        float f0 = __expf(rmax0 - nm0), f1 = __expf(rmax1 - nm1);
        rmax0 = nm0; rmax1 = nm1;

        float ps0 = 0.f, ps1 = 0.f;
#pragma unroll
        for (int nt = 0; nt < 8; nt++) {
            float p0 = __expf(s[nt][0] - nm0);
            float p1 = __expf(s[nt][1] - nm0);
            float p2 = __expf(s[nt][2] - nm1);
            float p3 = __expf(s[nt][3] - nm1);
            ps0 += p0 + p1;
            ps1 += p2 + p3;
            *(uint32_t*)&Ps[(w * 16 + g) * P_PAD + nt * 8 + 2 * tg] =
                h2u(__floats2half2_rn(p0, p1));
            *(uint32_t*)&Ps[(w * 16 + g + 8) * P_PAD + nt * 8 + 2 * tg] =
                h2u(__floats2half2_rn(p2, p3));
        }
        ps0 += __shfl_xor_sync(0xffffffffu, ps0, 1);
        ps0 += __shfl_xor_sync(0xffffffffu, ps0, 2);
        ps1 += __shfl_xor_sync(0xffffffffu, ps1, 1);
        ps1 += __shfl_xor_sync(0xffffffffu, ps1, 2);
        rsum0 = rsum0 * f0 + ps0;
        rsum1 = rsum1 * f1 + ps1;

#pragma unroll
        for (int nt = 0; nt < 16; nt++) {
            o[nt][0] *= f0; o[nt][1] *= f0;
            o[nt][2] *= f1; o[nt][3] *= f1;
        }
        __syncthreads();

        // load V tile naturally [key][dim]
        for (int idx = tid; idx < 64 * 32; idx += 128) {
            int rr = idx >> 5, dd = (idx & 31) * 4;
            float4 v = *(const float4*)(qkv + (size_t)(b * T_ + nb + rr) * RS + vcol + dd);
            uint2 u = make_uint2(h2u(__floats2half2_rn(v.x, v.y)),
                                 h2u(__floats2half2_rn(v.z, v.w)));
            *(uint2*)&KVs[rr * QK_PAD + dd] = u;
        }
        __syncthreads();

        // O += P V via ldmatrix.x4.trans
#pragma unroll
        for (int ks = 0; ks < 4; ks++) {
            int kh = ks * 16;
            uint32_t a[4];
            a[0] = *(const uint32_t*)&Ps[(w * 16 + g) * P_PAD + kh + 2 * tg];
            a[1] = *(const uint32_t*)&Ps[(w * 16 + g + 8) * P_PAD + kh + 2 * tg];
            a[2] = *(const uint32_t*)&Ps[(w * 16 + g) * P_PAD + kh + 2 * tg + 8];
            a[3] = *(const uint32_t*)&Ps[(w * 16 + g + 8) * P_PAD + kh + 2 * tg + 8];
#pragma unroll
            for (int ntp = 0; ntp < 8; ntp++) {
                uint32_t addr = v_u32 +
                    (uint32_t)(((kh + lm_row) * QK_PAD + ntp * 16 + lm_dim) * 2);
                uint32_t r0, r1, r2, r3;
                ldmatrix_x4_trans(r0, r1, r2, r3, addr);
                uint32_t b0[2] = {r0, r1};
                uint32_t b1[2] = {r2, r3};
                mma_f16(o[2 * ntp],     a, b0);
                mma_f16(o[2 * ntp + 1], a, b1);
            }
        }
    }

    float inv0 = 1.f / rsum0, inv1 = 1.f / rsum1;
    size_t m0 = (size_t)(b * T_ + row0);
    size_t m1 = m0 + 8;
#pragma unroll
    for (int nt = 0; nt < 16; nt++) {
        int col = h * HEAD + nt * 8 + tg * 2;
        *(__half2*)(y + m0 * C_ + col) = __floats2half2_rn(o[nt][0] * inv0, o[nt][1] * inv0);
        *(__half2*)(y + m1 * C_ + col) = __floats2half2_rn(o[nt][2] * inv1, o[nt][3] * inv1);
    }
}

// ---------------- launcher -----------------------------------------------------
extern "C" void kernel_launch(void* const* d_in, const int* in_sizes, int n_in,
                              void* d_out, int out_size)
{
    const float* x     = (const float*)d_in[0];
    const float* cosb  = (const float*)d_in[1];
    const float* sinb  = (const float*)d_in[2];
    const float* ln1w  = (const float*)d_in[3];
    const float* ln1b  = (const float*)d_in[4];
    const float* wqkv  = (const float*)d_in[5];
    const float* bqkv  = (const float*)d_in[6];
    const float* wproj = (const float*)d_in[7];
    const float* bproj = (const float*)d_in[8];
    const float* ln2w  = (const float*)d_in[9];
    const float* ln2b  = (const float*)d_in[10];
    const float* wfc1  = (const float*)d_in[11];
    const float* bfc1  = (const float*)d_in[12];
    const float* wfc2  = (const float*)d_in[13];
    const float* bfc2  = (const float*)d_in[14];
    float* out = (float*)d_out;

    __half *ln1, *ln2, *y, *act, *wqt, *wpt, *w1t, *w2t;
    float *qkv, *h;
    cudaGetSymbolAddress((void**)&ln1, g_ln1);
    cudaGetSymbolAddress((void**)&ln2, g_ln2);
    cudaGetSymbolAddress((void**)&qkv, g_qkv);
    cudaGetSymbolAddress((void**)&y,   g_y);
    cudaGetSymbolAddress((void**)&h,   g_h);
    cudaGetSymbolAddress((void**)&act, g_act);
    cudaGetSymbolAddress((void**)&wqt, g_wqkv_t);
    cudaGetSymbolAddress((void**)&wpt, g_wproj_t);
    cudaGetSymbolAddress((void**)&w1t, g_wfc1_t);
    cudaGetSymbolAddress((void**)&w2t, g_wfc2_t);

    cudaFuncSetAttribute(hgemm_kernel<0>, cudaFuncAttributeMaxDynamicSharedMemorySize, HSM_BYTES);
    cudaFuncSetAttribute(hgemm_kernel<1>, cudaFuncAttributeMaxDynamicSharedMemorySize, HSM_BYTES);
    cudaFuncSetAttribute(hgemm_kernel<2>, cudaFuncAttributeMaxDynamicSharedMemorySize, HSM_BYTES);
    cudaFuncSetAttribute(attn_kernel, cudaFuncAttributeMaxDynamicSharedMemorySize, ATT_SMEM);

    dim3 tb(32, 8);
    transpose_h_kernel<<<dim3(C_ / 64, QKV_OUT / 32), tb>>>(wqkv, wqt, C_, QKV_OUT);
    transpose_h_kernel<<<dim3(C_ / 64, C_ / 32), tb>>>(wproj, wpt, C_, C_);
    transpose_h_kernel<<<dim3(C_ / 64, FFN / 32), tb>>>(wfc1, w1t, C_, FFN);
    transpose_h_kernel<<<dim3(FFN / 64, C_ / 32), tb>>>(wfc2, w2t, FFN, C_);

    // 1. dual LayerNorm (fp16 outputs)
    ln_dual_kernel<<<M_TOK, 256>>>(x, ln1w, ln1b, ln2w, ln2b, ln1, ln2);

    // 2. QKV projection -> fp32 qkv
    hgemm_kernel<0><<<dim3(QKV_OUT / 128, M_TOK / 128), 256, HSM_BYTES>>>(
        ln1, wqt, bqkv, qkv, M_TOK, QKV_OUT, C_, nullptr, nullptr);

    // 3. RoPE
    rope_kernel<<<M_TOK, 320>>>(qkv, cosb, sinb);

    // 4. flash attention -> fp16 y
    attn_kernel<<<dim3(T_ / 64, N_HEAD, B_), 128, ATT_SMEM>>>(qkv, y);

    // 5. output projection -> fp32 h
    hgemm_kernel<0><<<dim3(C_ / 128, M_TOK / 128), 256, HSM_BYTES>>>(
        y, wpt, bproj, h, M_TOK, C_, C_, nullptr, nullptr);

    // 6. fc1 + GELU -> fp16 act
    hgemm_kernel<1><<<dim3(FFN / 128, M_TOK / 128), 256, HSM_BYTES>>>(
        ln2, w1t, bfc1, act, M_TOK, FFN, C_, nullptr, nullptr);

    // 7. fc2 + h + x -> out (fp32)
    hgemm_kernel<2><<<dim3(C_ / 128, M_TOK / 128), 256, HSM_BYTES>>>(
        act, w2t, bfc2, out, M_TOK, C_, FFN, h, x);
}

// round 14
// speedup vs baseline: 6.3845x; 1.0161x over previous
#include <cuda_runtime.h>
#include <cuda_fp16.h>
#include <math.h>
#include <stdint.h>

#define N_HEAD   16
#define HEAD     128
#define ROPE     32
#define C_       2048
#define B_       2
#define T_       2048
#define M_TOK    (B_*T_)        // 4096
#define QKV_OUT  3072
#define FFN      8192

// ---------------- scratch (device globals; no allocations allowed) -------------
__device__ __half g_ln1[(size_t)M_TOK * C_];
__device__ __half g_ln2[(size_t)M_TOK * C_];
__device__ float  g_qkv[(size_t)M_TOK * QKV_OUT];
__device__ __half g_y  [(size_t)M_TOK * C_];
__device__ float  g_h  [(size_t)M_TOK * C_];
__device__ float  g_mlp[(size_t)M_TOK * C_];
__device__ __half g_act[(size_t)M_TOK * FFN];
// transposed fp16 weights, [N][K]
__device__ __half g_wqkv_t[(size_t)QKV_OUT * C_];
__device__ __half g_wproj_t[(size_t)C_ * C_];
__device__ __half g_wfc1_t[(size_t)FFN * C_];
__device__ __half g_wfc2_t[(size_t)C_ * FFN];

// ---------------- helpers --------------------------------------------------------
__device__ __forceinline__ void mma_f16(float* c, const uint32_t* a, const uint32_t* b) {
    asm volatile(
        "mma.sync.aligned.m16n8k16.row.col.f32.f16.f16.f32 "
        "{%0,%1,%2,%3}, {%4,%5,%6,%7}, {%8,%9}, {%0,%1,%2,%3};"
        : "+f"(c[0]), "+f"(c[1]), "+f"(c[2]), "+f"(c[3])
        : "r"(a[0]), "r"(a[1]), "r"(a[2]), "r"(a[3]),
          "r"(b[0]), "r"(b[1]));
}

__device__ __forceinline__ void cp16(void* smem, const void* gmem) {
    uint32_t sa = (uint32_t)__cvta_generic_to_shared(smem);
    asm volatile("cp.async.cg.shared.global [%0], [%1], 16;" :: "r"(sa), "l"(gmem));
}
#define CP_COMMIT() asm volatile("cp.async.commit_group;" ::: "memory")
#define CP_WAIT(n)  asm volatile("cp.async.wait_group %0;" :: "n"(n) : "memory")

__device__ __forceinline__ uint32_t h2u(__half2 h) { return *(uint32_t*)&h; }

__device__ __forceinline__ void ldmatrix_x4(
    uint32_t& r0, uint32_t& r1, uint32_t& r2, uint32_t& r3, uint32_t smem_addr)
{
    asm volatile(
        "ldmatrix.sync.aligned.m8n8.x4.shared.b16 {%0,%1,%2,%3}, [%4];"
        : "=r"(r0), "=r"(r1), "=r"(r2), "=r"(r3) : "r"(smem_addr));
}

__device__ __forceinline__ void ldmatrix_x4_trans(
    uint32_t& r0, uint32_t& r1, uint32_t& r2, uint32_t& r3, uint32_t smem_addr)
{
    asm volatile(
        "ldmatrix.sync.aligned.m8n8.x4.trans.shared.b16 {%0,%1,%2,%3}, [%4];"
        : "=r"(r0), "=r"(r1), "=r"(r2), "=r"(r3) : "r"(smem_addr));
}

// ---------------- transpose device body -----------------------------------------
__device__ __forceinline__ void transpose_dev(
    const float* __restrict__ W, __half* __restrict__ Wt, int K, int N,
    int bx, int by, float (*t)[33], int tx, int ty)
{
    int k0 = bx * 64, n0 = by * 32;
#pragma unroll
    for (int i = 0; i < 64; i += 8)
        t[ty + i][tx] = W[(size_t)(k0 + ty + i) * N + n0 + tx];
    __syncthreads();
#pragma unroll
    for (int j = 0; j < 32; j += 8) {
        int n = n0 + ty + j;
        __half2 h = __floats2half2_rn(t[2 * tx][ty + j], t[2 * tx + 1][ty + j]);
        *(__half2*)&Wt[(size_t)n * K + k0 + 2 * tx] = h;
    }
}

// fused 4-way transpose: block ranges per weight
#define TB_QKV  3072   // (2048/64)*(3072/32)
#define TB_PROJ 2048   // 32*64
#define TB_FC1  8192   // 32*256
#define TB_FC2  8192   // 128*64
__global__ __launch_bounds__(256) void t4_kernel(
    const float* wqkv, __half* wqt, const float* wproj, __half* wpt,
    const float* wfc1, __half* w1t, const float* wfc2, __half* w2t)
{
    __shared__ float t[64][33];
    int tx = threadIdx.x & 31, ty = threadIdx.x >> 5;
    int bi = blockIdx.x;
    if (bi < TB_QKV) {
        transpose_dev(wqkv, wqt, C_, QKV_OUT, bi % 32, bi / 32, t, tx, ty);
    } else if (bi < TB_QKV + TB_PROJ) {
        int li = bi - TB_QKV;
        transpose_dev(wproj, wpt, C_, C_, li % 32, li / 32, t, tx, ty);
    } else if (bi < TB_QKV + TB_PROJ + TB_FC1) {
        int li = bi - TB_QKV - TB_PROJ;
        transpose_dev(wfc1, w1t, C_, FFN, li % 32, li / 32, t, tx, ty);
    } else {
        int li = bi - TB_QKV - TB_PROJ - TB_FC1;
        transpose_dev(wfc2, w2t, FFN, C_, li % 128, li / 128, t, tx, ty);
    }
}

// ---------------- fused dual LayerNorm (fp16 outputs, vectorized) ---------------
__global__ __launch_bounds__(256) void ln_dual_kernel(
    const float* __restrict__ x,
    const float* __restrict__ w1, const float* __restrict__ b1,
    const float* __restrict__ w2, const float* __restrict__ b2,
    __half* __restrict__ o1, __half* __restrict__ o2)
{
    int row = blockIdx.x;
    const float* xr = x + (size_t)row * C_;
    int tid = threadIdx.x;
    int c0 = tid * 8;

    float v[8];
    *(float4*)&v[0] = *(const float4*)(xr + c0);
    *(float4*)&v[4] = *(const float4*)(xr + c0 + 4);
    float s = 0.f, s2 = 0.f;
#pragma unroll
    for (int i = 0; i < 8; i++) { s += v[i]; s2 += v[i] * v[i]; }
#pragma unroll
    for (int o = 16; o; o >>= 1) {
        s  += __shfl_xor_sync(0xffffffffu, s,  o);
        s2 += __shfl_xor_sync(0xffffffffu, s2, o);
    }
    __shared__ float sh[16];
    __shared__ float mu_s, rstd_s;
    int w = tid >> 5;
    if ((tid & 31) == 0) { sh[w] = s; sh[w + 8] = s2; }
    __syncthreads();
    if (tid == 0) {
        float a = 0.f, b = 0.f;
#pragma unroll
        for (int i = 0; i < 8; i++) { a += sh[i]; b += sh[i + 8]; }
        float mu  = a * (1.0f / C_);
        float var = b * (1.0f / C_) - mu * mu;
        mu_s = mu;
        rstd_s = rsqrtf(var + 1e-5f);
    }
    __syncthreads();
    float mu = mu_s, rs = rstd_s;

    float w1v[8], b1v[8], w2v[8], b2v[8];
    *(float4*)&w1v[0] = *(const float4*)(w1 + c0);
    *(float4*)&w1v[4] = *(const float4*)(w1 + c0 + 4);
    *(float4*)&b1v[0] = *(const float4*)(b1 + c0);
    *(float4*)&b1v[4] = *(const float4*)(b1 + c0 + 4);
    *(float4*)&w2v[0] = *(const float4*)(w2 + c0);
    *(float4*)&w2v[4] = *(const float4*)(w2 + c0 + 4);
    *(float4*)&b2v[0] = *(const float4*)(b2 + c0);
    *(float4*)&b2v[4] = *(const float4*)(b2 + c0 + 4);

    uint32_t u1[4], u2[4];
#pragma unroll
    for (int j = 0; j < 4; j++) {
        float n0 = (v[2 * j] - mu) * rs, n1 = (v[2 * j + 1] - mu) * rs;
        u1[j] = h2u(__floats2half2_rn(n0 * w1v[2 * j] + b1v[2 * j],
                                      n1 * w1v[2 * j + 1] + b1v[2 * j + 1]));
        u2[j] = h2u(__floats2half2_rn(n0 * w2v[2 * j] + b2v[2 * j],
                                      n1 * w2v[2 * j + 1] + b2v[2 * j + 1]));
    }
    *(uint4*)(o1 + (size_t)row * C_ + c0) = make_uint4(u1[0], u1[1], u1[2], u1[3]);
    *(uint4*)(o2 + (size_t)row * C_ + c0) = make_uint4(u2[0], u2[1], u2[2], u2[3]);
}

// ---------------- RoPE in place on qkv (fp32) ------------------------------------
__global__ __launch_bounds__(320) void rope_kernel(
    float* __restrict__ qkv,
    const float* __restrict__ cosb, const float* __restrict__ sinb)
{
    int r = blockIdx.x;
    int t = r & (T_ - 1);
    int tid = threadIdx.x;
    int hh = tid >> 4;
    int i  = tid & 15;
    int col;
    if (hh < 16) col = ((hh >> 2) * 6 + (hh & 3)) * HEAD;
    else         col = ((hh - 16) * 6 + 4) * HEAD;
    float* p = qkv + (size_t)r * QKV_OUT + col;
    float c1 = cosb[t * ROPE + i],      s1 = sinb[t * ROPE + i];
    float c2 = cosb[t * ROPE + i + 16], s2 = sinb[t * ROPE + i + 16];
    float x1 = p[i], x2 = p[i + 16];
    p[i]      = x1 * c1 - x2 * s1;
    p[i + 16] = x2 * c2 + x1 * s2;
}

// ---------------- fp16 GEMM device body: 128x128x32, 8 warps, ldmatrix ----------
#define APADH 40
#define ASZH  (128 * APADH)
#define BSZH  (128 * APADH)
#define STGH  (ASZH + BSZH)
#define HSM_BYTES (3 * STGH * 2)       // 61440

template <int EPI>
__device__ __forceinline__ void hgemm_dev(
    const __half* __restrict__ A, const __half* __restrict__ Bt,
    const float* __restrict__ bias, void* __restrict__ Co,
    int N, int K, int bx, int by, __half* hsm)
{
    int tid = threadIdx.x;
    int lane = tid & 31, wid = tid >> 5;
    int wm = (wid >> 2) * 64;
    int wn = (wid & 3) * 32;
    int g  = lane >> 2;
    int tg = lane & 3;
    int bm = by * 128, bn = bx * 128;

    const __half* Agb = A  + (size_t)bm * K;
    const __half* Bgb = Bt + (size_t)bn * K;

    int lm_r = lane & 15;
    int lm_c = (lane >> 4) * 8;

    float acc[4][4][4];
#pragma unroll
    for (int mi = 0; mi < 4; mi++)
#pragma unroll
        for (int ni = 0; ni < 4; ni++)
#pragma unroll
            for (int r = 0; r < 4; r++) acc[mi][ni][r] = 0.f;

    int nIter = K >> 5;

    auto produce = [&](int it) {
        int s = it % 3;
        int k0 = it << 5;
        __half* As = hsm + s * STGH;
        __half* Bs = As + ASZH;
#pragma unroll
        for (int i = 0; i < 2; i++) {
            int idx = tid + 256 * i;
            int r = idx >> 2, c = (idx & 3) * 8;
            cp16(As + r * APADH + c, Agb + (size_t)r * K + k0 + c);
        }
#pragma unroll
        for (int i = 0; i < 2; i++) {
            int idx = tid + 256 * i;
            int r = idx >> 2, c = (idx & 3) * 8;
            cp16(Bs + r * APADH + c, Bgb + (size_t)r * K + k0 + c);
        }
        CP_COMMIT();
    };

    produce(0);
    produce(1);

    for (int it = 0; it < nIter; it++) {
        int s = it % 3;
        if (it + 1 < nIter) { CP_WAIT(1); } else { CP_WAIT(0); }
        __syncthreads();
        if (it + 2 < nIter) produce(it + 2);

        const __half* As = hsm + s * STGH;
        const __half* Bs = As + ASZH;
        uint32_t a_u32 = (uint32_t)__cvta_generic_to_shared(As);
        uint32_t b_u32 = (uint32_t)__cvta_generic_to_shared(Bs);

#pragma unroll
        for (int ks = 0; ks < 2; ks++) {
            int kh = ks * 16;
            uint32_t af[4][4], bf[2][4];
#pragma unroll
            for (int mi = 0; mi < 4; mi++) {
                uint32_t addr = a_u32 +
                    (uint32_t)(((wm + mi * 16 + lm_r) * APADH + kh + lm_c) * 2);
                ldmatrix_x4(af[mi][0], af[mi][1], af[mi][2], af[mi][3], addr);
            }
#pragma unroll
            for (int n2 = 0; n2 < 2; n2++) {
                uint32_t addr = b_u32 +
                    (uint32_t)(((wn + n2 * 16 + lm_r) * APADH + kh + lm_c) * 2);
                ldmatrix_x4(bf[n2][0], bf[n2][1], bf[n2][2], bf[n2][3], addr);
            }
#pragma unroll
            for (int mi = 0; mi < 4; mi++)
#pragma unroll
                for (int ni = 0; ni < 4; ni++) {
                    int n2 = ni >> 1, lo = ni & 1;
                    uint32_t b[2] = { bf[n2][lo], bf[n2][lo + 2] };
                    mma_f16(acc[mi][ni], af[mi], b);
                }
        }
    }

#pragma unroll
    for (int mi = 0; mi < 4; mi++) {
#pragma unroll
        for (int rr = 0; rr < 2; rr++) {
            int m = bm + wm + mi * 16 + g + rr * 8;
            size_t rowoff = (size_t)m * N;
#pragma unroll
            for (int ni = 0; ni < 4; ni++) {
                int n = bn + wn + ni * 8 + tg * 2;
                float v0 = acc[mi][ni][rr * 2 + 0] + bias[n];
                float v1 = acc[mi][ni][rr * 2 + 1] + bias[n + 1];
                if (EPI == 1) {
                    v0 = 0.5f * v0 * (1.f + erff(v0 * 0.70710678118654752f));
                    v1 = 0.5f * v1 * (1.f + erff(v1 * 0.70710678118654752f));
                    *(__half2*)((__half*)Co + rowoff + n) = __floats2half2_rn(v0, v1);
                } else {
                    *(float2*)((float*)Co + rowoff + n) = make_float2(v0, v1);
                }
            }
        }
    }
}

// standalone GEMM wrapper (used for QKV)
template <int EPI>
__global__ __launch_bounds__(256, 2) void hgemm_kernel(
    const __half* __restrict__ A, const __half* __restrict__ Bt,
    const float* __restrict__ bias, void* __restrict__ Co, int N, int K)
{
    extern __shared__ __half hsm[];
    hgemm_dev<EPI>(A, Bt, bias, Co, N, K, blockIdx.x, blockIdx.y, hsm);
}

// ---------------- attention device body (one 64-row q-tile, 128 threads) --------
#define QK_PAD 136
#define P_PAD  72
#define KV_HALVES (64 * QK_PAD)
#define ATT_HALF_BYTES ((64 * QK_PAD + KV_HALVES + 64 * P_PAD) * 2)  // 44032
#define F1_SMEM (2 * ATT_HALF_BYTES)                                 // 88064

__device__ __forceinline__ void attn_dev(
    const float* __restrict__ qkv, __half* __restrict__ y,
    int qt, int myN, int maxN, int hh, int bb, __half* sm, int tid128)
{
    __half* Qs  = sm;
    __half* KVs = sm + 64 * QK_PAD;
    __half* Ps  = KVs + KV_HALVES;

    int gq = hh >> 2;
    int qcol = (gq * 6 + (hh & 3)) * HEAD;
    int kcol = (gq * 6 + 4) * HEAD;
    int vcol = (gq * 6 + 5) * HEAD;

    int lane = tid128 & 31, w = tid128 >> 5;
    int g = lane >> 2, tg = lane & 3;
    int qbase = qt * 64;
    const size_t RS = QKV_OUT;
    const float scale = 0.08838834764831845f;

    int lm_row = ((lane >> 3) & 1) * 8 + (lane & 7);
    int lm_dim = (lane >> 4) * 8;
    uint32_t v_u32 = (uint32_t)__cvta_generic_to_shared(KVs);

    // load Q tile (scaled, fp16)
    for (int idx = tid128; idx < 64 * 32; idx += 128) {
        int rr = idx >> 5, dd = (idx & 31) * 4;
        float4 q = *(const float4*)(qkv + (size_t)(bb * T_ + qbase + rr) * RS + qcol + dd);
        uint2 u = make_uint2(h2u(__floats2half2_rn(q.x * scale, q.y * scale)),
                             h2u(__floats2half2_rn(q.z * scale, q.w * scale)));
        *(uint2*)&Qs[rr * QK_PAD + dd] = u;
    }

    float o[16][4];
#pragma unroll
    for (int nt = 0; nt < 16; nt++)
#pragma unroll
        for (int c = 0; c < 4; c++) o[nt][c] = 0.f;
    float rmax0 = -1e30f, rmax1 = -1e30f;
    float rsum0 = 0.f,    rsum1 = 0.f;

    int row0 = qbase + w * 16 + g;
    int row1 = row0 + 8;

    for (int kt = 0; kt < maxN; kt++) {
        int nb = kt * 64;
        bool act = (kt < myN);
        __syncthreads();
        if (act) {
            for (int idx = tid128; idx < 64 * 32; idx += 128) {
                int rr = idx >> 5, dd = (idx & 31) * 4;
                float4 k = *(const float4*)(qkv + (size_t)(bb * T_ + nb + rr) * RS + kcol + dd);
                uint2 u = make_uint2(h2u(__floats2half2_rn(k.x, k.y)),
                                     h2u(__floats2half2_rn(k.z, k.w)));
                *(uint2*)&KVs[rr * QK_PAD + dd] = u;
            }
        }
        __syncthreads();

        if (act) {
            float s[8][4];
#pragma unroll
            for (int nt = 0; nt < 8; nt++)
#pragma unroll
                for (int c = 0; c < 4; c++) s[nt][c] = 0.f;

#pragma unroll
            for (int ks = 0; ks < 8; ks++) {
                int kh = ks * 16;
                uint32_t a[4];
                a[0] = *(const uint32_t*)&Qs[(w * 16 + g) * QK_PAD + kh + 2 * tg];
                a[1] = *(const uint32_t*)&Qs[(w * 16 + g + 8) * QK_PAD + kh + 2 * tg];
                a[2] = *(const uint32_t*)&Qs[(w * 16 + g) * QK_PAD + kh + 2 * tg + 8];
                a[3] = *(const uint32_t*)&Qs[(w * 16 + g + 8) * QK_PAD + kh + 2 * tg + 8];
#pragma unroll
                for (int nt = 0; nt < 8; nt++) {
                    uint32_t bf[2];
                    bf[0] = *(const uint32_t*)&KVs[(nt * 8 + g) * QK_PAD + kh + 2 * tg];
                    bf[1] = *(const uint32_t*)&KVs[(nt * 8 + g) * QK_PAD + kh + 2 * tg + 8];
                    mma_f16(s[nt], a, bf);
                }
            }

            bool diag = (kt == qt);
            float ml0 = -1e30f, ml1 = -1e30f;
#pragma unroll
            for (int nt = 0; nt < 8; nt++) {
                int colb = nb + nt * 8 + tg * 2;
                float v0 = s[nt][0], v1 = s[nt][1];
                float v2 = s[nt][2], v3 = s[nt][3];
                if (diag) {
                    if (colb     > row0) v0 = -1e30f;
                    if (colb + 1 > row0) v1 = -1e30f;
                    if (colb     > row1) v2 = -1e30f;
                    if (colb + 1 > row1) v3 = -1e30f;
                }
                s[nt][0] = v0; s[nt][1] = v1; s[nt][2] = v2; s[nt][3] = v3;
                ml0 = fmaxf(ml0, fmaxf(v0, v1));
                ml1 = fmaxf(ml1, fmaxf(v2, v3));
            }
            ml0 = fmaxf(ml0, __shfl_xor_sync(0xffffffffu, ml0, 1));
            ml0 = fmaxf(ml0, __shfl_xor_sync(0xffffffffu, ml0, 2));
            ml1 = fmaxf(ml1, __shfl_xor_sync(0xffffffffu, ml1, 1));
            ml1 = fmaxf(ml1, __shfl_xor_sync(0xffffffffu, ml1, 2));

            float nm0 = fmaxf(rmax0, ml0), nm1 = fmaxf(rmax1, ml1);
            float f0 = __expf(rmax0 - nm0), f1 = __expf(rmax1 - nm1);
            rmax0 = nm0; rmax1 = nm1;

            float ps0 = 0.f, ps1 = 0.f;
#pragma unroll
            for (int nt = 0; nt < 8; nt++) {
                float p0 = __expf(s[nt][0] - nm0);
                float p1 = __expf(s[nt][1] - nm0);
                float p2 = __expf(s[nt][2] - nm1);
                float p3 = __expf(s[nt][3] - nm1);
                ps0 += p0 + p1;
                ps1 += p2 + p3;
                *(uint32_t*)&Ps[(w * 16 + g) * P_PAD + nt * 8 + 2 * tg] =
                    h2u(__floats2half2_rn(p0, p1));
                *(uint32_t*)&Ps[(w * 16 + g + 8) * P_PAD + nt * 8 + 2 * tg] =
                    h2u(__floats2half2_rn(p2, p3));
            }
            ps0 += __shfl_xor_sync(0xffffffffu, ps0, 1);
            ps0 += __shfl_xor_sync(0xffffffffu, ps0, 2);
            ps1 += __shfl_xor_sync(0xffffffffu, ps1, 1);
            ps1 += __shfl_xor_sync(0xffffffffu, ps1, 2);
            rsum0 = rsum0 * f0 + ps0;
            rsum1 = rsum1 * f1 + ps1;

#pragma unroll
            for (int nt = 0; nt < 16; nt++) {
                o[nt][0] *= f0; o[nt][1] *= f0;
                o[nt][2] *= f1; o[nt][3] *= f1;
            }
        }
        __syncthreads();

        if (act) {
            for (int idx = tid128; idx < 64 * 32; idx += 128) {
                int rr = idx >> 5, dd = (idx & 31) * 4;
                float4 v = *(const float4*)(qkv + (size_t)(bb * T_ + nb + rr) * RS + vcol + dd);
                uint2 u = make_uint2(h2u(__floats2half2_rn(v.x, v.y)),
                                     h2u(__floats2half2_rn(v.z, v.w)));
                *(uint2*)&KVs[rr * QK_PAD + dd] = u;
            }
        }
        __syncthreads();

        if (act) {
#pragma unroll
            for (int ks = 0; ks < 4; ks++) {
                int kh = ks * 16;
                uint32_t a[4];
                a[0] = *(const uint32_t*)&Ps[(w * 16 + g) * P_PAD + kh + 2 * tg];
                a[1] = *(const uint32_t*)&Ps[(w * 16 + g + 8) * P_PAD + kh + 2 * tg];
                a[2] = *(const uint32_t*)&Ps[(w * 16 + g) * P_PAD + kh + 2 * tg + 8];
                a[3] = *(const uint32_t*)&Ps[(w * 16 + g + 8) * P_PAD + kh + 2 * tg + 8];
#pragma unroll
                for (int ntp = 0; ntp < 8; ntp++) {
                    uint32_t addr = v_u32 +
                        (uint32_t)(((kh + lm_row) * QK_PAD + ntp * 16 + lm_dim) * 2);
                    uint32_t r0, r1, r2, r3;
                    ldmatrix_x4_trans(r0, r1, r2, r3, addr);
                    uint32_t b0[2] = {r0, r1};
                    uint32_t b1[2] = {r2, r3};
                    mma_f16(o[2 * ntp],     a, b0);
                    mma_f16(o[2 * ntp + 1], a, b1);
                }
            }
        }
    }

    float inv0 = 1.f / rsum0, inv1 = 1.f / rsum1;
    size_t m0 = (size_t)(bb * T_ + row0);
    size_t m1 = m0 + 8;
#pragma unroll
    for (int nt = 0; nt < 16; nt++) {
        int col = hh * HEAD + nt * 8 + tg * 2;
        *(__half2*)(y + m0 * C_ + col) = __floats2half2_rn(o[nt][0] * inv0, o[nt][1] * inv0);
        *(__half2*)(y + m1 * C_ + col) = __floats2half2_rn(o[nt][2] * inv1, o[nt][3] * inv1);
    }
}

// ---------------- fused1: attention (512 blocks) + fc1 GEMM (2048 blocks) -------
#define ATT_BLKS 512
__global__ __launch_bounds__(256, 2) void fused1_kernel(
    const float* __restrict__ qkv, __half* __restrict__ y,
    const __half* __restrict__ ln2, const __half* __restrict__ w1t,
    const float* __restrict__ bfc1, __half* __restrict__ act)
{
    extern __shared__ __half fsm[];
    int bi = blockIdx.x;
    if (bi < ATT_BLKS) {
        int p  = bi & 15;
        int hh = (bi >> 4) & 15;
        int bb = bi >> 8;
        int half = threadIdx.x >> 7;
        int tid128 = threadIdx.x & 127;
        int qt  = half ? (31 - p) : p;
        int myN = qt + 1;
        int maxN = 32 - p;                 // max(p+1, 32-p) for p<16
        __half* sm = fsm + half * (ATT_HALF_BYTES / 2);
        attn_dev(qkv, y, qt, myN, maxN, hh, bb, sm, tid128);
    } else {
        int li = bi - ATT_BLKS;
        hgemm_dev<1>(ln2, w1t, bfc1, act, FFN, C_, li & 63, li >> 6, fsm);
    }
}

// ---------------- fused2: proj (512 blocks) + fc2 (512 blocks) ------------------
__global__ __launch_bounds__(256, 2) void fused2_kernel(
    const __half* __restrict__ y,  const __half* __restrict__ wpt,
    const float* __restrict__ bproj, float* __restrict__ h,
    const __half* __restrict__ act, const __half* __restrict__ w2t,
    const float* __restrict__ bfc2, float* __restrict__ mlp)
{
    extern __shared__ __half fsm[];
    int bi = blockIdx.x;
    if (bi < 512) {
        hgemm_dev<0>(y, wpt, bproj, h, C_, C_, bi & 15, bi >> 4, fsm);
    } else {
        int li = bi - 512;
        hgemm_dev<0>(act, w2t, bfc2, mlp, C_, FFN, li & 15, li >> 4, fsm);
    }
}

// ---------------- final residual add: out = mlp + h + x -------------------------
__global__ __launch_bounds__(256) void add_kernel(
    const float* __restrict__ mlp, const float* __restrict__ h,
    const float* __restrict__ x, float* __restrict__ out)
{
    size_t i = ((size_t)blockIdx.x * 256 + threadIdx.x) * 4;
    float4 a = *(const float4*)(mlp + i);
    float4 b = *(const float4*)(h + i);
    float4 c = *(const float4*)(x + i);
    *(float4*)(out + i) = make_float4(a.x + b.x + c.x, a.y + b.y + c.y,
                                      a.z + b.z + c.z, a.w + b.w + c.w);
}

// ---------------- launcher -----------------------------------------------------
extern "C" void kernel_launch(void* const* d_in, const int* in_sizes, int n_in,
                              void* d_out, int out_size)
{
    const float* x     = (const float*)d_in[0];
    const float* cosb  = (const float*)d_in[1];
    const float* sinb  = (const float*)d_in[2];
    const float* ln1w  = (const float*)d_in[3];
    const float* ln1b  = (const float*)d_in[4];
    const float* wqkv  = (const float*)d_in[5];
    const float* bqkv  = (const float*)d_in[6];
    const float* wproj = (const float*)d_in[7];
    const float* bproj = (const float*)d_in[8];
    const float* ln2w  = (const float*)d_in[9];
    const float* ln2b  = (const float*)d_in[10];
    const float* wfc1  = (const float*)d_in[11];
    const float* bfc1  = (const float*)d_in[12];
    const float* wfc2  = (const float*)d_in[13];
    const float* bfc2  = (const float*)d_in[14];
    float* out = (float*)d_out;

    __half *ln1, *ln2, *y, *act, *wqt, *wpt, *w1t, *w2t;
    float *qkv, *h, *mlp;
    cudaGetSymbolAddress((void**)&ln1, g_ln1);
    cudaGetSymbolAddress((void**)&ln2, g_ln2);
    cudaGetSymbolAddress((void**)&qkv, g_qkv);
    cudaGetSymbolAddress((void**)&y,   g_y);
    cudaGetSymbolAddress((void**)&h,   g_h);
    cudaGetSymbolAddress((void**)&mlp, g_mlp);
    cudaGetSymbolAddress((void**)&act, g_act);
    cudaGetSymbolAddress((void**)&wqt, g_wqkv_t);
    cudaGetSymbolAddress((void**)&wpt, g_wproj_t);
    cudaGetSymbolAddress((void**)&w1t, g_wfc1_t);
    cudaGetSymbolAddress((void**)&w2t, g_wfc2_t);

    cudaFuncSetAttribute(hgemm_kernel<0>, cudaFuncAttributeMaxDynamicSharedMemorySize, HSM_BYTES);
    cudaFuncSetAttribute(fused1_kernel, cudaFuncAttributeMaxDynamicSharedMemorySize, F1_SMEM);
    cudaFuncSetAttribute(fused2_kernel, cudaFuncAttributeMaxDynamicSharedMemorySize, HSM_BYTES);

    // 0. fused weight transposes (fp16 cast)
    t4_kernel<<<TB_QKV + TB_PROJ + TB_FC1 + TB_FC2, 256>>>(
        wqkv, wqt, wproj, wpt, wfc1, w1t, wfc2, w2t);

    // 1. dual LayerNorm (fp16 outputs)
    ln_dual_kernel<<<M_TOK, 256>>>(x, ln1w, ln1b, ln2w, ln2b, ln1, ln2);

    // 2. QKV projection -> fp32 qkv
    hgemm_kernel<0><<<dim3(QKV_OUT / 128, M_TOK / 128), 256, HSM_BYTES>>>(
        ln1, wqt, bqkv, qkv, QKV_OUT, C_);

    // 3. RoPE
    rope_kernel<<<M_TOK, 320>>>(qkv, cosb, sinb);

    // 4. fused: flash attention + fc1(+GELU)
    fused1_kernel<<<ATT_BLKS + 2048, 256, F1_SMEM>>>(qkv, y, ln2, w1t, bfc1, act);

    // 5. fused: proj + fc2
    fused2_kernel<<<1024, 256, HSM_BYTES>>>(y, wpt, bproj, h, act, w2t, bfc2, mlp);

    // 6. out = mlp + h + x
    add_kernel<<<(M_TOK * C_) / 1024, 256>>>(mlp, h, x, out);
}